// round 10
// baseline (speedup 1.0000x reference)
#include <cuda_runtime.h>
#include <cuda_bf16.h>
#include <math.h>
#include <stdint.h>

#define BATCH 2
#define SEQ   4096
#define DM    2048
#define DI    4096
#define NH    32
#define HD    128
#define DS    64
#define CONVD (DI + 2*DS)          /* 4224 */
#define DIP   (2*DI + 2*DS + NH)   /* 8352 */
#define OFF_DT (DI + CONVD)        /* 8320 */
#define CHUNK 256
#define NC    (SEQ/CHUNK)          /* 16 */
#define TOK   (BATCH*SEQ)          /* 8192 */

// ---------------- scratch (device globals; no allocation allowed) ----------------
__device__ float g_zxbcdt[(size_t)TOK*DIP];
__device__ float g_dtsp[TOK*NH];
__device__ float g_dacs[BATCH*NH*NC*CHUNK];
__device__ float g_csum[BATCH*NH*NC];
__device__ float g_X[(size_t)BATCH*NC*NH*CHUNK*HD];
__device__ float g_Bm[BATCH*NC*CHUNK*DS];
__device__ float g_Cm[BATCH*NC*CHUNK*DS];
__device__ float g_G[BATCH*NC*CHUNK*CHUNK];
__device__ float g_states[(size_t)BATCH*NC*NH*HD*DS];
__device__ float g_inter[(size_t)BATCH*NC*NH*HD*DS];
__device__ float g_y[(size_t)TOK*DI];
__device__ float g_yn[(size_t)TOK*DI];

// ================= helpers =================
__device__ __forceinline__ uint32_t smem_u32(const void* p) {
    uint32_t a;
    asm("{ .reg .u64 t; cvta.to.shared.u64 t, %1; cvt.u32.u64 %0, t; }" : "=r"(a) : "l"(p));
    return a;
}
// split x0,x1 -> hi bf16x2 (rn) and lo bf16x2 (residual)
__device__ __forceinline__ void split2(float x0, float x1, uint32_t& hi, uint32_t& lo) {
    uint32_t h;
    asm("cvt.rn.bf16x2.f32 %0, %1, %2;" : "=r"(h) : "f"(x1), "f"(x0));
    float h0 = __uint_as_float(h << 16);
    float h1 = __uint_as_float(h & 0xFFFF0000u);
    float l0 = x0 - h0, l1 = x1 - h1;
    asm("cvt.rn.bf16x2.f32 %0, %1, %2;" : "=r"(lo) : "f"(l1), "f"(l0));
    hi = h;
}
#define LDMX4(r0, r1, r2, r3, addr) \
    asm volatile("ldmatrix.sync.aligned.m8n8.x4.shared.b16 {%0,%1,%2,%3}, [%4];" \
                 : "=r"(r0), "=r"(r1), "=r"(r2), "=r"(r3) : "r"(addr))
#define LDMX4T(r0, r1, r2, r3, addr) \
    asm volatile("ldmatrix.sync.aligned.m8n8.x4.trans.shared.b16 {%0,%1,%2,%3}, [%4];" \
                 : "=r"(r0), "=r"(r1), "=r"(r2), "=r"(r3) : "r"(addr))
#define MMA16816(d, a, b0, b1) \
    asm volatile("mma.sync.aligned.m16n8k16.row.col.f32.bf16.bf16.f32 " \
                 "{%0,%1,%2,%3}, {%4,%5,%6,%7}, {%8,%9}, {%0,%1,%2,%3};" \
                 : "+f"(d[0]), "+f"(d[1]), "+f"(d[2]), "+f"(d[3]) \
                 : "r"(a[0]), "r"(a[1]), "r"(a[2]), "r"(a[3]), "r"(b0), "r"(b1))

// ---------------- K1/K9: split-bf16 mma.sync GEMM (exact R5 core) ----------------
#define BM 128
#define BN 128
#define BK 32
#define LDT 40   /* padded bf16 row stride (80B) */

__global__ __launch_bounds__(256, 2) void gemm_mma(
    const float* __restrict__ A, const float* __restrict__ B,
    const float* __restrict__ bias, float* __restrict__ C,
    int M, int N, int K)
{
    __shared__ __align__(16) __nv_bfloat16 Ah[BM * LDT];
    __shared__ __align__(16) __nv_bfloat16 Al[BM * LDT];
    __shared__ __align__(16) __nv_bfloat16 Bh[BN * LDT];
    __shared__ __align__(16) __nv_bfloat16 Bl[BN * LDT];

    int tid = threadIdx.x;
    int warp = tid >> 5, lane = tid & 31;
    int wm = warp & 3, wn = warp >> 2;
    int m0 = blockIdx.y * BM, n0 = blockIdx.x * BN;

    float acc[2][8][4];
#pragma unroll
    for (int mi = 0; mi < 2; mi++)
#pragma unroll
        for (int ni = 0; ni < 8; ni++)
#pragma unroll
            for (int e = 0; e < 4; e++) acc[mi][ni][e] = 0.f;

    int lrow = tid >> 3;
    int lc4  = tid & 7;

    uint32_t ah_b = smem_u32(Ah), al_b = smem_u32(Al);
    uint32_t bh_b = smem_u32(Bh), bl_b = smem_u32(Bl);

    int lrow16 = lane & 15;
    int lkoff  = (lane >> 4) * 8;

    const float4 z4 = make_float4(0.f, 0.f, 0.f, 0.f);

    for (int k0 = 0; k0 < K; k0 += BK) {
#pragma unroll
        for (int u = 0; u < 4; u++) {
            int r = lrow + u * 32;
            float4 v = *(const float4*)&A[(size_t)(m0 + r) * K + k0 + lc4 * 4];
            uint32_t h0, l0, h1, l1;
            split2(v.x, v.y, h0, l0);
            split2(v.z, v.w, h1, l1);
            uint32_t off = (uint32_t)(r * LDT + lc4 * 4) * 2;
            asm volatile("st.shared.v2.b32 [%0], {%1,%2};" :: "r"(ah_b + off), "r"(h0), "r"(h1) : "memory");
            asm volatile("st.shared.v2.b32 [%0], {%1,%2};" :: "r"(al_b + off), "r"(l0), "r"(l1) : "memory");
        }
#pragma unroll
        for (int u = 0; u < 4; u++) {
            int r = lrow + u * 32;
            float4 v = (n0 + r < N) ? *(const float4*)&B[(size_t)(n0 + r) * K + k0 + lc4 * 4] : z4;
            uint32_t h0, l0, h1, l1;
            split2(v.x, v.y, h0, l0);
            split2(v.z, v.w, h1, l1);
            uint32_t off = (uint32_t)(r * LDT + lc4 * 4) * 2;
            asm volatile("st.shared.v2.b32 [%0], {%1,%2};" :: "r"(bh_b + off), "r"(h0), "r"(h1) : "memory");
            asm volatile("st.shared.v2.b32 [%0], {%1,%2};" :: "r"(bl_b + off), "r"(l0), "r"(l1) : "memory");
        }
        __syncthreads();

#pragma unroll
        for (int ks = 0; ks < BK; ks += 16) {
            uint32_t ahf[2][4], alf[2][4];
#pragma unroll
            for (int mi = 0; mi < 2; mi++) {
                uint32_t off = (uint32_t)((wm * 32 + mi * 16 + lrow16) * LDT + ks + lkoff) * 2;
                LDMX4(ahf[mi][0], ahf[mi][1], ahf[mi][2], ahf[mi][3], ah_b + off);
                LDMX4(alf[mi][0], alf[mi][1], alf[mi][2], alf[mi][3], al_b + off);
            }
#pragma unroll
            for (int nt = 0; nt < 4; nt++) {
                uint32_t off = (uint32_t)((wn * 64 + nt * 16 + lrow16) * LDT + ks + lkoff) * 2;
                uint32_t h0, h1, h2, h3, l0, l1, l2, l3;
                LDMX4(h0, h1, h2, h3, bh_b + off);
                LDMX4(l0, l1, l2, l3, bl_b + off);
#pragma unroll
                for (int mi = 0; mi < 2; mi++) {
                    MMA16816(acc[mi][nt * 2 + 0], ahf[mi], h0, h2);
                    MMA16816(acc[mi][nt * 2 + 0], alf[mi], h0, h2);
                    MMA16816(acc[mi][nt * 2 + 0], ahf[mi], l0, l2);
                    MMA16816(acc[mi][nt * 2 + 1], ahf[mi], h1, h3);
                    MMA16816(acc[mi][nt * 2 + 1], alf[mi], h1, h3);
                    MMA16816(acc[mi][nt * 2 + 1], ahf[mi], l1, l3);
                }
            }
        }
        __syncthreads();
    }

    int rbase = m0 + wm * 32 + (lane >> 2);
    int cbase = n0 + wn * 64 + (lane & 3) * 2;
#pragma unroll
    for (int mi = 0; mi < 2; mi++) {
#pragma unroll
        for (int ni = 0; ni < 8; ni++) {
            int col = cbase + ni * 8;
            if (col < N) {
                float2 bb = *(const float2*)&bias[col];
                int r0 = rbase + mi * 16;
                float2 v0 = make_float2(acc[mi][ni][0] + bb.x, acc[mi][ni][1] + bb.y);
                *(float2*)&C[(size_t)r0 * N + col] = v0;
                float2 v1 = make_float2(acc[mi][ni][2] + bb.x, acc[mi][ni][3] + bb.y);
                *(float2*)&C[(size_t)(r0 + 8) * N + col] = v1;
            }
        }
    }
}

// ---------------- K2: dt softplus + per-chunk inclusive cumsum of A*dt ----------------
__global__ __launch_bounds__(256) void dt_scan_kernel(
    const float* __restrict__ dt_bias, const float* __restrict__ A_log)
{
    int blk = blockIdx.x;
    int c = blk % NC; int bh = blk / NC;
    int h = bh % NH;  int b = bh / NH;
    int t = threadIdx.x;
    int l = c * CHUNK + t;

    float x = g_zxbcdt[(size_t)(b * SEQ + l) * DIP + OFF_DT + h] + dt_bias[h];
    float sp = (x > 20.f) ? x : log1pf(expf(x));
    g_dtsp[(b * SEQ + l) * NH + h] = sp;
    float da = -expf(A_log[h]) * sp;

    __shared__ float s[CHUNK];
    s[t] = da;
    __syncthreads();
    for (int off = 1; off < CHUNK; off <<= 1) {
        float v = (t >= off) ? s[t - off] : 0.f;
        __syncthreads();
        s[t] += v;
        __syncthreads();
    }
    int base = ((b * NH + h) * NC + c) * CHUNK;
    g_dacs[base + t] = s[t];
    if (t == CHUNK - 1) g_csum[(b * NH + h) * NC + c] = s[t];
}

// ---------------- K3: causal depthwise conv4 + SiLU + scatter ----------------
__global__ __launch_bounds__(256) void conv_kernel(
    const float* __restrict__ conv_w, const float* __restrict__ conv_b)
{
    int tok = blockIdx.x;
    int ch = blockIdx.y * 256 + threadIdx.x;
    if (ch >= CONVD) return;
    int b = tok / SEQ, l = tok % SEQ;

    const float* w = conv_w + ch * 4;
    float acc = conv_b[ch];
#pragma unroll
    for (int j = 0; j < 4; j++) {
        int ls = l - 3 + j;
        if (ls >= 0)
            acc += w[j] * g_zxbcdt[(size_t)(b * SEQ + ls) * DIP + DI + ch];
    }
    float v = acc / (1.f + __expf(-acc));

    int c = l / CHUNK, t = l % CHUNK;
    if (ch < DI) {
        int h = ch >> 7, p = ch & 127;
        float dt = g_dtsp[(b * SEQ + l) * NH + h];
        g_X[(size_t)(((b * NC + c) * NH + h) * CHUNK + t) * HD + p] = v * dt;
    } else if (ch < DI + DS) {
        g_Bm[((b * NC + c) * CHUNK + t) * DS + (ch - DI)] = v;
    } else {
        g_Cm[((b * NC + c) * CHUNK + t) * DS + (ch - DI - DS)] = v;
    }
}

// ---------------- K4: G[l,s] = sum_n C[l,n] B[s,n] per (b,c) ----------------
__global__ __launch_bounds__(256) void bc_gemm_kernel()
{
    int bc = blockIdx.y;
    int tile = blockIdx.x;
    int l0 = (tile >> 2) * 64, s0 = (tile & 3) * 64;
    __shared__ float Cs[64][65];
    __shared__ float Bs[64][65];
    int tid = threadIdx.x;
    const float* Cb = g_Cm + (size_t)bc * CHUNK * DS;
    const float* Bb = g_Bm + (size_t)bc * CHUNK * DS;

#pragma unroll
    for (int u = 0; u < 4; u++) {
        int e = tid + u * 256;
        int r = e >> 4, cv = (e & 15) << 2;
        float4 vc = *(const float4*)&Cb[(l0 + r) * DS + cv];
        Cs[r][cv + 0] = vc.x; Cs[r][cv + 1] = vc.y; Cs[r][cv + 2] = vc.z; Cs[r][cv + 3] = vc.w;
        float4 vb = *(const float4*)&Bb[(s0 + r) * DS + cv];
        Bs[r][cv + 0] = vb.x; Bs[r][cv + 1] = vb.y; Bs[r][cv + 2] = vb.z; Bs[r][cv + 3] = vb.w;
    }
    __syncthreads();

    int sq = tid & 15, lq = tid >> 4;
    float acc[4][4];
#pragma unroll
    for (int i = 0; i < 4; i++)
#pragma unroll
        for (int j = 0; j < 4; j++) acc[i][j] = 0.f;

#pragma unroll 8
    for (int n = 0; n < 64; n++) {
        float a[4], bb[4];
#pragma unroll
        for (int i = 0; i < 4; i++) a[i] = Cs[lq * 4 + i][n];
#pragma unroll
        for (int j = 0; j < 4; j++) bb[j] = Bs[sq * 4 + j][n];
#pragma unroll
        for (int i = 0; i < 4; i++)
#pragma unroll
            for (int j = 0; j < 4; j++) acc[i][j] = fmaf(a[i], bb[j], acc[i][j]);
    }
    float* Gout = g_G + (size_t)bc * CHUNK * CHUNK;
#pragma unroll
    for (int i = 0; i < 4; i++) {
        float4 v = make_float4(acc[i][0], acc[i][1], acc[i][2], acc[i][3]);
        *(float4*)&Gout[(l0 + lq * 4 + i) * CHUNK + s0 + sq * 4] = v;
    }
}

// ---------------- K5: Y_diag = (G .* L) @ X per (b,c,h), split-bf16 mma ----------------
#define YLDT 40
#define XLDT 136
#define YSMEM (2*256*YLDT*2 + 2*32*XLDT*2 + 256*4 + 256*4)   /* 60416 */

__global__ __launch_bounds__(512, 1) void ydiag_kernel()
{
    extern __shared__ __align__(16) char ysm[];
    __nv_bfloat16* Msh = (__nv_bfloat16*)ysm;
    __nv_bfloat16* Msl = Msh + 256 * YLDT;
    __nv_bfloat16* Xsh = Msl + 256 * YLDT;
    __nv_bfloat16* Xsl = Xsh + 32 * XLDT;
    float* acs   = (float*)(Xsl + 32 * XLDT);
    float* cfall = acs + 256;

    uint32_t msh_b = smem_u32(Msh), msl_b = smem_u32(Msl);
    uint32_t xsh_b = smem_u32(Xsh), xsl_b = smem_u32(Xsl);

    int blk = blockIdx.x;
    int h = blk % NH; int bc = blk / NH;
    int c = bc % NC;  int b = bc / NC;
    int tid = threadIdx.x;
    int warp = tid >> 5, lane = tid & 31;
    int wm = warp & 7, wn = warp >> 3;

    if (tid < 256) acs[tid] = g_dacs[((b * NH + h) * NC + c) * CHUNK + tid];
    __syncthreads();
    if (tid < 256) cfall[tid] = __expf(acs[tid & ~31] - acs[tid]);
    __syncthreads();

    const float* Gb = g_G + (size_t)bc * CHUNK * CHUNK;
    const float* Xb = g_X + (size_t)blk * CHUNK * HD;

    float acc[2][8][4];
#pragma unroll
    for (int mi = 0; mi < 2; mi++)
#pragma unroll
        for (int ni = 0; ni < 8; ni++)
#pragma unroll
            for (int e = 0; e < 4; e++) acc[mi][ni][e] = 0.f;

    int lrow16 = lane & 15, lkoff = (lane >> 4) * 8;
    int bl = tid >> 1, bs = (tid & 1) * 16;
    int i8 = lane & 7, sel = lane >> 3;

    for (int s0 = 0; s0 < CHUNK; s0 += 32) {
        if (s0) __syncthreads();

#pragma unroll
        for (int u = 0; u < 2; u++) {
            int e = tid + u * 512;
            int s = e >> 5, p4 = e & 31;
            float4 v = *(const float4*)&Xb[(s0 + s) * HD + p4 * 4];
            uint32_t h0, l0, h1, l1;
            split2(v.x, v.y, h0, l0);
            split2(v.z, v.w, h1, l1);
            uint32_t off = (uint32_t)(s * XLDT + p4 * 4) * 2;
            asm volatile("st.shared.v2.b32 [%0], {%1,%2};" :: "r"(xsh_b + off), "r"(h0), "r"(h1) : "memory");
            asm volatile("st.shared.v2.b32 [%0], {%1,%2};" :: "r"(xsl_b + off), "r"(l0), "r"(l1) : "memory");
        }

        if (bl >= s0 - 32) {
            float rowfac = __expf(acs[bl] - acs[s0]);
#pragma unroll
            for (int j4 = 0; j4 < 4; j4++) {
                int sg = s0 + bs + j4 * 4;
                float4 g4 = *(const float4*)&Gb[bl * CHUNK + sg];
                float m0 = (sg + 0 <= bl) ? g4.x * rowfac * cfall[sg + 0] : 0.f;
                float m1 = (sg + 1 <= bl) ? g4.y * rowfac * cfall[sg + 1] : 0.f;
                float m2 = (sg + 2 <= bl) ? g4.z * rowfac * cfall[sg + 2] : 0.f;
                float m3 = (sg + 3 <= bl) ? g4.w * rowfac * cfall[sg + 3] : 0.f;
                uint32_t h01, l01, h23, l23;
                split2(m0, m1, h01, l01);
                split2(m2, m3, h23, l23);
                uint32_t off = (uint32_t)(bl * YLDT + bs + j4 * 4) * 2;
                asm volatile("st.shared.v2.b32 [%0], {%1,%2};" :: "r"(msh_b + off), "r"(h01), "r"(h23) : "memory");
                asm volatile("st.shared.v2.b32 [%0], {%1,%2};" :: "r"(msl_b + off), "r"(l01), "r"(l23) : "memory");
            }
        }
        __syncthreads();

        if (wm * 32 + 31 >= s0) {
#pragma unroll
            for (int ks = 0; ks < 32; ks += 16) {
                uint32_t ahf[2][4], alf[2][4];
#pragma unroll
                for (int mi = 0; mi < 2; mi++) {
                    uint32_t off = (uint32_t)((wm * 32 + mi * 16 + lrow16) * YLDT + ks + lkoff) * 2;
                    LDMX4(ahf[mi][0], ahf[mi][1], ahf[mi][2], ahf[mi][3], msh_b + off);
                    LDMX4(alf[mi][0], alf[mi][1], alf[mi][2], alf[mi][3], msl_b + off);
                }
#pragma unroll
                for (int nt = 0; nt < 4; nt++) {
                    uint32_t xoff = (uint32_t)((ks + (sel >> 1) * 8 + i8) * XLDT
                                               + wn * 64 + nt * 16 + (sel & 1) * 8) * 2;
                    uint32_t h0, h1, h2, h3, l0, l1, l2, l3;
                    LDMX4T(h0, h1, h2, h3, xsh_b + xoff);
                    LDMX4T(l0, l1, l2, l3, xsl_b + xoff);
#pragma unroll
                    for (int mi = 0; mi < 2; mi++) {
                        MMA16816(acc[mi][nt * 2 + 0], ahf[mi], h0, h2);
                        MMA16816(acc[mi][nt * 2 + 0], alf[mi], h0, h2);
                        MMA16816(acc[mi][nt * 2 + 0], ahf[mi], l0, l2);
                        MMA16816(acc[mi][nt * 2 + 1], ahf[mi], h1, h3);
                        MMA16816(acc[mi][nt * 2 + 1], alf[mi], h1, h3);
                        MMA16816(acc[mi][nt * 2 + 1], ahf[mi], l1, l3);
                    }
                }
            }
        }
    }

    int rbase = wm * 32 + (lane >> 2);
    int cbase = wn * 64 + (lane & 3) * 2;
#pragma unroll
    for (int mi = 0; mi < 2; mi++) {
#pragma unroll
        for (int ni = 0; ni < 8; ni++) {
            int l0r = rbase + mi * 16;
            int col = cbase + ni * 8;
            float* out0 = g_y + (size_t)(b * SEQ + c * CHUNK + l0r) * DI + h * HD + col;
            *(float2*)out0 = make_float2(acc[mi][ni][0], acc[mi][ni][1]);
            float* out1 = g_y + (size_t)(b * SEQ + c * CHUNK + l0r + 8) * DI + h * HD + col;
            *(float2*)out1 = make_float2(acc[mi][ni][2], acc[mi][ni][3]);
        }
    }
}

// ---------------- K5b: states via mma: S[p,n] = sum_l X[l,p]*w[l]*B[l,n] ----------------
// 256 thr = 8 warps, each warp one p16 tile, all 64 n. A = X^T (trans ldmatrix),
// B = w.*Bm (trans ldmatrix from [l][n]).
#define SXP 136
#define SBP 72

__global__ __launch_bounds__(256, 1) void states_kernel()
{
    __shared__ __align__(16) __nv_bfloat16 Xh[32 * SXP];
    __shared__ __align__(16) __nv_bfloat16 Xl[32 * SXP];
    __shared__ __align__(16) __nv_bfloat16 Bh2[32 * SBP];
    __shared__ __align__(16) __nv_bfloat16 Bl2[32 * SBP];
    __shared__ float acs[CHUNK];

    uint32_t xh_b = smem_u32(Xh), xl_b = smem_u32(Xl);
    uint32_t bh_b = smem_u32(Bh2), bl_b = smem_u32(Bl2);

    int blk = blockIdx.x;
    int h = blk % NH; int bc = blk / NH;
    int c = bc % NC;  int b = bc / NC;
    int tid = threadIdx.x;
    int warp = tid >> 5, lane = tid & 31;
    int i8 = lane & 7, sel = lane >> 3;

    if (tid < 256) acs[tid] = g_dacs[((b * NH + h) * NC + c) * CHUNK + tid];
    __syncthreads();
    float alast = acs[CHUNK - 1];

    const float* Xb = g_X + (size_t)blk * CHUNK * HD;
    const float* Bb = g_Bm + (size_t)bc * CHUNK * DS;

    float acc[8][4];
#pragma unroll
    for (int ni = 0; ni < 8; ni++)
#pragma unroll
        for (int e = 0; e < 4; e++) acc[ni][e] = 0.f;

    for (int l0 = 0; l0 < CHUNK; l0 += 32) {
        if (l0) __syncthreads();
        // X tile 32x128 -> bf16 hi/lo [l][p]
#pragma unroll
        for (int u = 0; u < 4; u++) {
            int e = tid + u * 256;
            int s = e >> 5, p4 = e & 31;
            float4 v = *(const float4*)&Xb[(l0 + s) * HD + p4 * 4];
            uint32_t h0, l0r, h1, l1r;
            split2(v.x, v.y, h0, l0r);
            split2(v.z, v.w, h1, l1r);
            uint32_t off = (uint32_t)(s * SXP + p4 * 4) * 2;
            asm volatile("st.shared.v2.b32 [%0], {%1,%2};" :: "r"(xh_b + off), "r"(h0), "r"(h1) : "memory");
            asm volatile("st.shared.v2.b32 [%0], {%1,%2};" :: "r"(xl_b + off), "r"(l0r), "r"(l1r) : "memory");
        }
        // B' tile 32x64 = w[l]*Bm -> bf16 hi/lo [l][n]
#pragma unroll
        for (int u = 0; u < 2; u++) {
            int e = tid + u * 256;
            int s = e >> 4, n4 = e & 15;
            float w = __expf(alast - acs[l0 + s]);
            float4 v = *(const float4*)&Bb[(l0 + s) * DS + n4 * 4];
            uint32_t h0, l0r, h1, l1r;
            split2(v.x * w, v.y * w, h0, l0r);
            split2(v.z * w, v.w * w, h1, l1r);
            uint32_t off = (uint32_t)(s * SBP + n4 * 4) * 2;
            asm volatile("st.shared.v2.b32 [%0], {%1,%2};" :: "r"(bh_b + off), "r"(h0), "r"(h1) : "memory");
            asm volatile("st.shared.v2.b32 [%0], {%1,%2};" :: "r"(bl_b + off), "r"(l0r), "r"(l1r) : "memory");
        }
        __syncthreads();

#pragma unroll
        for (int ks = 0; ks < 32; ks += 16) {
            // A = X^T via trans: row = k, col = p
            uint32_t aoff = (uint32_t)((ks + (sel >> 1) * 8 + i8) * SXP
                                       + warp * 16 + (sel & 1) * 8) * 2;
            uint32_t ah[4], al[4];
            LDMX4T(ah[0], ah[1], ah[2], ah[3], xh_b + aoff);
            LDMX4T(al[0], al[1], al[2], al[3], xl_b + aoff);
#pragma unroll
            for (int nt = 0; nt < 2; nt++) {    // n32 groups of n16
                uint32_t boff = (uint32_t)((ks + (sel >> 1) * 8 + i8) * SBP
                                           + nt * 32 + (sel & 1) * 8) * 2;
                // covers n = nt*32 + {0..15}? No: col term (sel&1)*8 spans 16; need two loads
                uint32_t h0, h1, h2, h3, l0r, l1r, l2r, l3r;
                LDMX4T(h0, h1, h2, h3, bh_b + boff);
                LDMX4T(l0r, l1r, l2r, l3r, bl_b + boff);
                MMA16816(acc[nt * 4 + 0], ah, h0, h2);
                MMA16816(acc[nt * 4 + 0], al, h0, h2);
                MMA16816(acc[nt * 4 + 0], ah, l0r, l2r);
                MMA16816(acc[nt * 4 + 1], ah, h1, h3);
                MMA16816(acc[nt * 4 + 1], al, h1, h3);
                MMA16816(acc[nt * 4 + 1], ah, l1r, l3r);
                uint32_t boff2 = (uint32_t)((ks + (sel >> 1) * 8 + i8) * SBP
                                            + nt * 32 + 16 + (sel & 1) * 8) * 2;
                LDMX4T(h0, h1, h2, h3, bh_b + boff2);
                LDMX4T(l0r, l1r, l2r, l3r, bl_b + boff2);
                MMA16816(acc[nt * 4 + 2], ah, h0, h2);
                MMA16816(acc[nt * 4 + 2], al, h0, h2);
                MMA16816(acc[nt * 4 + 2], ah, l0r, l2r);
                MMA16816(acc[nt * 4 + 3], ah, h1, h3);
                MMA16816(acc[nt * 4 + 3], al, h1, h3);
                MMA16816(acc[nt * 4 + 3], ah, l1r, l3r);
            }
        }
    }

    float* So = g_states + (size_t)blk * HD * DS;
    int p0 = warp * 16 + (lane >> 2);
    int nc0 = (lane & 3) * 2;
#pragma unroll
    for (int ni = 0; ni < 8; ni++) {
        int col = nc0 + ni * 8;
        *(float2*)&So[p0 * DS + col] = make_float2(acc[ni][0], acc[ni][1]);
        *(float2*)&So[(p0 + 8) * DS + col] = make_float2(acc[ni][2], acc[ni][3]);
    }
}

// ---------------- K6: inter-chunk scan ----------------
__global__ __launch_bounds__(256) void scan_kernel()
{
    int bh = blockIdx.x;
    int b = bh / NH, h = bh % NH;
    int tid = threadIdx.x;
    float S[32];
#pragma unroll
    for (int k = 0; k < 32; k++) S[k] = 0.f;
    for (int c = 0; c < NC; c++) {
        float dec = __expf(g_csum[bh * NC + c]);
        size_t base = (size_t)((b * NC + c) * NH + h) * HD * DS;
#pragma unroll
        for (int k = 0; k < 32; k++) {
            int e = tid + k * 256;
            g_inter[base + e] = S[k];
            S[k] = S[k] * dec + g_states[base + e];
        }
    }
}

// ---------------- K7: Y_off via mma + combine + silu gate ----------------
// 512 thr = 16 warps (8m x 2n). Y_off[t,p] = ea[t] * sum_n C[t,n] inter[p,n].
// Both operands non-trans ldmatrix (gemm_mma pattern), K=64.
#define OLP 72
#define OSMEM ((2*256*OLP + 2*128*OLP)*2 + 256*4)   /* 111616 */

__global__ __launch_bounds__(512, 1) void yoff_kernel()
{
    extern __shared__ __align__(16) char osm[];
    __nv_bfloat16* Ch = (__nv_bfloat16*)osm;
    __nv_bfloat16* Cl = Ch + 256 * OLP;
    __nv_bfloat16* Ih = Cl + 256 * OLP;
    __nv_bfloat16* Il = Ih + 128 * OLP;
    float* acs = (float*)(Il + 128 * OLP);

    uint32_t ch_b = smem_u32(Ch), cl_b = smem_u32(Cl);
    uint32_t ih_b = smem_u32(Ih), il_b = smem_u32(Il);

    int blk = blockIdx.x;
    int h = blk % NH; int bc = blk / NH;
    int c = bc % NC;  int b = bc / NC;
    int tid = threadIdx.x;
    int warp = tid >> 5, lane = tid & 31;
    int wm = warp & 7, wn = warp >> 3;
    int lrow16 = lane & 15, lkoff = (lane >> 4) * 8;

    if (tid < 256) acs[tid] = g_dacs[((b * NH + h) * NC + c) * CHUNK + tid];

    const float* Cb = g_Cm + (size_t)bc * CHUNK * DS;
    const float* Ib = g_inter + (size_t)blk * HD * DS;

    // build C' 256x64 (8 float4/thread) and I' 128x64 (4 float4/thread)
#pragma unroll
    for (int u = 0; u < 8; u++) {
        int e = tid + u * 512;
        int t = e >> 4, n4 = e & 15;
        float4 v = *(const float4*)&Cb[t * DS + n4 * 4];
        uint32_t h0, l0, h1, l1;
        split2(v.x, v.y, h0, l0);
        split2(v.z, v.w, h1, l1);
        uint32_t off = (uint32_t)(t * OLP + n4 * 4) * 2;
        asm volatile("st.shared.v2.b32 [%0], {%1,%2};" :: "r"(ch_b + off), "r"(h0), "r"(h1) : "memory");
        asm volatile("st.shared.v2.b32 [%0], {%1,%2};" :: "r"(cl_b + off), "r"(l0), "r"(l1) : "memory");
    }
#pragma unroll
    for (int u = 0; u < 4; u++) {
        int e = tid + u * 512;
        int p = e >> 4, n4 = e & 15;
        float4 v = *(const float4*)&Ib[p * DS + n4 * 4];
        uint32_t h0, l0, h1, l1;
        split2(v.x, v.y, h0, l0);
        split2(v.z, v.w, h1, l1);
        uint32_t off = (uint32_t)(p * OLP + n4 * 4) * 2;
        asm volatile("st.shared.v2.b32 [%0], {%1,%2};" :: "r"(ih_b + off), "r"(h0), "r"(h1) : "memory");
        asm volatile("st.shared.v2.b32 [%0], {%1,%2};" :: "r"(il_b + off), "r"(l0), "r"(l1) : "memory");
    }
    __syncthreads();

    float acc[2][8][4];
#pragma unroll
    for (int mi = 0; mi < 2; mi++)
#pragma unroll
        for (int ni = 0; ni < 8; ni++)
#pragma unroll
            for (int e = 0; e < 4; e++) acc[mi][ni][e] = 0.f;

#pragma unroll
    for (int ks = 0; ks < 64; ks += 16) {
        uint32_t ahf[2][4], alf[2][4];
#pragma unroll
        for (int mi = 0; mi < 2; mi++) {
            uint32_t off = (uint32_t)((wm * 32 + mi * 16 + lrow16) * OLP + ks + lkoff) * 2;
            LDMX4(ahf[mi][0], ahf[mi][1], ahf[mi][2], ahf[mi][3], ch_b + off);
            LDMX4(alf[mi][0], alf[mi][1], alf[mi][2], alf[mi][3], cl_b + off);
        }
#pragma unroll
        for (int nt = 0; nt < 4; nt++) {
            uint32_t off = (uint32_t)((wn * 64 + nt * 16 + lrow16) * OLP + ks + lkoff) * 2;
            uint32_t h0, h1, h2, h3, l0, l1, l2, l3;
            LDMX4(h0, h1, h2, h3, ih_b + off);
            LDMX4(l0, l1, l2, l3, il_b + off);
#pragma unroll
            for (int mi = 0; mi < 2; mi++) {
                MMA16816(acc[mi][nt * 2 + 0], ahf[mi], h0, h2);
                MMA16816(acc[mi][nt * 2 + 0], alf[mi], h0, h2);
                MMA16816(acc[mi][nt * 2 + 0], ahf[mi], l0, l2);
                MMA16816(acc[mi][nt * 2 + 1], ahf[mi], h1, h3);
                MMA16816(acc[mi][nt * 2 + 1], alf[mi], h1, h3);
                MMA16816(acc[mi][nt * 2 + 1], ahf[mi], l1, l3);
            }
        }
    }

    // epilogue: combine with g_y, gate with silu(z)
    int rbase = wm * 32 + (lane >> 2);
    int cbase = wn * 64 + (lane & 3) * 2;
#pragma unroll
    for (int mi = 0; mi < 2; mi++) {
        int t0 = rbase + mi * 16;
        float ea0 = __expf(acs[t0]);
        float ea1 = __expf(acs[t0 + 8]);
#pragma unroll
        for (int ni = 0; ni < 8; ni++) {
            int col = cbase + ni * 8;
#pragma unroll
            for (int rr = 0; rr < 2; rr++) {
                int t = t0 + rr * 8;
                float ea = rr ? ea1 : ea0;
                int gl = c * CHUNK + t;
                size_t yidx = (size_t)(b * SEQ + gl) * DI + h * HD + col;
                size_t zidx = (size_t)(b * SEQ + gl) * DIP + h * HD + col;
                float2 yd = *(float2*)&g_y[yidx];
                float2 z  = *(const float2*)&g_zxbcdt[zidx];
                float2 o;
                float a0 = acc[mi][ni][rr * 2 + 0], a1 = acc[mi][ni][rr * 2 + 1];
                o.x = (yd.x + ea * a0) * z.x / (1.f + __expf(-z.x));
                o.y = (yd.y + ea * a1) * z.y / (1.f + __expf(-z.y));
                *(float2*)&g_y[yidx] = o;
            }
        }
    }
}

// ---------------- K8: layernorm over 4096 ----------------
__global__ __launch_bounds__(256) void ln_kernel(
    const float* __restrict__ ln_w, const float* __restrict__ ln_b)
{
    int tok = blockIdx.x;
    const float* y = g_y + (size_t)tok * DI;
    float* o = g_yn + (size_t)tok * DI;
    int tid = threadIdx.x;

    float v[16];
    float s = 0.f, ss = 0.f;
#pragma unroll
    for (int u = 0; u < 4; u++) {
        float4 x = *(const float4*)&y[tid * 4 + u * 1024];
        v[u * 4 + 0] = x.x; v[u * 4 + 1] = x.y; v[u * 4 + 2] = x.z; v[u * 4 + 3] = x.w;
        s += x.x + x.y + x.z + x.w;
        ss += x.x * x.x + x.y * x.y + x.z * x.z + x.w * x.w;
    }
#pragma unroll
    for (int off = 16; off; off >>= 1) {
        s  += __shfl_xor_sync(0xFFFFFFFFu, s, off);
        ss += __shfl_xor_sync(0xFFFFFFFFu, ss, off);
    }
    __shared__ float rs[8], rss[8];
    int warp = tid >> 5, lane = tid & 31;
    if (lane == 0) { rs[warp] = s; rss[warp] = ss; }
    __syncthreads();
    s = 0.f; ss = 0.f;
#pragma unroll
    for (int w = 0; w < 8; w++) { s += rs[w]; ss += rss[w]; }
    float mu = s * (1.f / DI);
    float var = ss * (1.f / DI) - mu * mu;
    float rstd = rsqrtf(var + 1e-5f);
#pragma unroll
    for (int u = 0; u < 4; u++) {
        int idx = tid * 4 + u * 1024;
        float4 w4 = *(const float4*)&ln_w[idx];
        float4 b4 = *(const float4*)&ln_b[idx];
        float4 ov;
        ov.x = (v[u * 4 + 0] - mu) * rstd * w4.x + b4.x;
        ov.y = (v[u * 4 + 1] - mu) * rstd * w4.y + b4.y;
        ov.z = (v[u * 4 + 2] - mu) * rstd * w4.z + b4.z;
        ov.w = (v[u * 4 + 3] - mu) * rstd * w4.w + b4.w;
        *(float4*)&o[idx] = ov;
    }
}

// ---------------- launch ----------------
extern "C" void kernel_launch(void* const* d_in, const int* in_sizes, int n_in,
                              void* d_out, int out_size)
{
    const float* u          = (const float*)d_in[0];
    const float* in_proj_w  = (const float*)d_in[1];
    const float* in_proj_b  = (const float*)d_in[2];
    const float* conv_w     = (const float*)d_in[3];
    const float* conv_b     = (const float*)d_in[4];
    const float* dt_bias    = (const float*)d_in[5];
    const float* A_log      = (const float*)d_in[6];
    const float* ln_w       = (const float*)d_in[7];
    const float* ln_b       = (const float*)d_in[8];
    const float* out_proj_w = (const float*)d_in[9];
    const float* out_proj_b = (const float*)d_in[10];
    float* out = (float*)d_out;

    float* zx; cudaGetSymbolAddress((void**)&zx, g_zxbcdt);
    float* yn; cudaGetSymbolAddress((void**)&yn, g_yn);

    cudaFuncSetAttribute(ydiag_kernel, cudaFuncAttributeMaxDynamicSharedMemorySize, YSMEM);
    cudaFuncSetAttribute(yoff_kernel, cudaFuncAttributeMaxDynamicSharedMemorySize, OSMEM);

    // K1: in_proj GEMM (8192 x 8352 x 2048)
    gemm_mma<<<dim3((DIP + BN - 1) / BN, TOK / BM), 256>>>(
        u, in_proj_w, in_proj_b, zx, TOK, DIP, DM);
    // K2: dt softplus + per-chunk cumsum
    dt_scan_kernel<<<BATCH * NH * NC, CHUNK>>>(dt_bias, A_log);
    // K3: conv + silu + scatter
    conv_kernel<<<dim3(TOK, (CONVD + 255) / 256), 256>>>(conv_w, conv_b);
    // K4: G = C B^T per (b,c)
    bc_gemm_kernel<<<dim3(16, BATCH * NC), 256>>>();
    // K5: Y_diag (split-bf16 mma)
    ydiag_kernel<<<BATCH * NC * NH, 512, YSMEM>>>();
    // K5b: local chunk states (split-bf16 mma)
    states_kernel<<<BATCH * NC * NH, 256>>>();
    // K6: inter-chunk scan
    scan_kernel<<<BATCH * NH, 256>>>();
    // K7: Y_off (split-bf16 mma) + gate
    yoff_kernel<<<BATCH * NC * NH, 512, OSMEM>>>();
    // K8: layernorm
    ln_kernel<<<TOK, 256>>>(ln_w, ln_b);
    // K9: out_proj GEMM (8192 x 2048 x 4096)
    gemm_mma<<<dim3(DM / BN, TOK / BM), 256>>>(
        yn, out_proj_b ? yn : yn, out_proj_b, out, TOK, DM, DI);
    // (fix args) -- real call below overwrites nothing; see note
    gemm_mma<<<dim3(DM / BN, TOK / BM), 256>>>(
        yn, out_proj_w, out_proj_b, out, TOK, DM, DI);
}

// round 11
// speedup vs baseline: 1.2005x; 1.2005x over previous
#include <cuda_runtime.h>
#include <cuda_bf16.h>
#include <math.h>
#include <stdint.h>

#define BATCH 2
#define SEQ   4096
#define DM    2048
#define DI    4096
#define NH    32
#define HD    128
#define DS    64
#define CONVD (DI + 2*DS)          /* 4224 */
#define DIP   (2*DI + 2*DS + NH)   /* 8352 */
#define OFF_DT (DI + CONVD)        /* 8320 */
#define CHUNK 256
#define NC    (SEQ/CHUNK)          /* 16 */
#define TOK   (BATCH*SEQ)          /* 8192 */

// ---------------- scratch (device globals; no allocation allowed) ----------------
__device__ float g_zxbcdt[(size_t)TOK*DIP];
__device__ float g_dtsp[TOK*NH];
__device__ float g_dacs[BATCH*NH*NC*CHUNK];
__device__ float g_csum[BATCH*NH*NC];
__device__ float g_X[(size_t)BATCH*NC*NH*CHUNK*HD];
__device__ float g_Bm[BATCH*NC*CHUNK*DS];
__device__ float g_Cm[BATCH*NC*CHUNK*DS];
__device__ float g_G[BATCH*NC*CHUNK*CHUNK];
__device__ float g_states[(size_t)BATCH*NC*NH*HD*DS];
__device__ float g_inter[(size_t)BATCH*NC*NH*HD*DS];
__device__ float g_y[(size_t)TOK*DI];
// pre-split bf16 operands for the two big GEMMs
__device__ __nv_bfloat16 g_u_hi[(size_t)TOK*DM];
__device__ __nv_bfloat16 g_u_lo[(size_t)TOK*DM];
__device__ __nv_bfloat16 g_w1_hi[(size_t)DIP*DM];
__device__ __nv_bfloat16 g_w1_lo[(size_t)DIP*DM];
__device__ __nv_bfloat16 g_w2_hi[(size_t)DM*DI];
__device__ __nv_bfloat16 g_w2_lo[(size_t)DM*DI];
__device__ __nv_bfloat16 g_yn_hi[(size_t)TOK*DI];
__device__ __nv_bfloat16 g_yn_lo[(size_t)TOK*DI];

// ================= helpers =================
__device__ __forceinline__ uint32_t smem_u32(const void* p) {
    uint32_t a;
    asm("{ .reg .u64 t; cvta.to.shared.u64 t, %1; cvt.u32.u64 %0, t; }" : "=r"(a) : "l"(p));
    return a;
}
// split x0,x1 -> hi bf16x2 (rn) and lo bf16x2 (residual)
__device__ __forceinline__ void split2(float x0, float x1, uint32_t& hi, uint32_t& lo) {
    uint32_t h;
    asm("cvt.rn.bf16x2.f32 %0, %1, %2;" : "=r"(h) : "f"(x1), "f"(x0));
    float h0 = __uint_as_float(h << 16);
    float h1 = __uint_as_float(h & 0xFFFF0000u);
    float l0 = x0 - h0, l1 = x1 - h1;
    asm("cvt.rn.bf16x2.f32 %0, %1, %2;" : "=r"(lo) : "f"(l1), "f"(l0));
    hi = h;
}
#define LDMX4(r0, r1, r2, r3, addr) \
    asm volatile("ldmatrix.sync.aligned.m8n8.x4.shared.b16 {%0,%1,%2,%3}, [%4];" \
                 : "=r"(r0), "=r"(r1), "=r"(r2), "=r"(r3) : "r"(addr))
#define LDMX4T(r0, r1, r2, r3, addr) \
    asm volatile("ldmatrix.sync.aligned.m8n8.x4.trans.shared.b16 {%0,%1,%2,%3}, [%4];" \
                 : "=r"(r0), "=r"(r1), "=r"(r2), "=r"(r3) : "r"(addr))
#define MMA16816(d, a, b0, b1) \
    asm volatile("mma.sync.aligned.m16n8k16.row.col.f32.bf16.bf16.f32 " \
                 "{%0,%1,%2,%3}, {%4,%5,%6,%7}, {%8,%9}, {%0,%1,%2,%3};" \
                 : "+f"(d[0]), "+f"(d[1]), "+f"(d[2]), "+f"(d[3]) \
                 : "r"(a[0]), "r"(a[1]), "r"(a[2]), "r"(a[3]), "r"(b0), "r"(b1))

// ---------------- K0: split pass f32 -> hi/lo bf16 ----------------
__global__ __launch_bounds__(256) void split_kernel(
    const float* __restrict__ src, __nv_bfloat16* __restrict__ hi,
    __nv_bfloat16* __restrict__ lo, int n4)
{
    int idx = blockIdx.x * 256 + threadIdx.x;
    if (idx >= n4) return;
    float4 v = ((const float4*)src)[idx];
    uint2 h, l;
    split2(v.x, v.y, h.x, l.x);
    split2(v.z, v.w, h.y, l.y);
    *(uint2*)&hi[(size_t)idx * 4] = h;
    *(uint2*)&lo[(size_t)idx * 4] = l;
}

// ---------------- K1/K9: split-bf16 mma.sync GEMM on PRE-SPLIT operands ----------------
// C[M,N] = (Ah+Al)[M,K] @ (Bh+Bl)[N,K]^T + bias. Same smem layout / MMA core as R5;
// only the loader changed: plain uint4 LDG -> STS.128, no conversion ALU.
#define BM 128
#define BN 128
#define BK 32
#define LDT 40   /* padded bf16 row stride (80B) */

__global__ __launch_bounds__(256, 2) void gemm_mma(
    const __nv_bfloat16* __restrict__ Agh, const __nv_bfloat16* __restrict__ Agl,
    const __nv_bfloat16* __restrict__ Bgh, const __nv_bfloat16* __restrict__ Bgl,
    const float* __restrict__ bias, float* __restrict__ C,
    int M, int N, int K)
{
    __shared__ __align__(16) __nv_bfloat16 Ah[BM * LDT];
    __shared__ __align__(16) __nv_bfloat16 Al[BM * LDT];
    __shared__ __align__(16) __nv_bfloat16 Bh[BN * LDT];
    __shared__ __align__(16) __nv_bfloat16 Bl[BN * LDT];

    int tid = threadIdx.x;
    int warp = tid >> 5, lane = tid & 31;
    int wm = warp & 3, wn = warp >> 2;
    int m0 = blockIdx.y * BM, n0 = blockIdx.x * BN;

    float acc[2][8][4];
#pragma unroll
    for (int mi = 0; mi < 2; mi++)
#pragma unroll
        for (int ni = 0; ni < 8; ni++)
#pragma unroll
            for (int e = 0; e < 4; e++) acc[mi][ni][e] = 0.f;

    int r0 = tid >> 2;            // 0..63
    int c8 = (tid & 3) * 8;       // bf16 col: 0,8,16,24

    uint32_t ah_b = smem_u32(Ah), al_b = smem_u32(Al);
    uint32_t bh_b = smem_u32(Bh), bl_b = smem_u32(Bl);

    int lrow16 = lane & 15;
    int lkoff  = (lane >> 4) * 8;

    const uint4 zz = make_uint4(0, 0, 0, 0);

    for (int k0 = 0; k0 < K; k0 += BK) {
        // ---- load pre-split tiles: 8 LDG.128 + 8 STS.128 per thread ----
#pragma unroll
        for (int u = 0; u < 2; u++) {
            int r = r0 + u * 64;
            uint32_t soff = (uint32_t)(r * LDT + c8) * 2;
            size_t goff = (size_t)(m0 + r) * K + k0 + c8;
            uint4 va = *(const uint4*)&Agh[goff];
            *(uint4*)((char*)Ah + soff) = va;
            uint4 vb = *(const uint4*)&Agl[goff];
            *(uint4*)((char*)Al + soff) = vb;
            bool ok = (n0 + r) < N;
            size_t goffb = (size_t)(ok ? (n0 + r) : 0) * K + k0 + c8;
            uint4 vc = ok ? *(const uint4*)&Bgh[goffb] : zz;
            *(uint4*)((char*)Bh + soff) = vc;
            uint4 vd = ok ? *(const uint4*)&Bgl[goffb] : zz;
            *(uint4*)((char*)Bl + soff) = vd;
        }
        __syncthreads();

        // ---- compute: 2 k16 steps (identical to R5 core) ----
#pragma unroll
        for (int ks = 0; ks < BK; ks += 16) {
            uint32_t ahf[2][4], alf[2][4];
#pragma unroll
            for (int mi = 0; mi < 2; mi++) {
                uint32_t off = (uint32_t)((wm * 32 + mi * 16 + lrow16) * LDT + ks + lkoff) * 2;
                LDMX4(ahf[mi][0], ahf[mi][1], ahf[mi][2], ahf[mi][3], ah_b + off);
                LDMX4(alf[mi][0], alf[mi][1], alf[mi][2], alf[mi][3], al_b + off);
            }
#pragma unroll
            for (int nt = 0; nt < 4; nt++) {
                uint32_t off = (uint32_t)((wn * 64 + nt * 16 + lrow16) * LDT + ks + lkoff) * 2;
                uint32_t h0, h1, h2, h3, l0, l1, l2, l3;
                LDMX4(h0, h1, h2, h3, bh_b + off);
                LDMX4(l0, l1, l2, l3, bl_b + off);
#pragma unroll
                for (int mi = 0; mi < 2; mi++) {
                    MMA16816(acc[mi][nt * 2 + 0], ahf[mi], h0, h2);
                    MMA16816(acc[mi][nt * 2 + 0], alf[mi], h0, h2);
                    MMA16816(acc[mi][nt * 2 + 0], ahf[mi], l0, l2);
                    MMA16816(acc[mi][nt * 2 + 1], ahf[mi], h1, h3);
                    MMA16816(acc[mi][nt * 2 + 1], alf[mi], h1, h3);
                    MMA16816(acc[mi][nt * 2 + 1], ahf[mi], l1, l3);
                }
            }
        }
        __syncthreads();
    }

    int rbase = m0 + wm * 32 + (lane >> 2);
    int cbase = n0 + wn * 64 + (lane & 3) * 2;
#pragma unroll
    for (int mi = 0; mi < 2; mi++) {
#pragma unroll
        for (int ni = 0; ni < 8; ni++) {
            int col = cbase + ni * 8;
            if (col < N) {
                float2 bb = *(const float2*)&bias[col];
                int r = rbase + mi * 16;
                float2 v0 = make_float2(acc[mi][ni][0] + bb.x, acc[mi][ni][1] + bb.y);
                *(float2*)&C[(size_t)r * N + col] = v0;
                float2 v1 = make_float2(acc[mi][ni][2] + bb.x, acc[mi][ni][3] + bb.y);
                *(float2*)&C[(size_t)(r + 8) * N + col] = v1;
            }
        }
    }
}

// ---------------- K2: dt softplus + per-chunk inclusive cumsum of A*dt ----------------
__global__ __launch_bounds__(256) void dt_scan_kernel(
    const float* __restrict__ dt_bias, const float* __restrict__ A_log)
{
    int blk = blockIdx.x;
    int c = blk % NC; int bh = blk / NC;
    int h = bh % NH;  int b = bh / NH;
    int t = threadIdx.x;
    int l = c * CHUNK + t;

    float x = g_zxbcdt[(size_t)(b * SEQ + l) * DIP + OFF_DT + h] + dt_bias[h];
    float sp = (x > 20.f) ? x : log1pf(expf(x));
    g_dtsp[(b * SEQ + l) * NH + h] = sp;
    float da = -expf(A_log[h]) * sp;

    __shared__ float s[CHUNK];
    s[t] = da;
    __syncthreads();
    for (int off = 1; off < CHUNK; off <<= 1) {
        float v = (t >= off) ? s[t - off] : 0.f;
        __syncthreads();
        s[t] += v;
        __syncthreads();
    }
    int base = ((b * NH + h) * NC + c) * CHUNK;
    g_dacs[base + t] = s[t];
    if (t == CHUNK - 1) g_csum[(b * NH + h) * NC + c] = s[t];
}

// ---------------- K3: causal depthwise conv4 + SiLU + scatter ----------------
__global__ __launch_bounds__(256) void conv_kernel(
    const float* __restrict__ conv_w, const float* __restrict__ conv_b)
{
    int tok = blockIdx.x;
    int ch = blockIdx.y * 256 + threadIdx.x;
    if (ch >= CONVD) return;
    int b = tok / SEQ, l = tok % SEQ;

    const float* w = conv_w + ch * 4;
    float acc = conv_b[ch];
#pragma unroll
    for (int j = 0; j < 4; j++) {
        int ls = l - 3 + j;
        if (ls >= 0)
            acc += w[j] * g_zxbcdt[(size_t)(b * SEQ + ls) * DIP + DI + ch];
    }
    float v = acc / (1.f + __expf(-acc));

    int c = l / CHUNK, t = l % CHUNK;
    if (ch < DI) {
        int h = ch >> 7, p = ch & 127;
        float dt = g_dtsp[(b * SEQ + l) * NH + h];
        g_X[(size_t)(((b * NC + c) * NH + h) * CHUNK + t) * HD + p] = v * dt;
    } else if (ch < DI + DS) {
        g_Bm[((b * NC + c) * CHUNK + t) * DS + (ch - DI)] = v;
    } else {
        g_Cm[((b * NC + c) * CHUNK + t) * DS + (ch - DI - DS)] = v;
    }
}

// ---------------- K4: G[l,s] = sum_n C[l,n] B[s,n] per (b,c) ----------------
__global__ __launch_bounds__(256) void bc_gemm_kernel()
{
    int bc = blockIdx.y;
    int tile = blockIdx.x;
    int l0 = (tile >> 2) * 64, s0 = (tile & 3) * 64;
    __shared__ float Cs[64][65];
    __shared__ float Bs[64][65];
    int tid = threadIdx.x;
    const float* Cb = g_Cm + (size_t)bc * CHUNK * DS;
    const float* Bb = g_Bm + (size_t)bc * CHUNK * DS;

#pragma unroll
    for (int u = 0; u < 4; u++) {
        int e = tid + u * 256;
        int r = e >> 4, cv = (e & 15) << 2;
        float4 vc = *(const float4*)&Cb[(l0 + r) * DS + cv];
        Cs[r][cv + 0] = vc.x; Cs[r][cv + 1] = vc.y; Cs[r][cv + 2] = vc.z; Cs[r][cv + 3] = vc.w;
        float4 vb = *(const float4*)&Bb[(s0 + r) * DS + cv];
        Bs[r][cv + 0] = vb.x; Bs[r][cv + 1] = vb.y; Bs[r][cv + 2] = vb.z; Bs[r][cv + 3] = vb.w;
    }
    __syncthreads();

    int sq = tid & 15, lq = tid >> 4;
    float acc[4][4];
#pragma unroll
    for (int i = 0; i < 4; i++)
#pragma unroll
        for (int j = 0; j < 4; j++) acc[i][j] = 0.f;

#pragma unroll 8
    for (int n = 0; n < 64; n++) {
        float a[4], bb[4];
#pragma unroll
        for (int i = 0; i < 4; i++) a[i] = Cs[lq * 4 + i][n];
#pragma unroll
        for (int j = 0; j < 4; j++) bb[j] = Bs[sq * 4 + j][n];
#pragma unroll
        for (int i = 0; i < 4; i++)
#pragma unroll
            for (int j = 0; j < 4; j++) acc[i][j] = fmaf(a[i], bb[j], acc[i][j]);
    }
    float* Gout = g_G + (size_t)bc * CHUNK * CHUNK;
#pragma unroll
    for (int i = 0; i < 4; i++) {
        float4 v = make_float4(acc[i][0], acc[i][1], acc[i][2], acc[i][3]);
        *(float4*)&Gout[(l0 + lq * 4 + i) * CHUNK + s0 + sq * 4] = v;
    }
}

// ---------------- K5: Y_diag = (G .* L) @ X per (b,c,h), split-bf16 mma (R8) ----------------
#define YLDT 40
#define XLDT 136
#define YSMEM (2*256*YLDT*2 + 2*32*XLDT*2 + 256*4 + 256*4)   /* 60416 */

__global__ __launch_bounds__(512, 1) void ydiag_kernel()
{
    extern __shared__ __align__(16) char ysm[];
    __nv_bfloat16* Msh = (__nv_bfloat16*)ysm;
    __nv_bfloat16* Msl = Msh + 256 * YLDT;
    __nv_bfloat16* Xsh = Msl + 256 * YLDT;
    __nv_bfloat16* Xsl = Xsh + 32 * XLDT;
    float* acs   = (float*)(Xsl + 32 * XLDT);
    float* cfall = acs + 256;

    uint32_t msh_b = smem_u32(Msh), msl_b = smem_u32(Msl);
    uint32_t xsh_b = smem_u32(Xsh), xsl_b = smem_u32(Xsl);

    int blk = blockIdx.x;
    int h = blk % NH; int bc = blk / NH;
    int c = bc % NC;  int b = bc / NC;
    int tid = threadIdx.x;
    int warp = tid >> 5, lane = tid & 31;
    int wm = warp & 7, wn = warp >> 3;

    if (tid < 256) acs[tid] = g_dacs[((b * NH + h) * NC + c) * CHUNK + tid];
    __syncthreads();
    if (tid < 256) cfall[tid] = __expf(acs[tid & ~31] - acs[tid]);
    __syncthreads();

    const float* Gb = g_G + (size_t)bc * CHUNK * CHUNK;
    const float* Xb = g_X + (size_t)blk * CHUNK * HD;

    float acc[2][8][4];
#pragma unroll
    for (int mi = 0; mi < 2; mi++)
#pragma unroll
        for (int ni = 0; ni < 8; ni++)
#pragma unroll
            for (int e = 0; e < 4; e++) acc[mi][ni][e] = 0.f;

    int lrow16 = lane & 15, lkoff = (lane >> 4) * 8;
    int bl = tid >> 1, bs = (tid & 1) * 16;
    int i8 = lane & 7, sel = lane >> 3;

    for (int s0 = 0; s0 < CHUNK; s0 += 32) {
        if (s0) __syncthreads();

#pragma unroll
        for (int u = 0; u < 2; u++) {
            int e = tid + u * 512;
            int s = e >> 5, p4 = e & 31;
            float4 v = *(const float4*)&Xb[(s0 + s) * HD + p4 * 4];
            uint32_t h0, l0, h1, l1;
            split2(v.x, v.y, h0, l0);
            split2(v.z, v.w, h1, l1);
            uint32_t off = (uint32_t)(s * XLDT + p4 * 4) * 2;
            asm volatile("st.shared.v2.b32 [%0], {%1,%2};" :: "r"(xsh_b + off), "r"(h0), "r"(h1) : "memory");
            asm volatile("st.shared.v2.b32 [%0], {%1,%2};" :: "r"(xsl_b + off), "r"(l0), "r"(l1) : "memory");
        }

        if (bl >= s0 - 32) {
            float rowfac = __expf(acs[bl] - acs[s0]);
#pragma unroll
            for (int j4 = 0; j4 < 4; j4++) {
                int sg = s0 + bs + j4 * 4;
                float4 g4 = *(const float4*)&Gb[bl * CHUNK + sg];
                float m0 = (sg + 0 <= bl) ? g4.x * rowfac * cfall[sg + 0] : 0.f;
                float m1 = (sg + 1 <= bl) ? g4.y * rowfac * cfall[sg + 1] : 0.f;
                float m2 = (sg + 2 <= bl) ? g4.z * rowfac * cfall[sg + 2] : 0.f;
                float m3 = (sg + 3 <= bl) ? g4.w * rowfac * cfall[sg + 3] : 0.f;
                uint32_t h01, l01, h23, l23;
                split2(m0, m1, h01, l01);
                split2(m2, m3, h23, l23);
                uint32_t off = (uint32_t)(bl * YLDT + bs + j4 * 4) * 2;
                asm volatile("st.shared.v2.b32 [%0], {%1,%2};" :: "r"(msh_b + off), "r"(h01), "r"(h23) : "memory");
                asm volatile("st.shared.v2.b32 [%0], {%1,%2};" :: "r"(msl_b + off), "r"(l01), "r"(l23) : "memory");
            }
        }
        __syncthreads();

        if (wm * 32 + 31 >= s0) {
#pragma unroll
            for (int ks = 0; ks < 32; ks += 16) {
                uint32_t ahf[2][4], alf[2][4];
#pragma unroll
                for (int mi = 0; mi < 2; mi++) {
                    uint32_t off = (uint32_t)((wm * 32 + mi * 16 + lrow16) * YLDT + ks + lkoff) * 2;
                    LDMX4(ahf[mi][0], ahf[mi][1], ahf[mi][2], ahf[mi][3], msh_b + off);
                    LDMX4(alf[mi][0], alf[mi][1], alf[mi][2], alf[mi][3], msl_b + off);
                }
#pragma unroll
                for (int nt = 0; nt < 4; nt++) {
                    uint32_t xoff = (uint32_t)((ks + (sel >> 1) * 8 + i8) * XLDT
                                               + wn * 64 + nt * 16 + (sel & 1) * 8) * 2;
                    uint32_t h0, h1, h2, h3, l0, l1, l2, l3;
                    LDMX4T(h0, h1, h2, h3, xsh_b + xoff);
                    LDMX4T(l0, l1, l2, l3, xsl_b + xoff);
#pragma unroll
                    for (int mi = 0; mi < 2; mi++) {
                        MMA16816(acc[mi][nt * 2 + 0], ahf[mi], h0, h2);
                        MMA16816(acc[mi][nt * 2 + 0], alf[mi], h0, h2);
                        MMA16816(acc[mi][nt * 2 + 0], ahf[mi], l0, l2);
                        MMA16816(acc[mi][nt * 2 + 1], ahf[mi], h1, h3);
                        MMA16816(acc[mi][nt * 2 + 1], alf[mi], h1, h3);
                        MMA16816(acc[mi][nt * 2 + 1], ahf[mi], l1, l3);
                    }
                }
            }
        }
    }

    int rbase = wm * 32 + (lane >> 2);
    int cbase = wn * 64 + (lane & 3) * 2;
#pragma unroll
    for (int mi = 0; mi < 2; mi++) {
#pragma unroll
        for (int ni = 0; ni < 8; ni++) {
            int l0r = rbase + mi * 16;
            int col = cbase + ni * 8;
            float* out0 = g_y + (size_t)(b * SEQ + c * CHUNK + l0r) * DI + h * HD + col;
            *(float2*)out0 = make_float2(acc[mi][ni][0], acc[mi][ni][1]);
            float* out1 = g_y + (size_t)(b * SEQ + c * CHUNK + l0r + 8) * DI + h * HD + col;
            *(float2*)out1 = make_float2(acc[mi][ni][2], acc[mi][ni][3]);
        }
    }
}

// ---------------- K5b: local states[p,n] = sum_l X[l,p]*decay[l]*B[l,n] (R8 SIMT) ----------------
__global__ __launch_bounds__(256) void states_kernel()
{
    int blk = blockIdx.x;
    int h = blk % NH; int bc = blk / NH;
    int c = bc % NC;  int b = bc / NC;

    __shared__ __align__(16) float Xs[32][128];
    __shared__ __align__(16) float Bs[32][64];
    __shared__ float ws[32];
    __shared__ float acs[CHUNK];
    int tid = threadIdx.x;
    if (tid < 256) acs[tid] = g_dacs[((b * NH + h) * NC + c) * CHUNK + tid];
    __syncthreads();
    float alast = acs[CHUNK - 1];

    const float* Xb = g_X + (size_t)blk * CHUNK * HD;
    const float* Bb = g_Bm + (size_t)bc * CHUNK * DS;

    int nq = tid & 7, pq = tid >> 3;
    float acc[4][8];
#pragma unroll
    for (int i = 0; i < 4; i++)
#pragma unroll
        for (int j = 0; j < 8; j++) acc[i][j] = 0.f;

    for (int l0 = 0; l0 < CHUNK; l0 += 32) {
#pragma unroll
        for (int u = 0; u < 4; u++) {
            int e = tid + u * 256;
            int r = e >> 5, cv = (e & 31) << 2;
            *(float4*)&Xs[r][cv] = *(const float4*)&Xb[(l0 + r) * HD + cv];
        }
#pragma unroll
        for (int u = 0; u < 2; u++) {
            int e = tid + u * 256;
            int r = e >> 4, cv = (e & 15) << 2;
            *(float4*)&Bs[r][cv] = *(const float4*)&Bb[(l0 + r) * DS + cv];
        }
        if (tid < 32) ws[tid] = __expf(alast - acs[l0 + tid]);
        __syncthreads();
#pragma unroll
        for (int lt = 0; lt < 32; lt++) {
            float w = ws[lt];
            float a[4];
#pragma unroll
            for (int i = 0; i < 4; i++) a[i] = Xs[lt][pq * 4 + i] * w;
            float bb[8];
#pragma unroll
            for (int j = 0; j < 8; j++) bb[j] = Bs[lt][nq * 8 + j];
#pragma unroll
            for (int i = 0; i < 4; i++)
#pragma unroll
                for (int j = 0; j < 8; j++)
                    acc[i][j] = fmaf(a[i], bb[j], acc[i][j]);
        }
        __syncthreads();
    }
    float* So = g_states + (size_t)blk * HD * DS;
#pragma unroll
    for (int i = 0; i < 4; i++) {
#pragma unroll
        for (int j = 0; j < 8; j += 4) {
            float4 v = make_float4(acc[i][j], acc[i][j + 1], acc[i][j + 2], acc[i][j + 3]);
            *(float4*)&So[(pq * 4 + i) * DS + nq * 8 + j] = v;
        }
    }
}

// ---------------- K6: inter-chunk scan ----------------
__global__ __launch_bounds__(256) void scan_kernel()
{
    int bh = blockIdx.x;
    int b = bh / NH, h = bh % NH;
    int tid = threadIdx.x;
    float S[32];
#pragma unroll
    for (int k = 0; k < 32; k++) S[k] = 0.f;
    for (int c = 0; c < NC; c++) {
        float dec = __expf(g_csum[bh * NC + c]);
        size_t base = (size_t)((b * NC + c) * NH + h) * HD * DS;
#pragma unroll
        for (int k = 0; k < 32; k++) {
            int e = tid + k * 256;
            g_inter[base + e] = S[k];
            S[k] = S[k] * dec + g_states[base + e];
        }
    }
}

// ---------------- K7: Y_off + combine + silu(z) gate (R8 SIMT) ----------------
__global__ __launch_bounds__(256) void yoff_kernel()
{
    int blk = blockIdx.x;
    int h = blk % NH; int bc = blk / NH;
    int c = bc % NC;  int b = bc / NC;

    __shared__ float Is[HD][DS + 1];
    __shared__ float Cs[64][DS + 1];
    __shared__ float acs[CHUNK];
    int tid = threadIdx.x;
    if (tid < 256) acs[tid] = g_dacs[((b * NH + h) * NC + c) * CHUNK + tid];

    const float* Ib = g_inter + (size_t)blk * HD * DS;
#pragma unroll
    for (int u = 0; u < 8; u++) {
        int e = tid + u * 256;
        int r = e >> 4, cv = (e & 15) << 2;
        float4 v = *(const float4*)&Ib[r * DS + cv];
        Is[r][cv + 0] = v.x; Is[r][cv + 1] = v.y; Is[r][cv + 2] = v.z; Is[r][cv + 3] = v.w;
    }

    int tq = tid & 7, pq = tid >> 3;
    const float* Cb = g_Cm + (size_t)bc * CHUNK * DS;

    for (int tg = 0; tg < 4; tg++) {
        __syncthreads();
#pragma unroll
        for (int u = 0; u < 4; u++) {
            int e = tid + u * 256;
            int r = e >> 4, cv = (e & 15) << 2;
            float4 v = *(const float4*)&Cb[(tg * 64 + r) * DS + cv];
            Cs[r][cv + 0] = v.x; Cs[r][cv + 1] = v.y; Cs[r][cv + 2] = v.z; Cs[r][cv + 3] = v.w;
        }
        __syncthreads();

        float acc[8][4];
#pragma unroll
        for (int k = 0; k < 8; k++)
#pragma unroll
            for (int i = 0; i < 4; i++) acc[k][i] = 0.f;

#pragma unroll 4
        for (int n = 0; n < DS; n++) {
            float iv[4];
#pragma unroll
            for (int i = 0; i < 4; i++) iv[i] = Is[pq * 4 + i][n];
#pragma unroll
            for (int k = 0; k < 8; k++) {
                float cv = Cs[k * 8 + tq][n];
#pragma unroll
                for (int i = 0; i < 4; i++)
                    acc[k][i] = fmaf(cv, iv[i], acc[k][i]);
            }
        }

#pragma unroll
        for (int k = 0; k < 8; k++) {
            int t = tg * 64 + k * 8 + tq;
            float ea = __expf(acs[t]);
            int gl = c * CHUNK + t;
            size_t yidx = (size_t)(b * SEQ + gl) * DI + h * HD + pq * 4;
            size_t zidx = (size_t)(b * SEQ + gl) * DIP + h * HD + pq * 4;
            float4 yd = *(float4*)&g_y[yidx];
            float4 z  = *(const float4*)&g_zxbcdt[zidx];
            float4 o;
            o.x = (yd.x + ea * acc[k][0]) * z.x / (1.f + __expf(-z.x));
            o.y = (yd.y + ea * acc[k][1]) * z.y / (1.f + __expf(-z.y));
            o.z = (yd.z + ea * acc[k][2]) * z.z / (1.f + __expf(-z.z));
            o.w = (yd.w + ea * acc[k][3]) * z.w / (1.f + __expf(-z.w));
            *(float4*)&g_y[yidx] = o;
        }
    }
}

// ---------------- K8: layernorm over 4096, emits split bf16 hi/lo ----------------
__global__ __launch_bounds__(256) void ln_kernel(
    const float* __restrict__ ln_w, const float* __restrict__ ln_b)
{
    int tok = blockIdx.x;
    const float* y = g_y + (size_t)tok * DI;
    __nv_bfloat16* ohi = g_yn_hi + (size_t)tok * DI;
    __nv_bfloat16* olo = g_yn_lo + (size_t)tok * DI;
    int tid = threadIdx.x;

    float v[16];
    float s = 0.f, ss = 0.f;
#pragma unroll
    for (int u = 0; u < 4; u++) {
        float4 x = *(const float4*)&y[tid * 4 + u * 1024];
        v[u * 4 + 0] = x.x; v[u * 4 + 1] = x.y; v[u * 4 + 2] = x.z; v[u * 4 + 3] = x.w;
        s += x.x + x.y + x.z + x.w;
        ss += x.x * x.x + x.y * x.y + x.z * x.z + x.w * x.w;
    }
#pragma unroll
    for (int off = 16; off; off >>= 1) {
        s  += __shfl_xor_sync(0xFFFFFFFFu, s, off);
        ss += __shfl_xor_sync(0xFFFFFFFFu, ss, off);
    }
    __shared__ float rs[8], rss[8];
    int warp = tid >> 5, lane = tid & 31;
    if (lane == 0) { rs[warp] = s; rss[warp] = ss; }
    __syncthreads();
    s = 0.f; ss = 0.f;
#pragma unroll
    for (int w = 0; w < 8; w++) { s += rs[w]; ss += rss[w]; }
    float mu = s * (1.f / DI);
    float var = ss * (1.f / DI) - mu * mu;
    float rstd = rsqrtf(var + 1e-5f);
#pragma unroll
    for (int u = 0; u < 4; u++) {
        int idx = tid * 4 + u * 1024;
        float4 w4 = *(const float4*)&ln_w[idx];
        float4 b4 = *(const float4*)&ln_b[idx];
        float o0 = (v[u * 4 + 0] - mu) * rstd * w4.x + b4.x;
        float o1 = (v[u * 4 + 1] - mu) * rstd * w4.y + b4.y;
        float o2 = (v[u * 4 + 2] - mu) * rstd * w4.z + b4.z;
        float o3 = (v[u * 4 + 3] - mu) * rstd * w4.w + b4.w;
        uint2 hh, ll;
        split2(o0, o1, hh.x, ll.x);
        split2(o2, o3, hh.y, ll.y);
        *(uint2*)&ohi[idx] = hh;
        *(uint2*)&olo[idx] = ll;
    }
}

// ---------------- launch ----------------
extern "C" void kernel_launch(void* const* d_in, const int* in_sizes, int n_in,
                              void* d_out, int out_size)
{
    const float* u          = (const float*)d_in[0];
    const float* in_proj_w  = (const float*)d_in[1];
    const float* in_proj_b  = (const float*)d_in[2];
    const float* conv_w     = (const float*)d_in[3];
    const float* conv_b     = (const float*)d_in[4];
    const float* dt_bias    = (const float*)d_in[5];
    const float* A_log      = (const float*)d_in[6];
    const float* ln_w       = (const float*)d_in[7];
    const float* ln_b       = (const float*)d_in[8];
    const float* out_proj_w = (const float*)d_in[9];
    const float* out_proj_b = (const float*)d_in[10];
    float* out = (float*)d_out;

    float* zx; cudaGetSymbolAddress((void**)&zx, g_zxbcdt);
    __nv_bfloat16 *uh, *ul, *w1h, *w1l, *w2h, *w2l, *ynh, *ynl;
    cudaGetSymbolAddress((void**)&uh,  g_u_hi);
    cudaGetSymbolAddress((void**)&ul,  g_u_lo);
    cudaGetSymbolAddress((void**)&w1h, g_w1_hi);
    cudaGetSymbolAddress((void**)&w1l, g_w1_lo);
    cudaGetSymbolAddress((void**)&w2h, g_w2_hi);
    cudaGetSymbolAddress((void**)&w2l, g_w2_lo);
    cudaGetSymbolAddress((void**)&ynh, g_yn_hi);
    cudaGetSymbolAddress((void**)&ynl, g_yn_lo);

    cudaFuncSetAttribute(ydiag_kernel, cudaFuncAttributeMaxDynamicSharedMemorySize, YSMEM);

    // K0: pre-split u / weights into bf16 hi/lo
    split_kernel<<<(TOK * DM / 4 + 255) / 256, 256>>>(u, uh, ul, TOK * DM / 4);
    split_kernel<<<(DIP * DM / 4 + 255) / 256, 256>>>(in_proj_w, w1h, w1l, DIP * DM / 4);
    split_kernel<<<(DM * DI / 4 + 255) / 256, 256>>>(out_proj_w, w2h, w2l, DM * DI / 4);

    // K1: in_proj GEMM (8192 x 8352 x 2048)
    gemm_mma<<<dim3((DIP + BN - 1) / BN, TOK / BM), 256>>>(
        uh, ul, w1h, w1l, in_proj_b, zx, TOK, DIP, DM);
    // K2: dt softplus + per-chunk cumsum
    dt_scan_kernel<<<BATCH * NH * NC, CHUNK>>>(dt_bias, A_log);
    // K3: conv + silu + scatter
    conv_kernel<<<dim3(TOK, (CONVD + 255) / 256), 256>>>(conv_w, conv_b);
    // K4: G = C B^T per (b,c)
    bc_gemm_kernel<<<dim3(16, BATCH * NC), 256>>>();
    // K5: Y_diag (split-bf16 mma)
    ydiag_kernel<<<BATCH * NC * NH, 512, YSMEM>>>();
    // K5b: local chunk states
    states_kernel<<<BATCH * NC * NH, 256>>>();
    // K6: inter-chunk scan
    scan_kernel<<<BATCH * NH, 256>>>();
    // K7: Y_off + gate
    yoff_kernel<<<BATCH * NC * NH, 256>>>();
    // K8: layernorm (emits bf16 hi/lo)
    ln_kernel<<<TOK, 256>>>(ln_w, ln_b);
    // K9: out_proj GEMM (8192 x 2048 x 4096)
    gemm_mma<<<dim3(DM / BN, TOK / BM), 256>>>(
        ynh, ynl, w2h, w2l, out_proj_b, out, TOK, DM, DI);
}

// round 12
// speedup vs baseline: 1.2646x; 1.0534x over previous
#include <cuda_runtime.h>
#include <cuda_bf16.h>
#include <math.h>
#include <stdint.h>

#define BATCH 2
#define SEQ   4096
#define DM    2048
#define DI    4096
#define NH    32
#define HD    128
#define DS    64
#define CONVD (DI + 2*DS)          /* 4224 */
#define DIP   (2*DI + 2*DS + NH)   /* 8352 */
#define OFF_DT (DI + CONVD)        /* 8320 */
#define CHUNK 256
#define NC    (SEQ/CHUNK)          /* 16 */
#define TOK   (BATCH*SEQ)          /* 8192 */

// ---------------- scratch (device globals; no allocation allowed) ----------------
__device__ float g_zxbcdt[(size_t)TOK*DIP];
__device__ float g_dtsp[TOK*NH];
__device__ float g_dacs[BATCH*NH*NC*CHUNK];
__device__ float g_csum[BATCH*NH*NC];
__device__ float g_X[(size_t)BATCH*NC*NH*CHUNK*HD];
__device__ float g_Bm[BATCH*NC*CHUNK*DS];
__device__ float g_Cm[BATCH*NC*CHUNK*DS];
__device__ float g_G[BATCH*NC*CHUNK*CHUNK];
__device__ float g_states[(size_t)BATCH*NC*NH*HD*DS];
__device__ float g_inter[(size_t)BATCH*NC*NH*HD*DS];
__device__ float g_y[(size_t)TOK*DI];
// pre-split bf16 operands for the two big GEMMs
__device__ __nv_bfloat16 g_u_hi[(size_t)TOK*DM];
__device__ __nv_bfloat16 g_u_lo[(size_t)TOK*DM];
__device__ __nv_bfloat16 g_w1_hi[(size_t)DIP*DM];
__device__ __nv_bfloat16 g_w1_lo[(size_t)DIP*DM];
__device__ __nv_bfloat16 g_w2_hi[(size_t)DM*DI];
__device__ __nv_bfloat16 g_w2_lo[(size_t)DM*DI];
__device__ __nv_bfloat16 g_yn_hi[(size_t)TOK*DI];
__device__ __nv_bfloat16 g_yn_lo[(size_t)TOK*DI];

// ================= helpers =================
__device__ __forceinline__ uint32_t smem_u32(const void* p) {
    uint32_t a;
    asm("{ .reg .u64 t; cvta.to.shared.u64 t, %1; cvt.u32.u64 %0, t; }" : "=r"(a) : "l"(p));
    return a;
}
// split x0,x1 -> hi bf16x2 (rn) and lo bf16x2 (residual)
__device__ __forceinline__ void split2(float x0, float x1, uint32_t& hi, uint32_t& lo) {
    uint32_t h;
    asm("cvt.rn.bf16x2.f32 %0, %1, %2;" : "=r"(h) : "f"(x1), "f"(x0));
    float h0 = __uint_as_float(h << 16);
    float h1 = __uint_as_float(h & 0xFFFF0000u);
    float l0 = x0 - h0, l1 = x1 - h1;
    asm("cvt.rn.bf16x2.f32 %0, %1, %2;" : "=r"(lo) : "f"(l1), "f"(l0));
    hi = h;
}
#define LDMX4(r0, r1, r2, r3, addr) \
    asm volatile("ldmatrix.sync.aligned.m8n8.x4.shared.b16 {%0,%1,%2,%3}, [%4];" \
                 : "=r"(r0), "=r"(r1), "=r"(r2), "=r"(r3) : "r"(addr))
#define LDMX4T(r0, r1, r2, r3, addr) \
    asm volatile("ldmatrix.sync.aligned.m8n8.x4.trans.shared.b16 {%0,%1,%2,%3}, [%4];" \
                 : "=r"(r0), "=r"(r1), "=r"(r2), "=r"(r3) : "r"(addr))
#define MMA16816(d, a, b0, b1) \
    asm volatile("mma.sync.aligned.m16n8k16.row.col.f32.bf16.bf16.f32 " \
                 "{%0,%1,%2,%3}, {%4,%5,%6,%7}, {%8,%9}, {%0,%1,%2,%3};" \
                 : "+f"(d[0]), "+f"(d[1]), "+f"(d[2]), "+f"(d[3]) \
                 : "r"(a[0]), "r"(a[1]), "r"(a[2]), "r"(a[3]), "r"(b0), "r"(b1))
#define CP16(dst, src, nbytes) \
    asm volatile("cp.async.ca.shared.global [%0], [%1], 16, %2;" \
                 :: "r"(dst), "l"(src), "r"(nbytes) : "memory")
#define CPCOMMIT() asm volatile("cp.async.commit_group;" ::: "memory")
#define CPWAIT1()  asm volatile("cp.async.wait_group 1;" ::: "memory")

// ---------------- K0: split pass f32 -> hi/lo bf16 ----------------
__global__ __launch_bounds__(256) void split_kernel(
    const float* __restrict__ src, __nv_bfloat16* __restrict__ hi,
    __nv_bfloat16* __restrict__ lo, int n4)
{
    int idx = blockIdx.x * 256 + threadIdx.x;
    if (idx >= n4) return;
    float4 v = ((const float4*)src)[idx];
    uint2 h, l;
    split2(v.x, v.y, h.x, l.x);
    split2(v.z, v.w, h.y, l.y);
    *(uint2*)&hi[(size_t)idx * 4] = h;
    *(uint2*)&lo[(size_t)idx * 4] = l;
}

// ---------------- K1/K9: cp.async double-buffered split-bf16 mma GEMM ----------------
// C[M,N] = (Ah+Al)[M,K] @ (Bh+Bl)[N,K]^T + bias. Proven LDT=40 layout and MMA core;
// loader = 8 cp.async.128 per thread per stage, 2 stages.
#define BM 128
#define BN 128
#define BK 32
#define LDT 40                        /* padded bf16 row stride (80B) */
#define TARR (BM * LDT * 2)           /* one operand array: 10240 B */
#define STAGE (4 * TARR)              /* Ah,Al,Bh,Bl: 40960 B */
#define GEMM_SMEM (2 * STAGE)         /* 81920 B */

__global__ __launch_bounds__(256, 2) void gemm_mma(
    const __nv_bfloat16* __restrict__ Agh, const __nv_bfloat16* __restrict__ Agl,
    const __nv_bfloat16* __restrict__ Bgh, const __nv_bfloat16* __restrict__ Bgl,
    const float* __restrict__ bias, float* __restrict__ C,
    int M, int N, int K)
{
    extern __shared__ __align__(16) char gsm[];
    uint32_t sb = smem_u32(gsm);

    int tid = threadIdx.x;
    int warp = tid >> 5, lane = tid & 31;
    int wm = warp & 3, wn = warp >> 2;
    int m0 = blockIdx.y * BM, n0 = blockIdx.x * BN;

    float acc[2][8][4];
#pragma unroll
    for (int mi = 0; mi < 2; mi++)
#pragma unroll
        for (int ni = 0; ni < 8; ni++)
#pragma unroll
            for (int e = 0; e < 4; e++) acc[mi][ni][e] = 0.f;

    int r0 = tid >> 2;            // 0..63
    int c8 = (tid & 3) * 8;       // bf16 col: 0,8,16,24

    const size_t arow0 = (size_t)(m0 + r0) * K + c8;
    const size_t arow1 = (size_t)(m0 + r0 + 64) * K + c8;
    const bool ok0 = (n0 + r0) < N;
    const bool ok1 = (n0 + r0 + 64) < N;
    const size_t brow0 = (size_t)(ok0 ? n0 + r0 : 0) * K + c8;
    const size_t brow1 = (size_t)(ok1 ? n0 + r0 + 64 : 0) * K + c8;
    const int nb0 = ok0 ? 16 : 0;
    const int nb1 = ok1 ? 16 : 0;
    const uint32_t so0 = (uint32_t)(r0 * LDT + c8) * 2;
    const uint32_t so1 = (uint32_t)((r0 + 64) * LDT + c8) * 2;

    int lrow16 = lane & 15;
    int lkoff  = (lane >> 4) * 8;

    auto issue = [&](uint32_t st, int k0) {
        CP16(st + so0,            Agh + arow0 + k0, 16);
        CP16(st + so0 + TARR,     Agl + arow0 + k0, 16);
        CP16(st + so0 + 2 * TARR, Bgh + brow0 + k0, nb0);
        CP16(st + so0 + 3 * TARR, Bgl + brow0 + k0, nb0);
        CP16(st + so1,            Agh + arow1 + k0, 16);
        CP16(st + so1 + TARR,     Agl + arow1 + k0, 16);
        CP16(st + so1 + 2 * TARR, Bgh + brow1 + k0, nb1);
        CP16(st + so1 + 3 * TARR, Bgl + brow1 + k0, nb1);
    };

    const int ntiles = K >> 5;     // K >= 2048 -> ntiles >= 64
    issue(sb, 0);          CPCOMMIT();
    issue(sb + STAGE, BK); CPCOMMIT();

    for (int t = 0; t < ntiles; t++) {
        CPWAIT1();
        __syncthreads();
        uint32_t buf = sb + (t & 1) * STAGE;
        uint32_t ah_b = buf, al_b = buf + TARR;
        uint32_t bh_b = buf + 2 * TARR, bl_b = buf + 3 * TARR;

#pragma unroll
        for (int ks = 0; ks < BK; ks += 16) {
            uint32_t ahf[2][4], alf[2][4];
#pragma unroll
            for (int mi = 0; mi < 2; mi++) {
                uint32_t off = (uint32_t)((wm * 32 + mi * 16 + lrow16) * LDT + ks + lkoff) * 2;
                LDMX4(ahf[mi][0], ahf[mi][1], ahf[mi][2], ahf[mi][3], ah_b + off);
                LDMX4(alf[mi][0], alf[mi][1], alf[mi][2], alf[mi][3], al_b + off);
            }
#pragma unroll
            for (int nt = 0; nt < 4; nt++) {
                uint32_t off = (uint32_t)((wn * 64 + nt * 16 + lrow16) * LDT + ks + lkoff) * 2;
                uint32_t h0, h1, h2, h3, l0, l1, l2, l3;
                LDMX4(h0, h1, h2, h3, bh_b + off);
                LDMX4(l0, l1, l2, l3, bl_b + off);
#pragma unroll
                for (int mi = 0; mi < 2; mi++) {
                    MMA16816(acc[mi][nt * 2 + 0], ahf[mi], h0, h2);
                    MMA16816(acc[mi][nt * 2 + 0], alf[mi], h0, h2);
                    MMA16816(acc[mi][nt * 2 + 0], ahf[mi], l0, l2);
                    MMA16816(acc[mi][nt * 2 + 1], ahf[mi], h1, h3);
                    MMA16816(acc[mi][nt * 2 + 1], alf[mi], h1, h3);
                    MMA16816(acc[mi][nt * 2 + 1], ahf[mi], l1, l3);
                }
            }
        }
        __syncthreads();
        if (t + 2 < ntiles) issue(buf, (t + 2) * BK);
        CPCOMMIT();
    }

    int rbase = m0 + wm * 32 + (lane >> 2);
    int cbase = n0 + wn * 64 + (lane & 3) * 2;
#pragma unroll
    for (int mi = 0; mi < 2; mi++) {
#pragma unroll
        for (int ni = 0; ni < 8; ni++) {
            int col = cbase + ni * 8;
            if (col < N) {
                float2 bb = *(const float2*)&bias[col];
                int r = rbase + mi * 16;
                float2 v0 = make_float2(acc[mi][ni][0] + bb.x, acc[mi][ni][1] + bb.y);
                *(float2*)&C[(size_t)r * N + col] = v0;
                float2 v1 = make_float2(acc[mi][ni][2] + bb.x, acc[mi][ni][3] + bb.y);
                *(float2*)&C[(size_t)(r + 8) * N + col] = v1;
            }
        }
    }
}

// ---------------- K2: dt softplus + per-chunk inclusive cumsum of A*dt ----------------
__global__ __launch_bounds__(256) void dt_scan_kernel(
    const float* __restrict__ dt_bias, const float* __restrict__ A_log)
{
    int blk = blockIdx.x;
    int c = blk % NC; int bh = blk / NC;
    int h = bh % NH;  int b = bh / NH;
    int t = threadIdx.x;
    int l = c * CHUNK + t;

    float x = g_zxbcdt[(size_t)(b * SEQ + l) * DIP + OFF_DT + h] + dt_bias[h];
    float sp = (x > 20.f) ? x : log1pf(expf(x));
    g_dtsp[(b * SEQ + l) * NH + h] = sp;
    float da = -expf(A_log[h]) * sp;

    __shared__ float s[CHUNK];
    s[t] = da;
    __syncthreads();
    for (int off = 1; off < CHUNK; off <<= 1) {
        float v = (t >= off) ? s[t - off] : 0.f;
        __syncthreads();
        s[t] += v;
        __syncthreads();
    }
    int base = ((b * NH + h) * NC + c) * CHUNK;
    g_dacs[base + t] = s[t];
    if (t == CHUNK - 1) g_csum[(b * NH + h) * NC + c] = s[t];
}

// ---------------- K3: causal depthwise conv4 + SiLU + scatter ----------------
__global__ __launch_bounds__(256) void conv_kernel(
    const float* __restrict__ conv_w, const float* __restrict__ conv_b)
{
    int tok = blockIdx.x;
    int ch = blockIdx.y * 256 + threadIdx.x;
    if (ch >= CONVD) return;
    int b = tok / SEQ, l = tok % SEQ;

    const float* w = conv_w + ch * 4;
    float acc = conv_b[ch];
#pragma unroll
    for (int j = 0; j < 4; j++) {
        int ls = l - 3 + j;
        if (ls >= 0)
            acc += w[j] * g_zxbcdt[(size_t)(b * SEQ + ls) * DIP + DI + ch];
    }
    float v = acc / (1.f + __expf(-acc));

    int c = l / CHUNK, t = l % CHUNK;
    if (ch < DI) {
        int h = ch >> 7, p = ch & 127;
        float dt = g_dtsp[(b * SEQ + l) * NH + h];
        g_X[(size_t)(((b * NC + c) * NH + h) * CHUNK + t) * HD + p] = v * dt;
    } else if (ch < DI + DS) {
        g_Bm[((b * NC + c) * CHUNK + t) * DS + (ch - DI)] = v;
    } else {
        g_Cm[((b * NC + c) * CHUNK + t) * DS + (ch - DI - DS)] = v;
    }
}

// ---------------- K4: G[l,s] = sum_n C[l,n] B[s,n] per (b,c) ----------------
__global__ __launch_bounds__(256) void bc_gemm_kernel()
{
    int bc = blockIdx.y;
    int tile = blockIdx.x;
    int l0 = (tile >> 2) * 64, s0 = (tile & 3) * 64;
    __shared__ float Cs[64][65];
    __shared__ float Bs[64][65];
    int tid = threadIdx.x;
    const float* Cb = g_Cm + (size_t)bc * CHUNK * DS;
    const float* Bb = g_Bm + (size_t)bc * CHUNK * DS;

#pragma unroll
    for (int u = 0; u < 4; u++) {
        int e = tid + u * 256;
        int r = e >> 4, cv = (e & 15) << 2;
        float4 vc = *(const float4*)&Cb[(l0 + r) * DS + cv];
        Cs[r][cv + 0] = vc.x; Cs[r][cv + 1] = vc.y; Cs[r][cv + 2] = vc.z; Cs[r][cv + 3] = vc.w;
        float4 vb = *(const float4*)&Bb[(s0 + r) * DS + cv];
        Bs[r][cv + 0] = vb.x; Bs[r][cv + 1] = vb.y; Bs[r][cv + 2] = vb.z; Bs[r][cv + 3] = vb.w;
    }
    __syncthreads();

    int sq = tid & 15, lq = tid >> 4;
    float acc[4][4];
#pragma unroll
    for (int i = 0; i < 4; i++)
#pragma unroll
        for (int j = 0; j < 4; j++) acc[i][j] = 0.f;

#pragma unroll 8
    for (int n = 0; n < 64; n++) {
        float a[4], bb[4];
#pragma unroll
        for (int i = 0; i < 4; i++) a[i] = Cs[lq * 4 + i][n];
#pragma unroll
        for (int j = 0; j < 4; j++) bb[j] = Bs[sq * 4 + j][n];
#pragma unroll
        for (int i = 0; i < 4; i++)
#pragma unroll
            for (int j = 0; j < 4; j++) acc[i][j] = fmaf(a[i], bb[j], acc[i][j]);
    }
    float* Gout = g_G + (size_t)bc * CHUNK * CHUNK;
#pragma unroll
    for (int i = 0; i < 4; i++) {
        float4 v = make_float4(acc[i][0], acc[i][1], acc[i][2], acc[i][3]);
        *(float4*)&Gout[(l0 + lq * 4 + i) * CHUNK + s0 + sq * 4] = v;
    }
}

// ---------------- K5: Y_diag = (G .* L) @ X per (b,c,h), split-bf16 mma ----------------
#define YLDT 40
#define XLDT 136
#define YSMEM (2*256*YLDT*2 + 2*32*XLDT*2 + 256*4 + 256*4)   /* 60416 */

__global__ __launch_bounds__(512, 1) void ydiag_kernel()
{
    extern __shared__ __align__(16) char ysm[];
    __nv_bfloat16* Msh = (__nv_bfloat16*)ysm;
    __nv_bfloat16* Msl = Msh + 256 * YLDT;
    __nv_bfloat16* Xsh = Msl + 256 * YLDT;
    __nv_bfloat16* Xsl = Xsh + 32 * XLDT;
    float* acs   = (float*)(Xsl + 32 * XLDT);
    float* cfall = acs + 256;

    uint32_t msh_b = smem_u32(Msh), msl_b = smem_u32(Msl);
    uint32_t xsh_b = smem_u32(Xsh), xsl_b = smem_u32(Xsl);

    int blk = blockIdx.x;
    int h = blk % NH; int bc = blk / NH;
    int c = bc % NC;  int b = bc / NC;
    int tid = threadIdx.x;
    int warp = tid >> 5, lane = tid & 31;
    int wm = warp & 7, wn = warp >> 3;

    if (tid < 256) acs[tid] = g_dacs[((b * NH + h) * NC + c) * CHUNK + tid];
    __syncthreads();
    if (tid < 256) cfall[tid] = __expf(acs[tid & ~31] - acs[tid]);
    __syncthreads();

    const float* Gb = g_G + (size_t)bc * CHUNK * CHUNK;
    const float* Xb = g_X + (size_t)blk * CHUNK * HD;

    float acc[2][8][4];
#pragma unroll
    for (int mi = 0; mi < 2; mi++)
#pragma unroll
        for (int ni = 0; ni < 8; ni++)
#pragma unroll
            for (int e = 0; e < 4; e++) acc[mi][ni][e] = 0.f;

    int lrow16 = lane & 15, lkoff = (lane >> 4) * 8;
    int bl = tid >> 1, bs = (tid & 1) * 16;
    int i8 = lane & 7, sel = lane >> 3;

    for (int s0 = 0; s0 < CHUNK; s0 += 32) {
        if (s0) __syncthreads();

#pragma unroll
        for (int u = 0; u < 2; u++) {
            int e = tid + u * 512;
            int s = e >> 5, p4 = e & 31;
            float4 v = *(const float4*)&Xb[(s0 + s) * HD + p4 * 4];
            uint32_t h0, l0, h1, l1;
            split2(v.x, v.y, h0, l0);
            split2(v.z, v.w, h1, l1);
            uint32_t off = (uint32_t)(s * XLDT + p4 * 4) * 2;
            asm volatile("st.shared.v2.b32 [%0], {%1,%2};" :: "r"(xsh_b + off), "r"(h0), "r"(h1) : "memory");
            asm volatile("st.shared.v2.b32 [%0], {%1,%2};" :: "r"(xsl_b + off), "r"(l0), "r"(l1) : "memory");
        }

        if (bl >= s0 - 32) {
            float rowfac = __expf(acs[bl] - acs[s0]);
#pragma unroll
            for (int j4 = 0; j4 < 4; j4++) {
                int sg = s0 + bs + j4 * 4;
                float4 g4 = *(const float4*)&Gb[bl * CHUNK + sg];
                float m0 = (sg + 0 <= bl) ? g4.x * rowfac * cfall[sg + 0] : 0.f;
                float m1 = (sg + 1 <= bl) ? g4.y * rowfac * cfall[sg + 1] : 0.f;
                float m2 = (sg + 2 <= bl) ? g4.z * rowfac * cfall[sg + 2] : 0.f;
                float m3 = (sg + 3 <= bl) ? g4.w * rowfac * cfall[sg + 3] : 0.f;
                uint32_t h01, l01, h23, l23;
                split2(m0, m1, h01, l01);
                split2(m2, m3, h23, l23);
                uint32_t off = (uint32_t)(bl * YLDT + bs + j4 * 4) * 2;
                asm volatile("st.shared.v2.b32 [%0], {%1,%2};" :: "r"(msh_b + off), "r"(h01), "r"(h23) : "memory");
                asm volatile("st.shared.v2.b32 [%0], {%1,%2};" :: "r"(msl_b + off), "r"(l01), "r"(l23) : "memory");
            }
        }
        __syncthreads();

        if (wm * 32 + 31 >= s0) {
#pragma unroll
            for (int ks = 0; ks < 32; ks += 16) {
                uint32_t ahf[2][4], alf[2][4];
#pragma unroll
                for (int mi = 0; mi < 2; mi++) {
                    uint32_t off = (uint32_t)((wm * 32 + mi * 16 + lrow16) * YLDT + ks + lkoff) * 2;
                    LDMX4(ahf[mi][0], ahf[mi][1], ahf[mi][2], ahf[mi][3], msh_b + off);
                    LDMX4(alf[mi][0], alf[mi][1], alf[mi][2], alf[mi][3], msl_b + off);
                }
#pragma unroll
                for (int nt = 0; nt < 4; nt++) {
                    uint32_t xoff = (uint32_t)((ks + (sel >> 1) * 8 + i8) * XLDT
                                               + wn * 64 + nt * 16 + (sel & 1) * 8) * 2;
                    uint32_t h0, h1, h2, h3, l0, l1, l2, l3;
                    LDMX4T(h0, h1, h2, h3, xsh_b + xoff);
                    LDMX4T(l0, l1, l2, l3, xsl_b + xoff);
#pragma unroll
                    for (int mi = 0; mi < 2; mi++) {
                        MMA16816(acc[mi][nt * 2 + 0], ahf[mi], h0, h2);
                        MMA16816(acc[mi][nt * 2 + 0], alf[mi], h0, h2);
                        MMA16816(acc[mi][nt * 2 + 0], ahf[mi], l0, l2);
                        MMA16816(acc[mi][nt * 2 + 1], ahf[mi], h1, h3);
                        MMA16816(acc[mi][nt * 2 + 1], alf[mi], h1, h3);
                        MMA16816(acc[mi][nt * 2 + 1], ahf[mi], l1, l3);
                    }
                }
            }
        }
    }

    int rbase = wm * 32 + (lane >> 2);
    int cbase = wn * 64 + (lane & 3) * 2;
#pragma unroll
    for (int mi = 0; mi < 2; mi++) {
#pragma unroll
        for (int ni = 0; ni < 8; ni++) {
            int l0r = rbase + mi * 16;
            int col = cbase + ni * 8;
            float* out0 = g_y + (size_t)(b * SEQ + c * CHUNK + l0r) * DI + h * HD + col;
            *(float2*)out0 = make_float2(acc[mi][ni][0], acc[mi][ni][1]);
            float* out1 = g_y + (size_t)(b * SEQ + c * CHUNK + l0r + 8) * DI + h * HD + col;
            *(float2*)out1 = make_float2(acc[mi][ni][2], acc[mi][ni][3]);
        }
    }
}

// ---------------- K5b: local states[p,n] = sum_l X[l,p]*decay[l]*B[l,n] ----------------
__global__ __launch_bounds__(256) void states_kernel()
{
    int blk = blockIdx.x;
    int h = blk % NH; int bc = blk / NH;
    int c = bc % NC;  int b = bc / NC;

    __shared__ __align__(16) float Xs[32][128];
    __shared__ __align__(16) float Bs[32][64];
    __shared__ float ws[32];
    __shared__ float acs[CHUNK];
    int tid = threadIdx.x;
    if (tid < 256) acs[tid] = g_dacs[((b * NH + h) * NC + c) * CHUNK + tid];
    __syncthreads();
    float alast = acs[CHUNK - 1];

    const float* Xb = g_X + (size_t)blk * CHUNK * HD;
    const float* Bb = g_Bm + (size_t)bc * CHUNK * DS;

    int nq = tid & 7, pq = tid >> 3;
    float acc[4][8];
#pragma unroll
    for (int i = 0; i < 4; i++)
#pragma unroll
        for (int j = 0; j < 8; j++) acc[i][j] = 0.f;

    for (int l0 = 0; l0 < CHUNK; l0 += 32) {
#pragma unroll
        for (int u = 0; u < 4; u++) {
            int e = tid + u * 256;
            int r = e >> 5, cv = (e & 31) << 2;
            *(float4*)&Xs[r][cv] = *(const float4*)&Xb[(l0 + r) * HD + cv];
        }
#pragma unroll
        for (int u = 0; u < 2; u++) {
            int e = tid + u * 256;
            int r = e >> 4, cv = (e & 15) << 2;
            *(float4*)&Bs[r][cv] = *(const float4*)&Bb[(l0 + r) * DS + cv];
        }
        if (tid < 32) ws[tid] = __expf(alast - acs[l0 + tid]);
        __syncthreads();
#pragma unroll
        for (int lt = 0; lt < 32; lt++) {
            float w = ws[lt];
            float a[4];
#pragma unroll
            for (int i = 0; i < 4; i++) a[i] = Xs[lt][pq * 4 + i] * w;
            float bb[8];
#pragma unroll
            for (int j = 0; j < 8; j++) bb[j] = Bs[lt][nq * 8 + j];
#pragma unroll
            for (int i = 0; i < 4; i++)
#pragma unroll
                for (int j = 0; j < 8; j++)
                    acc[i][j] = fmaf(a[i], bb[j], acc[i][j]);
        }
        __syncthreads();
    }
    float* So = g_states + (size_t)blk * HD * DS;
#pragma unroll
    for (int i = 0; i < 4; i++) {
#pragma unroll
        for (int j = 0; j < 8; j += 4) {
            float4 v = make_float4(acc[i][j], acc[i][j + 1], acc[i][j + 2], acc[i][j + 3]);
            *(float4*)&So[(pq * 4 + i) * DS + nq * 8 + j] = v;
        }
    }
}

// ---------------- K6: inter-chunk scan (8-way split, float4) ----------------
__global__ __launch_bounds__(256) void scan_kernel()
{
    int blk = blockIdx.x;                 // (b*NH + h)*8 + part
    int part = blk & 7;
    int bh = blk >> 3;
    int b = bh / NH, h = bh % NH;
    int e0 = part * 1024 + threadIdx.x * 4;

    float4 S = make_float4(0.f, 0.f, 0.f, 0.f);
    for (int c = 0; c < NC; c++) {
        float dec = __expf(g_csum[bh * NC + c]);
        size_t base = (size_t)((b * NC + c) * NH + h) * HD * DS + e0;
        *(float4*)&g_inter[base] = S;
        float4 v = *(const float4*)&g_states[base];
        S.x = S.x * dec + v.x;
        S.y = S.y * dec + v.y;
        S.z = S.z * dec + v.z;
        S.w = S.w * dec + v.w;
    }
}

// ---------------- K7: Y_off + combine + silu(z) gate ----------------
__global__ __launch_bounds__(256) void yoff_kernel()
{
    int blk = blockIdx.x;
    int h = blk % NH; int bc = blk / NH;
    int c = bc % NC;  int b = bc / NC;

    __shared__ float Is[HD][DS + 1];
    __shared__ float Cs[64][DS + 1];
    __shared__ float acs[CHUNK];
    int tid = threadIdx.x;
    if (tid < 256) acs[tid] = g_dacs[((b * NH + h) * NC + c) * CHUNK + tid];

    const float* Ib = g_inter + (size_t)blk * HD * DS;
#pragma unroll
    for (int u = 0; u < 8; u++) {
        int e = tid + u * 256;
        int r = e >> 4, cv = (e & 15) << 2;
        float4 v = *(const float4*)&Ib[r * DS + cv];
        Is[r][cv + 0] = v.x; Is[r][cv + 1] = v.y; Is[r][cv + 2] = v.z; Is[r][cv + 3] = v.w;
    }

    int tq = tid & 7, pq = tid >> 3;
    const float* Cb = g_Cm + (size_t)bc * CHUNK * DS;

    for (int tg = 0; tg < 4; tg++) {
        __syncthreads();
#pragma unroll
        for (int u = 0; u < 4; u++) {
            int e = tid + u * 256;
            int r = e >> 4, cv = (e & 15) << 2;
            float4 v = *(const float4*)&Cb[(tg * 64 + r) * DS + cv];
            Cs[r][cv + 0] = v.x; Cs[r][cv + 1] = v.y; Cs[r][cv + 2] = v.z; Cs[r][cv + 3] = v.w;
        }
        __syncthreads();

        float acc[8][4];
#pragma unroll
        for (int k = 0; k < 8; k++)
#pragma unroll
            for (int i = 0; i < 4; i++) acc[k][i] = 0.f;

#pragma unroll 4
        for (int n = 0; n < DS; n++) {
            float iv[4];
#pragma unroll
            for (int i = 0; i < 4; i++) iv[i] = Is[pq * 4 + i][n];
#pragma unroll
            for (int k = 0; k < 8; k++) {
                float cv = Cs[k * 8 + tq][n];
#pragma unroll
                for (int i = 0; i < 4; i++)
                    acc[k][i] = fmaf(cv, iv[i], acc[k][i]);
            }
        }

#pragma unroll
        for (int k = 0; k < 8; k++) {
            int t = tg * 64 + k * 8 + tq;
            float ea = __expf(acs[t]);
            int gl = c * CHUNK + t;
            size_t yidx = (size_t)(b * SEQ + gl) * DI + h * HD + pq * 4;
            size_t zidx = (size_t)(b * SEQ + gl) * DIP + h * HD + pq * 4;
            float4 yd = *(float4*)&g_y[yidx];
            float4 z  = *(const float4*)&g_zxbcdt[zidx];
            float4 o;
            o.x = (yd.x + ea * acc[k][0]) * z.x / (1.f + __expf(-z.x));
            o.y = (yd.y + ea * acc[k][1]) * z.y / (1.f + __expf(-z.y));
            o.z = (yd.z + ea * acc[k][2]) * z.z / (1.f + __expf(-z.z));
            o.w = (yd.w + ea * acc[k][3]) * z.w / (1.f + __expf(-z.w));
            *(float4*)&g_y[yidx] = o;
        }
    }
}

// ---------------- K8: layernorm over 4096, emits split bf16 hi/lo ----------------
__global__ __launch_bounds__(256) void ln_kernel(
    const float* __restrict__ ln_w, const float* __restrict__ ln_b)
{
    int tok = blockIdx.x;
    const float* y = g_y + (size_t)tok * DI;
    __nv_bfloat16* ohi = g_yn_hi + (size_t)tok * DI;
    __nv_bfloat16* olo = g_yn_lo + (size_t)tok * DI;
    int tid = threadIdx.x;

    float v[16];
    float s = 0.f, ss = 0.f;
#pragma unroll
    for (int u = 0; u < 4; u++) {
        float4 x = *(const float4*)&y[tid * 4 + u * 1024];
        v[u * 4 + 0] = x.x; v[u * 4 + 1] = x.y; v[u * 4 + 2] = x.z; v[u * 4 + 3] = x.w;
        s += x.x + x.y + x.z + x.w;
        ss += x.x * x.x + x.y * x.y + x.z * x.z + x.w * x.w;
    }
#pragma unroll
    for (int off = 16; off; off >>= 1) {
        s  += __shfl_xor_sync(0xFFFFFFFFu, s, off);
        ss += __shfl_xor_sync(0xFFFFFFFFu, ss, off);
    }
    __shared__ float rs[8], rss[8];
    int warp = tid >> 5, lane = tid & 31;
    if (lane == 0) { rs[warp] = s; rss[warp] = ss; }
    __syncthreads();
    s = 0.f; ss = 0.f;
#pragma unroll
    for (int w = 0; w < 8; w++) { s += rs[w]; ss += rss[w]; }
    float mu = s * (1.f / DI);
    float var = ss * (1.f / DI) - mu * mu;
    float rstd = rsqrtf(var + 1e-5f);
#pragma unroll
    for (int u = 0; u < 4; u++) {
        int idx = tid * 4 + u * 1024;
        float4 w4 = *(const float4*)&ln_w[idx];
        float4 b4 = *(const float4*)&ln_b[idx];
        float o0 = (v[u * 4 + 0] - mu) * rstd * w4.x + b4.x;
        float o1 = (v[u * 4 + 1] - mu) * rstd * w4.y + b4.y;
        float o2 = (v[u * 4 + 2] - mu) * rstd * w4.z + b4.z;
        float o3 = (v[u * 4 + 3] - mu) * rstd * w4.w + b4.w;
        uint2 hh, ll;
        split2(o0, o1, hh.x, ll.x);
        split2(o2, o3, hh.y, ll.y);
        *(uint2*)&ohi[idx] = hh;
        *(uint2*)&olo[idx] = ll;
    }
}

// ---------------- launch ----------------
extern "C" void kernel_launch(void* const* d_in, const int* in_sizes, int n_in,
                              void* d_out, int out_size)
{
    const float* u          = (const float*)d_in[0];
    const float* in_proj_w  = (const float*)d_in[1];
    const float* in_proj_b  = (const float*)d_in[2];
    const float* conv_w     = (const float*)d_in[3];
    const float* conv_b     = (const float*)d_in[4];
    const float* dt_bias    = (const float*)d_in[5];
    const float* A_log      = (const float*)d_in[6];
    const float* ln_w       = (const float*)d_in[7];
    const float* ln_b       = (const float*)d_in[8];
    const float* out_proj_w = (const float*)d_in[9];
    const float* out_proj_b = (const float*)d_in[10];
    float* out = (float*)d_out;

    float* zx; cudaGetSymbolAddress((void**)&zx, g_zxbcdt);
    __nv_bfloat16 *uh, *ul, *w1h, *w1l, *w2h, *w2l, *ynh, *ynl;
    cudaGetSymbolAddress((void**)&uh,  g_u_hi);
    cudaGetSymbolAddress((void**)&ul,  g_u_lo);
    cudaGetSymbolAddress((void**)&w1h, g_w1_hi);
    cudaGetSymbolAddress((void**)&w1l, g_w1_lo);
    cudaGetSymbolAddress((void**)&w2h, g_w2_hi);
    cudaGetSymbolAddress((void**)&w2l, g_w2_lo);
    cudaGetSymbolAddress((void**)&ynh, g_yn_hi);
    cudaGetSymbolAddress((void**)&ynl, g_yn_lo);

    cudaFuncSetAttribute(gemm_mma, cudaFuncAttributeMaxDynamicSharedMemorySize, GEMM_SMEM);
    cudaFuncSetAttribute(ydiag_kernel, cudaFuncAttributeMaxDynamicSharedMemorySize, YSMEM);

    // K0: pre-split u / weights into bf16 hi/lo
    split_kernel<<<(TOK * DM / 4 + 255) / 256, 256>>>(u, uh, ul, TOK * DM / 4);
    split_kernel<<<(DIP * DM / 4 + 255) / 256, 256>>>(in_proj_w, w1h, w1l, DIP * DM / 4);
    split_kernel<<<(DM * DI / 4 + 255) / 256, 256>>>(out_proj_w, w2h, w2l, DM * DI / 4);

    // K1: in_proj GEMM (8192 x 8352 x 2048)
    gemm_mma<<<dim3((DIP + BN - 1) / BN, TOK / BM), 256, GEMM_SMEM>>>(
        uh, ul, w1h, w1l, in_proj_b, zx, TOK, DIP, DM);
    // K2: dt softplus + per-chunk cumsum
    dt_scan_kernel<<<BATCH * NH * NC, CHUNK>>>(dt_bias, A_log);
    // K3: conv + silu + scatter
    conv_kernel<<<dim3(TOK, (CONVD + 255) / 256), 256>>>(conv_w, conv_b);
    // K4: G = C B^T per (b,c)
    bc_gemm_kernel<<<dim3(16, BATCH * NC), 256>>>();
    // K5: Y_diag (split-bf16 mma)
    ydiag_kernel<<<BATCH * NC * NH, 512, YSMEM>>>();
    // K5b: local chunk states
    states_kernel<<<BATCH * NC * NH, 256>>>();
    // K6: inter-chunk scan (8-way split)
    scan_kernel<<<BATCH * NH * 8, 256>>>();
    // K7: Y_off + gate
    yoff_kernel<<<BATCH * NC * NH, 256>>>();
    // K8: layernorm (emits bf16 hi/lo)
    ln_kernel<<<TOK, 256>>>(ln_w, ln_b);
    // K9: out_proj GEMM (8192 x 2048 x 4096)
    gemm_mma<<<dim3(DM / BN, TOK / BM), 256, GEMM_SMEM>>>(
        ynh, ynl, w2h, w2l, out_proj_b, out, TOK, DM, DI);
}

// round 13
// speedup vs baseline: 1.2804x; 1.0124x over previous
#include <cuda_runtime.h>
#include <cuda_bf16.h>
#include <math.h>
#include <stdint.h>

#define BATCH 2
#define SEQ   4096
#define DM    2048
#define DI    4096
#define NH    32
#define HD    128
#define DS    64
#define CONVD (DI + 2*DS)          /* 4224 */
#define DIP   (2*DI + 2*DS + NH)   /* 8352 */
#define OFF_DT (DI + CONVD)        /* 8320 */
#define CHUNK 256
#define NC    (SEQ/CHUNK)          /* 16 */
#define TOK   (BATCH*SEQ)          /* 8192 */

// ---------------- scratch (device globals; no allocation allowed) ----------------
__device__ float g_zxbcdt[(size_t)TOK*DIP];
__device__ float g_dtsp[TOK*NH];
__device__ float g_dacs[BATCH*NH*NC*CHUNK];
__device__ float g_csum[BATCH*NH*NC];
__device__ float g_X[(size_t)BATCH*NC*NH*CHUNK*HD];
__device__ float g_Bm[BATCH*NC*CHUNK*DS];
__device__ float g_Cm[BATCH*NC*CHUNK*DS];
__device__ float g_G[BATCH*NC*CHUNK*CHUNK];
__device__ float g_states[(size_t)BATCH*NC*NH*HD*DS];
__device__ float g_inter[(size_t)BATCH*NC*NH*HD*DS];
__device__ float g_y[(size_t)TOK*DI];
// pre-split bf16 operands for the two big GEMMs
__device__ __nv_bfloat16 g_u_hi[(size_t)TOK*DM];
__device__ __nv_bfloat16 g_u_lo[(size_t)TOK*DM];
__device__ __nv_bfloat16 g_w1_hi[(size_t)DIP*DM];
__device__ __nv_bfloat16 g_w1_lo[(size_t)DIP*DM];
__device__ __nv_bfloat16 g_w2_hi[(size_t)DM*DI];
__device__ __nv_bfloat16 g_w2_lo[(size_t)DM*DI];
__device__ __nv_bfloat16 g_yn_hi[(size_t)TOK*DI];
__device__ __nv_bfloat16 g_yn_lo[(size_t)TOK*DI];

// ================= helpers =================
__device__ __forceinline__ uint32_t smem_u32(const void* p) {
    uint32_t a;
    asm("{ .reg .u64 t; cvta.to.shared.u64 t, %1; cvt.u32.u64 %0, t; }" : "=r"(a) : "l"(p));
    return a;
}
// split x0,x1 -> hi bf16x2 (rn) and lo bf16x2 (residual)
__device__ __forceinline__ void split2(float x0, float x1, uint32_t& hi, uint32_t& lo) {
    uint32_t h;
    asm("cvt.rn.bf16x2.f32 %0, %1, %2;" : "=r"(h) : "f"(x1), "f"(x0));
    float h0 = __uint_as_float(h << 16);
    float h1 = __uint_as_float(h & 0xFFFF0000u);
    float l0 = x0 - h0, l1 = x1 - h1;
    asm("cvt.rn.bf16x2.f32 %0, %1, %2;" : "=r"(lo) : "f"(l1), "f"(l0));
    hi = h;
}
#define LDMX4(r0, r1, r2, r3, addr) \
    asm volatile("ldmatrix.sync.aligned.m8n8.x4.shared.b16 {%0,%1,%2,%3}, [%4];" \
                 : "=r"(r0), "=r"(r1), "=r"(r2), "=r"(r3) : "r"(addr))
#define LDMX4T(r0, r1, r2, r3, addr) \
    asm volatile("ldmatrix.sync.aligned.m8n8.x4.trans.shared.b16 {%0,%1,%2,%3}, [%4];" \
                 : "=r"(r0), "=r"(r1), "=r"(r2), "=r"(r3) : "r"(addr))
#define MMA16816(d, a, b0, b1) \
    asm volatile("mma.sync.aligned.m16n8k16.row.col.f32.bf16.bf16.f32 " \
                 "{%0,%1,%2,%3}, {%4,%5,%6,%7}, {%8,%9}, {%0,%1,%2,%3};" \
                 : "+f"(d[0]), "+f"(d[1]), "+f"(d[2]), "+f"(d[3]) \
                 : "r"(a[0]), "r"(a[1]), "r"(a[2]), "r"(a[3]), "r"(b0), "r"(b1))
#define CP16(dst, src, nbytes) \
    asm volatile("cp.async.ca.shared.global [%0], [%1], 16, %2;" \
                 :: "r"(dst), "l"(src), "r"(nbytes) : "memory")
#define CPCOMMIT() asm volatile("cp.async.commit_group;" ::: "memory")
#define CPWAIT1()  asm volatile("cp.async.wait_group 1;" ::: "memory")

// ---------------- K0: split pass f32 -> hi/lo bf16 ----------------
__global__ __launch_bounds__(256) void split_kernel(
    const float* __restrict__ src, __nv_bfloat16* __restrict__ hi,
    __nv_bfloat16* __restrict__ lo, int n4)
{
    int idx = blockIdx.x * 256 + threadIdx.x;
    if (idx >= n4) return;
    float4 v = ((const float4*)src)[idx];
    uint2 h, l;
    split2(v.x, v.y, h.x, l.x);
    split2(v.z, v.w, h.y, l.y);
    *(uint2*)&hi[(size_t)idx * 4] = h;
    *(uint2*)&lo[(size_t)idx * 4] = l;
}

// ---------------- K1/K9: cp.async double-buffered split-bf16 mma GEMM ----------------
#define BM 128
#define BN 128
#define BK 32
#define LDT 40                        /* padded bf16 row stride (80B) */
#define TARR (BM * LDT * 2)           /* one operand array: 10240 B */
#define STAGE (4 * TARR)              /* Ah,Al,Bh,Bl: 40960 B */
#define GEMM_SMEM (2 * STAGE)         /* 81920 B */

__global__ __launch_bounds__(256, 2) void gemm_mma(
    const __nv_bfloat16* __restrict__ Agh, const __nv_bfloat16* __restrict__ Agl,
    const __nv_bfloat16* __restrict__ Bgh, const __nv_bfloat16* __restrict__ Bgl,
    const float* __restrict__ bias, float* __restrict__ C,
    int M, int N, int K)
{
    extern __shared__ __align__(16) char gsm[];
    uint32_t sb = smem_u32(gsm);

    int tid = threadIdx.x;
    int warp = tid >> 5, lane = tid & 31;
    int wm = warp & 3, wn = warp >> 2;
    int m0 = blockIdx.y * BM, n0 = blockIdx.x * BN;

    float acc[2][8][4];
#pragma unroll
    for (int mi = 0; mi < 2; mi++)
#pragma unroll
        for (int ni = 0; ni < 8; ni++)
#pragma unroll
            for (int e = 0; e < 4; e++) acc[mi][ni][e] = 0.f;

    int r0 = tid >> 2;            // 0..63
    int c8 = (tid & 3) * 8;       // bf16 col: 0,8,16,24

    const size_t arow0 = (size_t)(m0 + r0) * K + c8;
    const size_t arow1 = (size_t)(m0 + r0 + 64) * K + c8;
    const bool ok0 = (n0 + r0) < N;
    const bool ok1 = (n0 + r0 + 64) < N;
    const size_t brow0 = (size_t)(ok0 ? n0 + r0 : 0) * K + c8;
    const size_t brow1 = (size_t)(ok1 ? n0 + r0 + 64 : 0) * K + c8;
    const int nb0 = ok0 ? 16 : 0;
    const int nb1 = ok1 ? 16 : 0;
    const uint32_t so0 = (uint32_t)(r0 * LDT + c8) * 2;
    const uint32_t so1 = (uint32_t)((r0 + 64) * LDT + c8) * 2;

    int lrow16 = lane & 15;
    int lkoff  = (lane >> 4) * 8;

    auto issue = [&](uint32_t st, int k0) {
        CP16(st + so0,            Agh + arow0 + k0, 16);
        CP16(st + so0 + TARR,     Agl + arow0 + k0, 16);
        CP16(st + so0 + 2 * TARR, Bgh + brow0 + k0, nb0);
        CP16(st + so0 + 3 * TARR, Bgl + brow0 + k0, nb0);
        CP16(st + so1,            Agh + arow1 + k0, 16);
        CP16(st + so1 + TARR,     Agl + arow1 + k0, 16);
        CP16(st + so1 + 2 * TARR, Bgh + brow1 + k0, nb1);
        CP16(st + so1 + 3 * TARR, Bgl + brow1 + k0, nb1);
    };

    const int ntiles = K >> 5;
    issue(sb, 0);          CPCOMMIT();
    issue(sb + STAGE, BK); CPCOMMIT();

    for (int t = 0; t < ntiles; t++) {
        CPWAIT1();
        __syncthreads();
        uint32_t buf = sb + (t & 1) * STAGE;
        uint32_t ah_b = buf, al_b = buf + TARR;
        uint32_t bh_b = buf + 2 * TARR, bl_b = buf + 3 * TARR;

#pragma unroll
        for (int ks = 0; ks < BK; ks += 16) {
            uint32_t ahf[2][4], alf[2][4];
#pragma unroll
            for (int mi = 0; mi < 2; mi++) {
                uint32_t off = (uint32_t)((wm * 32 + mi * 16 + lrow16) * LDT + ks + lkoff) * 2;
                LDMX4(ahf[mi][0], ahf[mi][1], ahf[mi][2], ahf[mi][3], ah_b + off);
                LDMX4(alf[mi][0], alf[mi][1], alf[mi][2], alf[mi][3], al_b + off);
            }
#pragma unroll
            for (int nt = 0; nt < 4; nt++) {
                uint32_t off = (uint32_t)((wn * 64 + nt * 16 + lrow16) * LDT + ks + lkoff) * 2;
                uint32_t h0, h1, h2, h3, l0, l1, l2, l3;
                LDMX4(h0, h1, h2, h3, bh_b + off);
                LDMX4(l0, l1, l2, l3, bl_b + off);
#pragma unroll
                for (int mi = 0; mi < 2; mi++) {
                    MMA16816(acc[mi][nt * 2 + 0], ahf[mi], h0, h2);
                    MMA16816(acc[mi][nt * 2 + 0], alf[mi], h0, h2);
                    MMA16816(acc[mi][nt * 2 + 0], ahf[mi], l0, l2);
                    MMA16816(acc[mi][nt * 2 + 1], ahf[mi], h1, h3);
                    MMA16816(acc[mi][nt * 2 + 1], alf[mi], h1, h3);
                    MMA16816(acc[mi][nt * 2 + 1], ahf[mi], l1, l3);
                }
            }
        }
        __syncthreads();
        if (t + 2 < ntiles) issue(buf, (t + 2) * BK);
        CPCOMMIT();
    }

    int rbase = m0 + wm * 32 + (lane >> 2);
    int cbase = n0 + wn * 64 + (lane & 3) * 2;
#pragma unroll
    for (int mi = 0; mi < 2; mi++) {
#pragma unroll
        for (int ni = 0; ni < 8; ni++) {
            int col = cbase + ni * 8;
            if (col < N) {
                float2 bb = *(const float2*)&bias[col];
                int r = rbase + mi * 16;
                float2 v0 = make_float2(acc[mi][ni][0] + bb.x, acc[mi][ni][1] + bb.y);
                *(float2*)&C[(size_t)r * N + col] = v0;
                float2 v1 = make_float2(acc[mi][ni][2] + bb.x, acc[mi][ni][3] + bb.y);
                *(float2*)&C[(size_t)(r + 8) * N + col] = v1;
            }
        }
    }
}

// ---------------- K2: dt softplus + per-chunk inclusive cumsum of A*dt ----------------
__global__ __launch_bounds__(256) void dt_scan_kernel(
    const float* __restrict__ dt_bias, const float* __restrict__ A_log)
{
    int blk = blockIdx.x;
    int c = blk % NC; int bh = blk / NC;
    int h = bh % NH;  int b = bh / NH;
    int t = threadIdx.x;
    int l = c * CHUNK + t;

    float x = g_zxbcdt[(size_t)(b * SEQ + l) * DIP + OFF_DT + h] + dt_bias[h];
    float sp = (x > 20.f) ? x : log1pf(expf(x));
    g_dtsp[(b * SEQ + l) * NH + h] = sp;
    float da = -expf(A_log[h]) * sp;

    __shared__ float s[CHUNK];
    s[t] = da;
    __syncthreads();
    for (int off = 1; off < CHUNK; off <<= 1) {
        float v = (t >= off) ? s[t - off] : 0.f;
        __syncthreads();
        s[t] += v;
        __syncthreads();
    }
    int base = ((b * NH + h) * NC + c) * CHUNK;
    g_dacs[base + t] = s[t];
    if (t == CHUNK - 1) g_csum[(b * NH + h) * NC + c] = s[t];
}

// ---------------- K3: causal depthwise conv4 + SiLU + scatter (8 tokens/thread) ----------------
__global__ __launch_bounds__(256) void conv_kernel(
    const float* __restrict__ conv_w, const float* __restrict__ conv_b)
{
    int ch = blockIdx.y * 256 + threadIdx.x;
    if (ch >= CONVD) return;
    int tok0 = blockIdx.x * 8;             // 8 tokens per thread, same batch (SEQ%8==0)
    int b = tok0 / SEQ, l0 = tok0 % SEQ;

    const float* w = conv_w + ch * 4;
    float w0 = w[0], w1 = w[1], w2 = w[2], w3 = w[3];
    float bb = conv_b[ch];

    // load 11 covering rows once
    float xv[11];
#pragma unroll
    for (int r = 0; r < 11; r++) {
        int ls = l0 - 3 + r;
        xv[r] = (ls >= 0) ? g_zxbcdt[(size_t)(b * SEQ + ls) * DIP + DI + ch] : 0.f;
    }

#pragma unroll
    for (int j = 0; j < 8; j++) {
        float acc = bb + w0 * xv[j] + w1 * xv[j + 1] + w2 * xv[j + 2] + w3 * xv[j + 3];
        float v = acc / (1.f + __expf(-acc));   // silu
        int l = l0 + j;
        int c = l / CHUNK, t = l % CHUNK;
        if (ch < DI) {
            int h = ch >> 7, p = ch & 127;
            float dt = g_dtsp[(b * SEQ + l) * NH + h];
            g_X[(size_t)(((b * NC + c) * NH + h) * CHUNK + t) * HD + p] = v * dt;
        } else if (ch < DI + DS) {
            g_Bm[((b * NC + c) * CHUNK + t) * DS + (ch - DI)] = v;
        } else {
            g_Cm[((b * NC + c) * CHUNK + t) * DS + (ch - DI - DS)] = v;
        }
    }
}

// ---------------- K4: G[l,s] = sum_n C[l,n] B[s,n] per (b,c) ----------------
__global__ __launch_bounds__(256) void bc_gemm_kernel()
{
    int bc = blockIdx.y;
    int tile = blockIdx.x;
    int l0 = (tile >> 2) * 64, s0 = (tile & 3) * 64;
    __shared__ float Cs[64][65];
    __shared__ float Bs[64][65];
    int tid = threadIdx.x;
    const float* Cb = g_Cm + (size_t)bc * CHUNK * DS;
    const float* Bb = g_Bm + (size_t)bc * CHUNK * DS;

#pragma unroll
    for (int u = 0; u < 4; u++) {
        int e = tid + u * 256;
        int r = e >> 4, cv = (e & 15) << 2;
        float4 vc = *(const float4*)&Cb[(l0 + r) * DS + cv];
        Cs[r][cv + 0] = vc.x; Cs[r][cv + 1] = vc.y; Cs[r][cv + 2] = vc.z; Cs[r][cv + 3] = vc.w;
        float4 vb = *(const float4*)&Bb[(s0 + r) * DS + cv];
        Bs[r][cv + 0] = vb.x; Bs[r][cv + 1] = vb.y; Bs[r][cv + 2] = vb.z; Bs[r][cv + 3] = vb.w;
    }
    __syncthreads();

    int sq = tid & 15, lq = tid >> 4;
    float acc[4][4];
#pragma unroll
    for (int i = 0; i < 4; i++)
#pragma unroll
        for (int j = 0; j < 4; j++) acc[i][j] = 0.f;

#pragma unroll 8
    for (int n = 0; n < 64; n++) {
        float a[4], bb[4];
#pragma unroll
        for (int i = 0; i < 4; i++) a[i] = Cs[lq * 4 + i][n];
#pragma unroll
        for (int j = 0; j < 4; j++) bb[j] = Bs[sq * 4 + j][n];
#pragma unroll
        for (int i = 0; i < 4; i++)
#pragma unroll
            for (int j = 0; j < 4; j++) acc[i][j] = fmaf(a[i], bb[j], acc[i][j]);
    }
    float* Gout = g_G + (size_t)bc * CHUNK * CHUNK;
#pragma unroll
    for (int i = 0; i < 4; i++) {
        float4 v = make_float4(acc[i][0], acc[i][1], acc[i][2], acc[i][3]);
        *(float4*)&Gout[(l0 + lq * 4 + i) * CHUNK + s0 + sq * 4] = v;
    }
}

// ---------------- K5: Y_diag = (G .* L) @ X per (b,c,h), split-bf16 mma ----------------
#define YLDT 40
#define XLDT 136
#define YSMEM (2*256*YLDT*2 + 2*32*XLDT*2 + 256*4 + 256*4)   /* 60416 */

__global__ __launch_bounds__(512, 1) void ydiag_kernel()
{
    extern __shared__ __align__(16) char ysm[];
    __nv_bfloat16* Msh = (__nv_bfloat16*)ysm;
    __nv_bfloat16* Msl = Msh + 256 * YLDT;
    __nv_bfloat16* Xsh = Msl + 256 * YLDT;
    __nv_bfloat16* Xsl = Xsh + 32 * XLDT;
    float* acs   = (float*)(Xsl + 32 * XLDT);
    float* cfall = acs + 256;

    uint32_t msh_b = smem_u32(Msh), msl_b = smem_u32(Msl);
    uint32_t xsh_b = smem_u32(Xsh), xsl_b = smem_u32(Xsl);

    int blk = blockIdx.x;
    int h = blk % NH; int bc = blk / NH;
    int c = bc % NC;  int b = bc / NC;
    int tid = threadIdx.x;
    int warp = tid >> 5, lane = tid & 31;
    int wm = warp & 7, wn = warp >> 3;

    if (tid < 256) acs[tid] = g_dacs[((b * NH + h) * NC + c) * CHUNK + tid];
    __syncthreads();
    if (tid < 256) cfall[tid] = __expf(acs[tid & ~31] - acs[tid]);
    __syncthreads();

    const float* Gb = g_G + (size_t)bc * CHUNK * CHUNK;
    const float* Xb = g_X + (size_t)blk * CHUNK * HD;

    float acc[2][8][4];
#pragma unroll
    for (int mi = 0; mi < 2; mi++)
#pragma unroll
        for (int ni = 0; ni < 8; ni++)
#pragma unroll
            for (int e = 0; e < 4; e++) acc[mi][ni][e] = 0.f;

    int lrow16 = lane & 15, lkoff = (lane >> 4) * 8;
    int bl = tid >> 1, bs = (tid & 1) * 16;
    int i8 = lane & 7, sel = lane >> 3;

    for (int s0 = 0; s0 < CHUNK; s0 += 32) {
        if (s0) __syncthreads();

#pragma unroll
        for (int u = 0; u < 2; u++) {
            int e = tid + u * 512;
            int s = e >> 5, p4 = e & 31;
            float4 v = *(const float4*)&Xb[(s0 + s) * HD + p4 * 4];
            uint32_t h0, l0, h1, l1;
            split2(v.x, v.y, h0, l0);
            split2(v.z, v.w, h1, l1);
            uint32_t off = (uint32_t)(s * XLDT + p4 * 4) * 2;
            asm volatile("st.shared.v2.b32 [%0], {%1,%2};" :: "r"(xsh_b + off), "r"(h0), "r"(h1) : "memory");
            asm volatile("st.shared.v2.b32 [%0], {%1,%2};" :: "r"(xsl_b + off), "r"(l0), "r"(l1) : "memory");
        }

        if (bl >= s0 - 32) {
            float rowfac = __expf(acs[bl] - acs[s0]);
#pragma unroll
            for (int j4 = 0; j4 < 4; j4++) {
                int sg = s0 + bs + j4 * 4;
                float4 g4 = *(const float4*)&Gb[bl * CHUNK + sg];
                float m0 = (sg + 0 <= bl) ? g4.x * rowfac * cfall[sg + 0] : 0.f;
                float m1 = (sg + 1 <= bl) ? g4.y * rowfac * cfall[sg + 1] : 0.f;
                float m2 = (sg + 2 <= bl) ? g4.z * rowfac * cfall[sg + 2] : 0.f;
                float m3 = (sg + 3 <= bl) ? g4.w * rowfac * cfall[sg + 3] : 0.f;
                uint32_t h01, l01, h23, l23;
                split2(m0, m1, h01, l01);
                split2(m2, m3, h23, l23);
                uint32_t off = (uint32_t)(bl * YLDT + bs + j4 * 4) * 2;
                asm volatile("st.shared.v2.b32 [%0], {%1,%2};" :: "r"(msh_b + off), "r"(h01), "r"(h23) : "memory");
                asm volatile("st.shared.v2.b32 [%0], {%1,%2};" :: "r"(msl_b + off), "r"(l01), "r"(l23) : "memory");
            }
        }
        __syncthreads();

        if (wm * 32 + 31 >= s0) {
#pragma unroll
            for (int ks = 0; ks < 32; ks += 16) {
                uint32_t ahf[2][4], alf[2][4];
#pragma unroll
                for (int mi = 0; mi < 2; mi++) {
                    uint32_t off = (uint32_t)((wm * 32 + mi * 16 + lrow16) * YLDT + ks + lkoff) * 2;
                    LDMX4(ahf[mi][0], ahf[mi][1], ahf[mi][2], ahf[mi][3], msh_b + off);
                    LDMX4(alf[mi][0], alf[mi][1], alf[mi][2], alf[mi][3], msl_b + off);
                }
#pragma unroll
                for (int nt = 0; nt < 4; nt++) {
                    uint32_t xoff = (uint32_t)((ks + (sel >> 1) * 8 + i8) * XLDT
                                               + wn * 64 + nt * 16 + (sel & 1) * 8) * 2;
                    uint32_t h0, h1, h2, h3, l0, l1, l2, l3;
                    LDMX4T(h0, h1, h2, h3, xsh_b + xoff);
                    LDMX4T(l0, l1, l2, l3, xsl_b + xoff);
#pragma unroll
                    for (int mi = 0; mi < 2; mi++) {
                        MMA16816(acc[mi][nt * 2 + 0], ahf[mi], h0, h2);
                        MMA16816(acc[mi][nt * 2 + 0], alf[mi], h0, h2);
                        MMA16816(acc[mi][nt * 2 + 0], ahf[mi], l0, l2);
                        MMA16816(acc[mi][nt * 2 + 1], ahf[mi], h1, h3);
                        MMA16816(acc[mi][nt * 2 + 1], alf[mi], h1, h3);
                        MMA16816(acc[mi][nt * 2 + 1], ahf[mi], l1, l3);
                    }
                }
            }
        }
    }

    int rbase = wm * 32 + (lane >> 2);
    int cbase = wn * 64 + (lane & 3) * 2;
#pragma unroll
    for (int mi = 0; mi < 2; mi++) {
#pragma unroll
        for (int ni = 0; ni < 8; ni++) {
            int l0r = rbase + mi * 16;
            int col = cbase + ni * 8;
            float* out0 = g_y + (size_t)(b * SEQ + c * CHUNK + l0r) * DI + h * HD + col;
            *(float2*)out0 = make_float2(acc[mi][ni][0], acc[mi][ni][1]);
            float* out1 = g_y + (size_t)(b * SEQ + c * CHUNK + l0r + 8) * DI + h * HD + col;
            *(float2*)out1 = make_float2(acc[mi][ni][2], acc[mi][ni][3]);
        }
    }
}

// ---------------- K5b: local states[p,n] = sum_l X[l,p]*decay[l]*B[l,n] ----------------
__global__ __launch_bounds__(256) void states_kernel()
{
    int blk = blockIdx.x;
    int h = blk % NH; int bc = blk / NH;
    int c = bc % NC;  int b = bc / NC;

    __shared__ __align__(16) float Xs[32][128];
    __shared__ __align__(16) float Bs[32][64];
    __shared__ float ws[32];
    __shared__ float acs[CHUNK];
    int tid = threadIdx.x;
    if (tid < 256) acs[tid] = g_dacs[((b * NH + h) * NC + c) * CHUNK + tid];
    __syncthreads();
    float alast = acs[CHUNK - 1];

    const float* Xb = g_X + (size_t)blk * CHUNK * HD;
    const float* Bb = g_Bm + (size_t)bc * CHUNK * DS;

    int nq = tid & 7, pq = tid >> 3;
    float acc[4][8];
#pragma unroll
    for (int i = 0; i < 4; i++)
#pragma unroll
        for (int j = 0; j < 8; j++) acc[i][j] = 0.f;

    for (int l0 = 0; l0 < CHUNK; l0 += 32) {
#pragma unroll
        for (int u = 0; u < 4; u++) {
            int e = tid + u * 256;
            int r = e >> 5, cv = (e & 31) << 2;
            *(float4*)&Xs[r][cv] = *(const float4*)&Xb[(l0 + r) * HD + cv];
        }
#pragma unroll
        for (int u = 0; u < 2; u++) {
            int e = tid + u * 256;
            int r = e >> 4, cv = (e & 15) << 2;
            *(float4*)&Bs[r][cv] = *(const float4*)&Bb[(l0 + r) * DS + cv];
        }
        if (tid < 32) ws[tid] = __expf(alast - acs[l0 + tid]);
        __syncthreads();
#pragma unroll
        for (int lt = 0; lt < 32; lt++) {
            float w = ws[lt];
            float a[4];
#pragma unroll
            for (int i = 0; i < 4; i++) a[i] = Xs[lt][pq * 4 + i] * w;
            float bb[8];
#pragma unroll
            for (int j = 0; j < 8; j++) bb[j] = Bs[lt][nq * 8 + j];
#pragma unroll
            for (int i = 0; i < 4; i++)
#pragma unroll
                for (int j = 0; j < 8; j++)
                    acc[i][j] = fmaf(a[i], bb[j], acc[i][j]);
        }
        __syncthreads();
    }
    float* So = g_states + (size_t)blk * HD * DS;
#pragma unroll
    for (int i = 0; i < 4; i++) {
#pragma unroll
        for (int j = 0; j < 8; j += 4) {
            float4 v = make_float4(acc[i][j], acc[i][j + 1], acc[i][j + 2], acc[i][j + 3]);
            *(float4*)&So[(pq * 4 + i) * DS + nq * 8 + j] = v;
        }
    }
}

// ---------------- K6: inter-chunk scan (8-way split, float4) ----------------
__global__ __launch_bounds__(256) void scan_kernel()
{
    int blk = blockIdx.x;                 // (b*NH + h)*8 + part
    int part = blk & 7;
    int bh = blk >> 3;
    int b = bh / NH, h = bh % NH;
    int e0 = part * 1024 + threadIdx.x * 4;

    float4 S = make_float4(0.f, 0.f, 0.f, 0.f);
    for (int c = 0; c < NC; c++) {
        float dec = __expf(g_csum[bh * NC + c]);
        size_t base = (size_t)((b * NC + c) * NH + h) * HD * DS + e0;
        *(float4*)&g_inter[base] = S;
        float4 v = *(const float4*)&g_states[base];
        S.x = S.x * dec + v.x;
        S.y = S.y * dec + v.y;
        S.z = S.z * dec + v.z;
        S.w = S.w * dec + v.w;
    }
}

// ---------------- K7: Y_off + combine + silu(z) gate ----------------
__global__ __launch_bounds__(256) void yoff_kernel()
{
    int blk = blockIdx.x;
    int h = blk % NH; int bc = blk / NH;
    int c = bc % NC;  int b = bc / NC;

    __shared__ float Is[HD][DS + 1];
    __shared__ float Cs[64][DS + 1];
    __shared__ float acs[CHUNK];
    int tid = threadIdx.x;
    if (tid < 256) acs[tid] = g_dacs[((b * NH + h) * NC + c) * CHUNK + tid];

    const float* Ib = g_inter + (size_t)blk * HD * DS;
#pragma unroll
    for (int u = 0; u < 8; u++) {
        int e = tid + u * 256;
        int r = e >> 4, cv = (e & 15) << 2;
        float4 v = *(const float4*)&Ib[r * DS + cv];
        Is[r][cv + 0] = v.x; Is[r][cv + 1] = v.y; Is[r][cv + 2] = v.z; Is[r][cv + 3] = v.w;
    }

    int tq = tid & 7, pq = tid >> 3;
    const float* Cb = g_Cm + (size_t)bc * CHUNK * DS;

    for (int tg = 0; tg < 4; tg++) {
        __syncthreads();
#pragma unroll
        for (int u = 0; u < 4; u++) {
            int e = tid + u * 256;
            int r = e >> 4, cv = (e & 15) << 2;
            float4 v = *(const float4*)&Cb[(tg * 64 + r) * DS + cv];
            Cs[r][cv + 0] = v.x; Cs[r][cv + 1] = v.y; Cs[r][cv + 2] = v.z; Cs[r][cv + 3] = v.w;
        }
        __syncthreads();

        float acc[8][4];
#pragma unroll
        for (int k = 0; k < 8; k++)
#pragma unroll
            for (int i = 0; i < 4; i++) acc[k][i] = 0.f;

#pragma unroll 4
        for (int n = 0; n < DS; n++) {
            float iv[4];
#pragma unroll
            for (int i = 0; i < 4; i++) iv[i] = Is[pq * 4 + i][n];
#pragma unroll
            for (int k = 0; k < 8; k++) {
                float cv = Cs[k * 8 + tq][n];
#pragma unroll
                for (int i = 0; i < 4; i++)
                    acc[k][i] = fmaf(cv, iv[i], acc[k][i]);
            }
        }

#pragma unroll
        for (int k = 0; k < 8; k++) {
            int t = tg * 64 + k * 8 + tq;
            float ea = __expf(acs[t]);
            int gl = c * CHUNK + t;
            size_t yidx = (size_t)(b * SEQ + gl) * DI + h * HD + pq * 4;
            size_t zidx = (size_t)(b * SEQ + gl) * DIP + h * HD + pq * 4;
            float4 yd = *(float4*)&g_y[yidx];
            float4 z  = *(const float4*)&g_zxbcdt[zidx];
            float4 o;
            o.x = (yd.x + ea * acc[k][0]) * z.x / (1.f + __expf(-z.x));
            o.y = (yd.y + ea * acc[k][1]) * z.y / (1.f + __expf(-z.y));
            o.z = (yd.z + ea * acc[k][2]) * z.z / (1.f + __expf(-z.z));
            o.w = (yd.w + ea * acc[k][3]) * z.w / (1.f + __expf(-z.w));
            *(float4*)&g_y[yidx] = o;
        }
    }
}

// ---------------- K8: layernorm over 4096, emits split bf16 hi/lo ----------------
__global__ __launch_bounds__(256) void ln_kernel(
    const float* __restrict__ ln_w, const float* __restrict__ ln_b)
{
    int tok = blockIdx.x;
    const float* y = g_y + (size_t)tok * DI;
    __nv_bfloat16* ohi = g_yn_hi + (size_t)tok * DI;
    __nv_bfloat16* olo = g_yn_lo + (size_t)tok * DI;
    int tid = threadIdx.x;

    float v[16];
    float s = 0.f, ss = 0.f;
#pragma unroll
    for (int u = 0; u < 4; u++) {
        float4 x = *(const float4*)&y[tid * 4 + u * 1024];
        v[u * 4 + 0] = x.x; v[u * 4 + 1] = x.y; v[u * 4 + 2] = x.z; v[u * 4 + 3] = x.w;
        s += x.x + x.y + x.z + x.w;
        ss += x.x * x.x + x.y * x.y + x.z * x.z + x.w * x.w;
    }
#pragma unroll
    for (int off = 16; off; off >>= 1) {
        s  += __shfl_xor_sync(0xFFFFFFFFu, s, off);
        ss += __shfl_xor_sync(0xFFFFFFFFu, ss, off);
    }
    __shared__ float rs[8], rss[8];
    int warp = tid >> 5, lane = tid & 31;
    if (lane == 0) { rs[warp] = s; rss[warp] = ss; }
    __syncthreads();
    s = 0.f; ss = 0.f;
#pragma unroll
    for (int w = 0; w < 8; w++) { s += rs[w]; ss += rss[w]; }
    float mu = s * (1.f / DI);
    float var = ss * (1.f / DI) - mu * mu;
    float rstd = rsqrtf(var + 1e-5f);
#pragma unroll
    for (int u = 0; u < 4; u++) {
        int idx = tid * 4 + u * 1024;
        float4 w4 = *(const float4*)&ln_w[idx];
        float4 b4 = *(const float4*)&ln_b[idx];
        float o0 = (v[u * 4 + 0] - mu) * rstd * w4.x + b4.x;
        float o1 = (v[u * 4 + 1] - mu) * rstd * w4.y + b4.y;
        float o2 = (v[u * 4 + 2] - mu) * rstd * w4.z + b4.z;
        float o3 = (v[u * 4 + 3] - mu) * rstd * w4.w + b4.w;
        uint2 hh, ll;
        split2(o0, o1, hh.x, ll.x);
        split2(o2, o3, hh.y, ll.y);
        *(uint2*)&ohi[idx] = hh;
        *(uint2*)&olo[idx] = ll;
    }
}

// ---------------- launch ----------------
extern "C" void kernel_launch(void* const* d_in, const int* in_sizes, int n_in,
                              void* d_out, int out_size)
{
    const float* u          = (const float*)d_in[0];
    const float* in_proj_w  = (const float*)d_in[1];
    const float* in_proj_b  = (const float*)d_in[2];
    const float* conv_w     = (const float*)d_in[3];
    const float* conv_b     = (const float*)d_in[4];
    const float* dt_bias    = (const float*)d_in[5];
    const float* A_log      = (const float*)d_in[6];
    const float* ln_w       = (const float*)d_in[7];
    const float* ln_b       = (const float*)d_in[8];
    const float* out_proj_w = (const float*)d_in[9];
    const float* out_proj_b = (const float*)d_in[10];
    float* out = (float*)d_out;

    float* zx; cudaGetSymbolAddress((void**)&zx, g_zxbcdt);
    __nv_bfloat16 *uh, *ul, *w1h, *w1l, *w2h, *w2l, *ynh, *ynl;
    cudaGetSymbolAddress((void**)&uh,  g_u_hi);
    cudaGetSymbolAddress((void**)&ul,  g_u_lo);
    cudaGetSymbolAddress((void**)&w1h, g_w1_hi);
    cudaGetSymbolAddress((void**)&w1l, g_w1_lo);
    cudaGetSymbolAddress((void**)&w2h, g_w2_hi);
    cudaGetSymbolAddress((void**)&w2l, g_w2_lo);
    cudaGetSymbolAddress((void**)&ynh, g_yn_hi);
    cudaGetSymbolAddress((void**)&ynl, g_yn_lo);

    cudaFuncSetAttribute(gemm_mma, cudaFuncAttributeMaxDynamicSharedMemorySize, GEMM_SMEM);
    cudaFuncSetAttribute(ydiag_kernel, cudaFuncAttributeMaxDynamicSharedMemorySize, YSMEM);

    // K0: pre-split u / weights into bf16 hi/lo
    split_kernel<<<(TOK * DM / 4 + 255) / 256, 256>>>(u, uh, ul, TOK * DM / 4);
    split_kernel<<<(DIP * DM / 4 + 255) / 256, 256>>>(in_proj_w, w1h, w1l, DIP * DM / 4);
    split_kernel<<<(DM * DI / 4 + 255) / 256, 256>>>(out_proj_w, w2h, w2l, DM * DI / 4);

    // K1: in_proj GEMM (8192 x 8352 x 2048)
    gemm_mma<<<dim3((DIP + BN - 1) / BN, TOK / BM), 256, GEMM_SMEM>>>(
        uh, ul, w1h, w1l, in_proj_b, zx, TOK, DIP, DM);
    // K2: dt softplus + per-chunk cumsum
    dt_scan_kernel<<<BATCH * NH * NC, CHUNK>>>(dt_bias, A_log);
    // K3: conv + silu + scatter (8 tokens/thread)
    conv_kernel<<<dim3(TOK / 8, (CONVD + 255) / 256), 256>>>(conv_w, conv_b);
    // K4: G = C B^T per (b,c)
    bc_gemm_kernel<<<dim3(16, BATCH * NC), 256>>>();
    // K5: Y_diag (split-bf16 mma)
    ydiag_kernel<<<BATCH * NC * NH, 512, YSMEM>>>();
    // K5b: local chunk states
    states_kernel<<<BATCH * NC * NH, 256>>>();
    // K6: inter-chunk scan (8-way split)
    scan_kernel<<<BATCH * NH * 8, 256>>>();
    // K7: Y_off + gate
    yoff_kernel<<<BATCH * NC * NH, 256>>>();
    // K8: layernorm (emits bf16 hi/lo)
    ln_kernel<<<TOK, 256>>>(ln_w, ln_b);
    // K9: out_proj GEMM (8192 x 2048 x 4096)
    gemm_mma<<<dim3(DM / BN, TOK / BM), 256, GEMM_SMEM>>>(
        ynh, ynl, w2h, w2l, out_proj_b, out, TOK, DM, DI);
}

// round 16
// speedup vs baseline: 1.3141x; 1.0263x over previous
#include <cuda_runtime.h>
#include <cuda_bf16.h>
#include <math.h>
#include <stdint.h>

#define BATCH 2
#define SEQ   4096
#define DM    2048
#define DI    4096
#define NH    32
#define HD    128
#define DS    64
#define CONVD (DI + 2*DS)          /* 4224 */
#define DIP   (2*DI + 2*DS + NH)   /* 8352 */
#define OFF_DT (DI + CONVD)        /* 8320 */
#define CHUNK 256
#define NC    (SEQ/CHUNK)          /* 16 */
#define TOK   (BATCH*SEQ)          /* 8192 */

// ---------------- scratch (device globals; no allocation allowed) ----------------
__device__ float g_zxbcdt[(size_t)TOK*DIP];
__device__ float g_dtsp[TOK*NH];
__device__ float g_dacs[BATCH*NH*NC*CHUNK];
__device__ float g_csum[BATCH*NH*NC];
__device__ float g_X[(size_t)BATCH*NC*NH*CHUNK*HD];
__device__ float g_Bm[BATCH*NC*CHUNK*DS];
__device__ float g_Cm[BATCH*NC*CHUNK*DS];
__device__ float g_G[BATCH*NC*CHUNK*CHUNK];
__device__ float g_states[(size_t)BATCH*NC*NH*HD*DS];
__device__ float g_inter[(size_t)BATCH*NC*NH*HD*DS];
__device__ float g_y[(size_t)TOK*DI];
// pre-split bf16 operands for the two big GEMMs
__device__ __nv_bfloat16 g_u_hi[(size_t)TOK*DM];
__device__ __nv_bfloat16 g_u_lo[(size_t)TOK*DM];
__device__ __nv_bfloat16 g_w1_hi[(size_t)DIP*DM];
__device__ __nv_bfloat16 g_w1_lo[(size_t)DIP*DM];
__device__ __nv_bfloat16 g_w2_hi[(size_t)DM*DI];
__device__ __nv_bfloat16 g_w2_lo[(size_t)DM*DI];
__device__ __nv_bfloat16 g_yn_hi[(size_t)TOK*DI];
__device__ __nv_bfloat16 g_yn_lo[(size_t)TOK*DI];

// ================= helpers =================
__device__ __forceinline__ uint32_t smem_u32(const void* p) {
    uint32_t a;
    asm("{ .reg .u64 t; cvta.to.shared.u64 t, %1; cvt.u32.u64 %0, t; }" : "=r"(a) : "l"(p));
    return a;
}
// split x0,x1 -> hi bf16x2 (rn) and lo bf16x2 (residual)
__device__ __forceinline__ void split2(float x0, float x1, uint32_t& hi, uint32_t& lo) {
    uint32_t h;
    asm("cvt.rn.bf16x2.f32 %0, %1, %2;" : "=r"(h) : "f"(x1), "f"(x0));
    float h0 = __uint_as_float(h << 16);
    float h1 = __uint_as_float(h & 0xFFFF0000u);
    float l0 = x0 - h0, l1 = x1 - h1;
    asm("cvt.rn.bf16x2.f32 %0, %1, %2;" : "=r"(lo) : "f"(l1), "f"(l0));
    hi = h;
}
#define LDMX4(r0, r1, r2, r3, addr) \
    asm volatile("ldmatrix.sync.aligned.m8n8.x4.shared.b16 {%0,%1,%2,%3}, [%4];" \
                 : "=r"(r0), "=r"(r1), "=r"(r2), "=r"(r3) : "r"(addr))
#define LDMX4T(r0, r1, r2, r3, addr) \
    asm volatile("ldmatrix.sync.aligned.m8n8.x4.trans.shared.b16 {%0,%1,%2,%3}, [%4];" \
                 : "=r"(r0), "=r"(r1), "=r"(r2), "=r"(r3) : "r"(addr))
#define MMA16816(d, a, b0, b1) \
    asm volatile("mma.sync.aligned.m16n8k16.row.col.f32.bf16.bf16.f32 " \
                 "{%0,%1,%2,%3}, {%4,%5,%6,%7}, {%8,%9}, {%0,%1,%2,%3};" \
                 : "+f"(d[0]), "+f"(d[1]), "+f"(d[2]), "+f"(d[3]) \
                 : "r"(a[0]), "r"(a[1]), "r"(a[2]), "r"(a[3]), "r"(b0), "r"(b1))
#define CP16(dst, src, nbytes) \
    asm volatile("cp.async.ca.shared.global [%0], [%1], 16, %2;" \
                 :: "r"(dst), "l"(src), "r"(nbytes) : "memory")
#define CPCOMMIT() asm volatile("cp.async.commit_group;" ::: "memory")
#define CPWAIT1()  asm volatile("cp.async.wait_group 1;" ::: "memory")

// ---------------- K0: split pass f32 -> hi/lo bf16 ----------------
__global__ __launch_bounds__(256) void split_kernel(
    const float* __restrict__ src, __nv_bfloat16* __restrict__ hi,
    __nv_bfloat16* __restrict__ lo, int n4)
{
    int idx = blockIdx.x * 256 + threadIdx.x;
    if (idx >= n4) return;
    float4 v = ((const float4*)src)[idx];
    uint2 h, l;
    split2(v.x, v.y, h.x, l.x);
    split2(v.z, v.w, h.y, l.y);
    *(uint2*)&hi[(size_t)idx * 4] = h;
    *(uint2*)&lo[(size_t)idx * 4] = l;
}

// ---------------- K1/K9: cp.async double-buffered split-bf16 mma GEMM ----------------
#define BM 128
#define BN 128
#define BK 32
#define LDT 40                        /* padded bf16 row stride (80B) */
#define TARR (BM * LDT * 2)           /* one operand array: 10240 B */
#define STAGE (4 * TARR)              /* Ah,Al,Bh,Bl: 40960 B */
#define GEMM_SMEM (2 * STAGE)         /* 81920 B */

__global__ __launch_bounds__(256, 2) void gemm_mma(
    const __nv_bfloat16* __restrict__ Agh, const __nv_bfloat16* __restrict__ Agl,
    const __nv_bfloat16* __restrict__ Bgh, const __nv_bfloat16* __restrict__ Bgl,
    const float* __restrict__ bias, float* __restrict__ C,
    int M, int N, int K)
{
    extern __shared__ __align__(16) char gsm[];
    uint32_t sb = smem_u32(gsm);

    int tid = threadIdx.x;
    int warp = tid >> 5, lane = tid & 31;
    int wm = warp & 3, wn = warp >> 2;
    int m0 = blockIdx.y * BM, n0 = blockIdx.x * BN;

    float acc[2][8][4];
#pragma unroll
    for (int mi = 0; mi < 2; mi++)
#pragma unroll
        for (int ni = 0; ni < 8; ni++)
#pragma unroll
            for (int e = 0; e < 4; e++) acc[mi][ni][e] = 0.f;

    int r0 = tid >> 2;            // 0..63
    int c8 = (tid & 3) * 8;       // bf16 col: 0,8,16,24

    const size_t arow0 = (size_t)(m0 + r0) * K + c8;
    const size_t arow1 = (size_t)(m0 + r0 + 64) * K + c8;
    const bool ok0 = (n0 + r0) < N;
    const bool ok1 = (n0 + r0 + 64) < N;
    const size_t brow0 = (size_t)(ok0 ? n0 + r0 : 0) * K + c8;
    const size_t brow1 = (size_t)(ok1 ? n0 + r0 + 64 : 0) * K + c8;
    const int nb0 = ok0 ? 16 : 0;
    const int nb1 = ok1 ? 16 : 0;
    const uint32_t so0 = (uint32_t)(r0 * LDT + c8) * 2;
    const uint32_t so1 = (uint32_t)((r0 + 64) * LDT + c8) * 2;

    int lrow16 = lane & 15;
    int lkoff  = (lane >> 4) * 8;

    auto issue = [&](uint32_t st, int k0) {
        CP16(st + so0,            Agh + arow0 + k0, 16);
        CP16(st + so0 + TARR,     Agl + arow0 + k0, 16);
        CP16(st + so0 + 2 * TARR, Bgh + brow0 + k0, nb0);
        CP16(st + so0 + 3 * TARR, Bgl + brow0 + k0, nb0);
        CP16(st + so1,            Agh + arow1 + k0, 16);
        CP16(st + so1 + TARR,     Agl + arow1 + k0, 16);
        CP16(st + so1 + 2 * TARR, Bgh + brow1 + k0, nb1);
        CP16(st + so1 + 3 * TARR, Bgl + brow1 + k0, nb1);
    };

    const int ntiles = K >> 5;
    issue(sb, 0);          CPCOMMIT();
    issue(sb + STAGE, BK); CPCOMMIT();

    for (int t = 0; t < ntiles; t++) {
        CPWAIT1();
        __syncthreads();
        uint32_t buf = sb + (t & 1) * STAGE;
        uint32_t ah_b = buf, al_b = buf + TARR;
        uint32_t bh_b = buf + 2 * TARR, bl_b = buf + 3 * TARR;

#pragma unroll
        for (int ks = 0; ks < BK; ks += 16) {
            uint32_t ahf[2][4], alf[2][4];
#pragma unroll
            for (int mi = 0; mi < 2; mi++) {
                uint32_t off = (uint32_t)((wm * 32 + mi * 16 + lrow16) * LDT + ks + lkoff) * 2;
                LDMX4(ahf[mi][0], ahf[mi][1], ahf[mi][2], ahf[mi][3], ah_b + off);
                LDMX4(alf[mi][0], alf[mi][1], alf[mi][2], alf[mi][3], al_b + off);
            }
#pragma unroll
            for (int nt = 0; nt < 4; nt++) {
                uint32_t off = (uint32_t)((wn * 64 + nt * 16 + lrow16) * LDT + ks + lkoff) * 2;
                uint32_t h0, h1, h2, h3, l0, l1, l2, l3;
                LDMX4(h0, h1, h2, h3, bh_b + off);
                LDMX4(l0, l1, l2, l3, bl_b + off);
#pragma unroll
                for (int mi = 0; mi < 2; mi++) {
                    MMA16816(acc[mi][nt * 2 + 0], ahf[mi], h0, h2);
                    MMA16816(acc[mi][nt * 2 + 0], alf[mi], h0, h2);
                    MMA16816(acc[mi][nt * 2 + 0], ahf[mi], l0, l2);
                    MMA16816(acc[mi][nt * 2 + 1], ahf[mi], h1, h3);
                    MMA16816(acc[mi][nt * 2 + 1], alf[mi], h1, h3);
                    MMA16816(acc[mi][nt * 2 + 1], ahf[mi], l1, l3);
                }
            }
        }
        __syncthreads();
        if (t + 2 < ntiles) issue(buf, (t + 2) * BK);
        CPCOMMIT();
    }

    int rbase = m0 + wm * 32 + (lane >> 2);
    int cbase = n0 + wn * 64 + (lane & 3) * 2;
#pragma unroll
    for (int mi = 0; mi < 2; mi++) {
#pragma unroll
        for (int ni = 0; ni < 8; ni++) {
            int col = cbase + ni * 8;
            if (col < N) {
                float2 bb = *(const float2*)&bias[col];
                int r = rbase + mi * 16;
                float2 v0 = make_float2(acc[mi][ni][0] + bb.x, acc[mi][ni][1] + bb.y);
                *(float2*)&C[(size_t)r * N + col] = v0;
                float2 v1 = make_float2(acc[mi][ni][2] + bb.x, acc[mi][ni][3] + bb.y);
                *(float2*)&C[(size_t)(r + 8) * N + col] = v1;
            }
        }
    }
}

// ---------------- K2: dt softplus + per-chunk inclusive cumsum (warp scan) ----------------
__global__ __launch_bounds__(256) void dt_scan_kernel(
    const float* __restrict__ dt_bias, const float* __restrict__ A_log)
{
    int blk = blockIdx.x;
    int c = blk % NC; int bh = blk / NC;
    int h = bh % NH;  int b = bh / NH;
    int t = threadIdx.x;
    int l = c * CHUNK + t;
    int warp = t >> 5, lane = t & 31;

    float x = g_zxbcdt[(size_t)(b * SEQ + l) * DIP + OFF_DT + h] + dt_bias[h];
    float sp = (x > 20.f) ? x : log1pf(expf(x));
    g_dtsp[(b * SEQ + l) * NH + h] = sp;
    float v = -expf(A_log[h]) * sp;

    // intra-warp inclusive scan
#pragma unroll
    for (int off = 1; off < 32; off <<= 1) {
        float n = __shfl_up_sync(0xFFFFFFFFu, v, off);
        if (lane >= off) v += n;
    }
    __shared__ float wsum[8];
    if (lane == 31) wsum[warp] = v;
    __syncthreads();
    float offs = 0.f;
#pragma unroll
    for (int w = 0; w < 8; w++)
        if (w < warp) offs += wsum[w];
    v += offs;

    int base = ((b * NH + h) * NC + c) * CHUNK;
    g_dacs[base + t] = v;
    if (t == CHUNK - 1) g_csum[(b * NH + h) * NC + c] = v;
}

// ---------------- K3: causal depthwise conv4 + SiLU + scatter (8 tokens/thread) ----------------
__global__ __launch_bounds__(256) void conv_kernel(
    const float* __restrict__ conv_w, const float* __restrict__ conv_b)
{
    int ch = blockIdx.y * 256 + threadIdx.x;
    if (ch >= CONVD) return;
    int tok0 = blockIdx.x * 8;
    int b = tok0 / SEQ, l0 = tok0 % SEQ;

    const float* w = conv_w + ch * 4;
    float w0 = w[0], w1 = w[1], w2 = w[2], w3 = w[3];
    float bb = conv_b[ch];

    float xv[11];
#pragma unroll
    for (int r = 0; r < 11; r++) {
        int ls = l0 - 3 + r;
        xv[r] = (ls >= 0) ? g_zxbcdt[(size_t)(b * SEQ + ls) * DIP + DI + ch] : 0.f;
    }

#pragma unroll
    for (int j = 0; j < 8; j++) {
        float acc = bb + w0 * xv[j] + w1 * xv[j + 1] + w2 * xv[j + 2] + w3 * xv[j + 3];
        float v = acc / (1.f + __expf(-acc));
        int l = l0 + j;
        int c = l / CHUNK, t = l % CHUNK;
        if (ch < DI) {
            int h = ch >> 7, p = ch & 127;
            float dt = g_dtsp[(b * SEQ + l) * NH + h];
            g_X[(size_t)(((b * NC + c) * NH + h) * CHUNK + t) * HD + p] = v * dt;
        } else if (ch < DI + DS) {
            g_Bm[((b * NC + c) * CHUNK + t) * DS + (ch - DI)] = v;
        } else {
            g_Cm[((b * NC + c) * CHUNK + t) * DS + (ch - DI - DS)] = v;
        }
    }
}

// ---------------- K4: G[l,s] = sum_n C[l,n] B[s,n] per (b,c) ----------------
__global__ __launch_bounds__(256) void bc_gemm_kernel()
{
    int bc = blockIdx.y;
    int tile = blockIdx.x;
    int l0 = (tile >> 2) * 64, s0 = (tile & 3) * 64;
    __shared__ float Cs[64][65];
    __shared__ float Bs[64][65];
    int tid = threadIdx.x;
    const float* Cb = g_Cm + (size_t)bc * CHUNK * DS;
    const float* Bb = g_Bm + (size_t)bc * CHUNK * DS;

#pragma unroll
    for (int u = 0; u < 4; u++) {
        int e = tid + u * 256;
        int r = e >> 4, cv = (e & 15) << 2;
        float4 vc = *(const float4*)&Cb[(l0 + r) * DS + cv];
        Cs[r][cv + 0] = vc.x; Cs[r][cv + 1] = vc.y; Cs[r][cv + 2] = vc.z; Cs[r][cv + 3] = vc.w;
        float4 vb = *(const float4*)&Bb[(s0 + r) * DS + cv];
        Bs[r][cv + 0] = vb.x; Bs[r][cv + 1] = vb.y; Bs[r][cv + 2] = vb.z; Bs[r][cv + 3] = vb.w;
    }
    __syncthreads();

    int sq = tid & 15, lq = tid >> 4;
    float acc[4][4];
#pragma unroll
    for (int i = 0; i < 4; i++)
#pragma unroll
        for (int j = 0; j < 4; j++) acc[i][j] = 0.f;

#pragma unroll 8
    for (int n = 0; n < 64; n++) {
        float a[4], bb[4];
#pragma unroll
        for (int i = 0; i < 4; i++) a[i] = Cs[lq * 4 + i][n];
#pragma unroll
        for (int j = 0; j < 4; j++) bb[j] = Bs[sq * 4 + j][n];
#pragma unroll
        for (int i = 0; i < 4; i++)
#pragma unroll
            for (int j = 0; j < 4; j++) acc[i][j] = fmaf(a[i], bb[j], acc[i][j]);
    }
    float* Gout = g_G + (size_t)bc * CHUNK * CHUNK;
#pragma unroll
    for (int i = 0; i < 4; i++) {
        float4 v = make_float4(acc[i][0], acc[i][1], acc[i][2], acc[i][3]);
        *(float4*)&Gout[(l0 + lq * 4 + i) * CHUNK + s0 + sq * 4] = v;
    }
}

// ---------------- K5: Y_diag = (G .* L) @ X per (b,c,h), split-bf16 mma ----------------
#define YLDT 40
#define XLDT 136
#define YSMEM (2*256*YLDT*2 + 2*32*XLDT*2 + 256*4 + 256*4)   /* 60416 */

__global__ __launch_bounds__(512, 1) void ydiag_kernel()
{
    extern __shared__ __align__(16) char ysm[];
    __nv_bfloat16* Msh = (__nv_bfloat16*)ysm;
    __nv_bfloat16* Msl = Msh + 256 * YLDT;
    __nv_bfloat16* Xsh = Msl + 256 * YLDT;
    __nv_bfloat16* Xsl = Xsh + 32 * XLDT;
    float* acs   = (float*)(Xsl + 32 * XLDT);
    float* cfall = acs + 256;

    uint32_t msh_b = smem_u32(Msh), msl_b = smem_u32(Msl);
    uint32_t xsh_b = smem_u32(Xsh), xsl_b = smem_u32(Xsl);

    int blk = blockIdx.x;
    int h = blk % NH; int bc = blk / NH;
    int c = bc % NC;  int b = bc / NC;
    int tid = threadIdx.x;
    int warp = tid >> 5, lane = tid & 31;
    int wm = warp & 7, wn = warp >> 3;

    if (tid < 256) acs[tid] = g_dacs[((b * NH + h) * NC + c) * CHUNK + tid];
    __syncthreads();
    if (tid < 256) cfall[tid] = __expf(acs[tid & ~31] - acs[tid]);
    __syncthreads();

    const float* Gb = g_G + (size_t)bc * CHUNK * CHUNK;
    const float* Xb = g_X + (size_t)blk * CHUNK * HD;

    float acc[2][8][4];
#pragma unroll
    for (int mi = 0; mi < 2; mi++)
#pragma unroll
        for (int ni = 0; ni < 8; ni++)
#pragma unroll
            for (int e = 0; e < 4; e++) acc[mi][ni][e] = 0.f;

    int lrow16 = lane & 15, lkoff = (lane >> 4) * 8;
    int bl = tid >> 1, bs = (tid & 1) * 16;
    int i8 = lane & 7, sel = lane >> 3;

    for (int s0 = 0; s0 < CHUNK; s0 += 32) {
        if (s0) __syncthreads();

#pragma unroll
        for (int u = 0; u < 2; u++) {
            int e = tid + u * 512;
            int s = e >> 5, p4 = e & 31;
            float4 v = *(const float4*)&Xb[(s0 + s) * HD + p4 * 4];
            uint32_t h0, l0, h1, l1;
            split2(v.x, v.y, h0, l0);
            split2(v.z, v.w, h1, l1);
            uint32_t off = (uint32_t)(s * XLDT + p4 * 4) * 2;
            asm volatile("st.shared.v2.b32 [%0], {%1,%2};" :: "r"(xsh_b + off), "r"(h0), "r"(h1) : "memory");
            asm volatile("st.shared.v2.b32 [%0], {%1,%2};" :: "r"(xsl_b + off), "r"(l0), "r"(l1) : "memory");
        }

        if (bl >= s0 - 32) {
            float rowfac = __expf(acs[bl] - acs[s0]);
#pragma unroll
            for (int j4 = 0; j4 < 4; j4++) {
                int sg = s0 + bs + j4 * 4;
                float4 g4 = *(const float4*)&Gb[bl * CHUNK + sg];
                float m0 = (sg + 0 <= bl) ? g4.x * rowfac * cfall[sg + 0] : 0.f;
                float m1 = (sg + 1 <= bl) ? g4.y * rowfac * cfall[sg + 1] : 0.f;
                float m2 = (sg + 2 <= bl) ? g4.z * rowfac * cfall[sg + 2] : 0.f;
                float m3 = (sg + 3 <= bl) ? g4.w * rowfac * cfall[sg + 3] : 0.f;
                uint32_t h01, l01, h23, l23;
                split2(m0, m1, h01, l01);
                split2(m2, m3, h23, l23);
                uint32_t off = (uint32_t)(bl * YLDT + bs + j4 * 4) * 2;
                asm volatile("st.shared.v2.b32 [%0], {%1,%2};" :: "r"(msh_b + off), "r"(h01), "r"(h23) : "memory");
                asm volatile("st.shared.v2.b32 [%0], {%1,%2};" :: "r"(msl_b + off), "r"(l01), "r"(l23) : "memory");
            }
        }
        __syncthreads();

        if (wm * 32 + 31 >= s0) {
#pragma unroll
            for (int ks = 0; ks < 32; ks += 16) {
                uint32_t ahf[2][4], alf[2][4];
#pragma unroll
                for (int mi = 0; mi < 2; mi++) {
                    uint32_t off = (uint32_t)((wm * 32 + mi * 16 + lrow16) * YLDT + ks + lkoff) * 2;
                    LDMX4(ahf[mi][0], ahf[mi][1], ahf[mi][2], ahf[mi][3], msh_b + off);
                    LDMX4(alf[mi][0], alf[mi][1], alf[mi][2], alf[mi][3], msl_b + off);
                }
#pragma unroll
                for (int nt = 0; nt < 4; nt++) {
                    uint32_t xoff = (uint32_t)((ks + (sel >> 1) * 8 + i8) * XLDT
                                               + wn * 64 + nt * 16 + (sel & 1) * 8) * 2;
                    uint32_t h0, h1, h2, h3, l0, l1, l2, l3;
                    LDMX4T(h0, h1, h2, h3, xsh_b + xoff);
                    LDMX4T(l0, l1, l2, l3, xsl_b + xoff);
#pragma unroll
                    for (int mi = 0; mi < 2; mi++) {
                        MMA16816(acc[mi][nt * 2 + 0], ahf[mi], h0, h2);
                        MMA16816(acc[mi][nt * 2 + 0], alf[mi], h0, h2);
                        MMA16816(acc[mi][nt * 2 + 0], ahf[mi], l0, l2);
                        MMA16816(acc[mi][nt * 2 + 1], ahf[mi], h1, h3);
                        MMA16816(acc[mi][nt * 2 + 1], alf[mi], h1, h3);
                        MMA16816(acc[mi][nt * 2 + 1], ahf[mi], l1, l3);
                    }
                }
            }
        }
    }

    int rbase = wm * 32 + (lane >> 2);
    int cbase = wn * 64 + (lane & 3) * 2;
#pragma unroll
    for (int mi = 0; mi < 2; mi++) {
#pragma unroll
        for (int ni = 0; ni < 8; ni++) {
            int l0r = rbase + mi * 16;
            int col = cbase + ni * 8;
            float* out0 = g_y + (size_t)(b * SEQ + c * CHUNK + l0r) * DI + h * HD + col;
            *(float2*)out0 = make_float2(acc[mi][ni][0], acc[mi][ni][1]);
            float* out1 = g_y + (size_t)(b * SEQ + c * CHUNK + l0r + 8) * DI + h * HD + col;
            *(float2*)out1 = make_float2(acc[mi][ni][2], acc[mi][ni][3]);
        }
    }
}

// ---------------- K5b: states via mma: S[p,n] = sum_l X[l,p]*w[l]*B[l,n] ----------------
// 256 thr = 8 warps, each warp one p16 tile, all 64 n. A = X^T (trans ldmatrix),
// B = w.*Bm (trans ldmatrix from [l][n]). Validated numerically in R9.
#define SXP 136
#define SBP 72

__global__ __launch_bounds__(256, 1) void states_kernel()
{
    __shared__ __align__(16) __nv_bfloat16 Xh[32 * SXP];
    __shared__ __align__(16) __nv_bfloat16 Xl[32 * SXP];
    __shared__ __align__(16) __nv_bfloat16 Bh2[32 * SBP];
    __shared__ __align__(16) __nv_bfloat16 Bl2[32 * SBP];
    __shared__ float acs[CHUNK];

    uint32_t xh_b = smem_u32(Xh), xl_b = smem_u32(Xl);
    uint32_t bh_b = smem_u32(Bh2), bl_b = smem_u32(Bl2);

    int blk = blockIdx.x;
    int h = blk % NH; int bc = blk / NH;
    int c = bc % NC;  int b = bc / NC;
    int tid = threadIdx.x;
    int warp = tid >> 5, lane = tid & 31;
    int i8 = lane & 7, sel = lane >> 3;

    if (tid < 256) acs[tid] = g_dacs[((b * NH + h) * NC + c) * CHUNK + tid];
    __syncthreads();
    float alast = acs[CHUNK - 1];

    const float* Xb = g_X + (size_t)blk * CHUNK * HD;
    const float* Bb = g_Bm + (size_t)bc * CHUNK * DS;

    float acc[8][4];
#pragma unroll
    for (int ni = 0; ni < 8; ni++)
#pragma unroll
        for (int e = 0; e < 4; e++) acc[ni][e] = 0.f;

    for (int l0 = 0; l0 < CHUNK; l0 += 32) {
        if (l0) __syncthreads();
        // X tile 32x128 -> bf16 hi/lo [l][p]
#pragma unroll
        for (int u = 0; u < 4; u++) {
            int e = tid + u * 256;
            int s = e >> 5, p4 = e & 31;
            float4 v = *(const float4*)&Xb[(l0 + s) * HD + p4 * 4];
            uint32_t h0, l0r, h1, l1r;
            split2(v.x, v.y, h0, l0r);
            split2(v.z, v.w, h1, l1r);
            uint32_t off = (uint32_t)(s * SXP + p4 * 4) * 2;
            asm volatile("st.shared.v2.b32 [%0], {%1,%2};" :: "r"(xh_b + off), "r"(h0), "r"(h1) : "memory");
            asm volatile("st.shared.v2.b32 [%0], {%1,%2};" :: "r"(xl_b + off), "r"(l0r), "r"(l1r) : "memory");
        }
        // B' tile 32x64 = w[l]*Bm -> bf16 hi/lo [l][n]
#pragma unroll
        for (int u = 0; u < 2; u++) {
            int e = tid + u * 256;
            int s = e >> 4, n4 = e & 15;
            float w = __expf(alast - acs[l0 + s]);
            float4 v = *(const float4*)&Bb[(l0 + s) * DS + n4 * 4];
            uint32_t h0, l0r, h1, l1r;
            split2(v.x * w, v.y * w, h0, l0r);
            split2(v.z * w, v.w * w, h1, l1r);
            uint32_t off = (uint32_t)(s * SBP + n4 * 4) * 2;
            asm volatile("st.shared.v2.b32 [%0], {%1,%2};" :: "r"(bh_b + off), "r"(h0), "r"(h1) : "memory");
            asm volatile("st.shared.v2.b32 [%0], {%1,%2};" :: "r"(bl_b + off), "r"(l0r), "r"(l1r) : "memory");
        }
        __syncthreads();

#pragma unroll
        for (int ks = 0; ks < 32; ks += 16) {
            uint32_t aoff = (uint32_t)((ks + (sel >> 1) * 8 + i8) * SXP
                                       + warp * 16 + (sel & 1) * 8) * 2;
            uint32_t ah[4], al[4];
            LDMX4T(ah[0], ah[1], ah[2], ah[3], xh_b + aoff);
            LDMX4T(al[0], al[1], al[2], al[3], xl_b + aoff);
#pragma unroll
            for (int nt = 0; nt < 2; nt++) {
                uint32_t boff = (uint32_t)((ks + (sel >> 1) * 8 + i8) * SBP
                                           + nt * 32 + (sel & 1) * 8) * 2;
                uint32_t h0, h1, h2, h3, l0r, l1r, l2r, l3r;
                LDMX4T(h0, h1, h2, h3, bh_b + boff);
                LDMX4T(l0r, l1r, l2r, l3r, bl_b + boff);
                MMA16816(acc[nt * 4 + 0], ah, h0, h2);
                MMA16816(acc[nt * 4 + 0], al, h0, h2);
                MMA16816(acc[nt * 4 + 0], ah, l0r, l2r);
                MMA16816(acc[nt * 4 + 1], ah, h1, h3);
                MMA16816(acc[nt * 4 + 1], al, h1, h3);
                MMA16816(acc[nt * 4 + 1], ah, l1r, l3r);
                uint32_t boff2 = (uint32_t)((ks + (sel >> 1) * 8 + i8) * SBP
                                            + nt * 32 + 16 + (sel & 1) * 8) * 2;
                LDMX4T(h0, h1, h2, h3, bh_b + boff2);
                LDMX4T(l0r, l1r, l2r, l3r, bl_b + boff2);
                MMA16816(acc[nt * 4 + 2], ah, h0, h2);
                MMA16816(acc[nt * 4 + 2], al, h0, h2);
                MMA16816(acc[nt * 4 + 2], ah, l0r, l2r);
                MMA16816(acc[nt * 4 + 3], ah, h1, h3);
                MMA16816(acc[nt * 4 + 3], al, h1, h3);
                MMA16816(acc[nt * 4 + 3], ah, l1r, l3r);
            }
        }
    }

    float* So = g_states + (size_t)blk * HD * DS;
    int p0 = warp * 16 + (lane >> 2);
    int nc0 = (lane & 3) * 2;
#pragma unroll
    for (int ni = 0; ni < 8; ni++) {
        int col = nc0 + ni * 8;
        *(float2*)&So[p0 * DS + col] = make_float2(acc[ni][0], acc[ni][1]);
        *(float2*)&So[(p0 + 8) * DS + col] = make_float2(acc[ni][2], acc[ni][3]);
    }
}

// ---------------- K6: inter-chunk scan (8-way split, float4) ----------------
__global__ __launch_bounds__(256) void scan_kernel()
{
    int blk = blockIdx.x;
    int part = blk & 7;
    int bh = blk >> 3;
    int b = bh / NH, h = bh % NH;
    int e0 = part * 1024 + threadIdx.x * 4;

    float4 S = make_float4(0.f, 0.f, 0.f, 0.f);
    for (int c = 0; c < NC; c++) {
        float dec = __expf(g_csum[bh * NC + c]);
        size_t base = (size_t)((b * NC + c) * NH + h) * HD * DS + e0;
        *(float4*)&g_inter[base] = S;
        float4 v = *(const float4*)&g_states[base];
        S.x = S.x * dec + v.x;
        S.y = S.y * dec + v.y;
        S.z = S.z * dec + v.z;
        S.w = S.w * dec + v.w;
    }
}

// ---------------- K7: Y_off + combine + silu(z) gate ----------------
__global__ __launch_bounds__(256) void yoff_kernel()
{
    int blk = blockIdx.x;
    int h = blk % NH; int bc = blk / NH;
    int c = bc % NC;  int b = bc / NC;

    __shared__ float Is[HD][DS + 1];
    __shared__ float Cs[64][DS + 1];
    __shared__ float acs[CHUNK];
    int tid = threadIdx.x;
    if (tid < 256) acs[tid] = g_dacs[((b * NH + h) * NC + c) * CHUNK + tid];

    const float* Ib = g_inter + (size_t)blk * HD * DS;
#pragma unroll
    for (int u = 0; u < 8; u++) {
        int e = tid + u * 256;
        int r = e >> 4, cv = (e & 15) << 2;
        float4 v = *(const float4*)&Ib[r * DS + cv];
        Is[r][cv + 0] = v.x; Is[r][cv + 1] = v.y; Is[r][cv + 2] = v.z; Is[r][cv + 3] = v.w;
    }

    int tq = tid & 7, pq = tid >> 3;
    const float* Cb = g_Cm + (size_t)bc * CHUNK * DS;

    for (int tg = 0; tg < 4; tg++) {
        __syncthreads();
#pragma unroll
        for (int u = 0; u < 4; u++) {
            int e = tid + u * 256;
            int r = e >> 4, cv = (e & 15) << 2;
            float4 v = *(const float4*)&Cb[(tg * 64 + r) * DS + cv];
            Cs[r][cv + 0] = v.x; Cs[r][cv + 1] = v.y; Cs[r][cv + 2] = v.z; Cs[r][cv + 3] = v.w;
        }
        __syncthreads();

        float acc[8][4];
#pragma unroll
        for (int k = 0; k < 8; k++)
#pragma unroll
            for (int i = 0; i < 4; i++) acc[k][i] = 0.f;

#pragma unroll 4
        for (int n = 0; n < DS; n++) {
            float iv[4];
#pragma unroll
            for (int i = 0; i < 4; i++) iv[i] = Is[pq * 4 + i][n];
#pragma unroll
            for (int k = 0; k < 8; k++) {
                float cv = Cs[k * 8 + tq][n];
#pragma unroll
                for (int i = 0; i < 4; i++)
                    acc[k][i] = fmaf(cv, iv[i], acc[k][i]);
            }
        }

#pragma unroll
        for (int k = 0; k < 8; k++) {
            int t = tg * 64 + k * 8 + tq;
            float ea = __expf(acs[t]);
            int gl = c * CHUNK + t;
            size_t yidx = (size_t)(b * SEQ + gl) * DI + h * HD + pq * 4;
            size_t zidx = (size_t)(b * SEQ + gl) * DIP + h * HD + pq * 4;
            float4 yd = *(float4*)&g_y[yidx];
            float4 z  = *(const float4*)&g_zxbcdt[zidx];
            float4 o;
            o.x = (yd.x + ea * acc[k][0]) * z.x / (1.f + __expf(-z.x));
            o.y = (yd.y + ea * acc[k][1]) * z.y / (1.f + __expf(-z.y));
            o.z = (yd.z + ea * acc[k][2]) * z.z / (1.f + __expf(-z.z));
            o.w = (yd.w + ea * acc[k][3]) * z.w / (1.f + __expf(-z.w));
            *(float4*)&g_y[yidx] = o;
        }
    }
}

// ---------------- K8: layernorm over 4096, emits split bf16 hi/lo ----------------
__global__ __launch_bounds__(256) void ln_kernel(
    const float* __restrict__ ln_w, const float* __restrict__ ln_b)
{
    int tok = blockIdx.x;
    const float* y = g_y + (size_t)tok * DI;
    __nv_bfloat16* ohi = g_yn_hi + (size_t)tok * DI;
    __nv_bfloat16* olo = g_yn_lo + (size_t)tok * DI;
    int tid = threadIdx.x;

    float v[16];
    float s = 0.f, ss = 0.f;
#pragma unroll
    for (int u = 0; u < 4; u++) {
        float4 x = *(const float4*)&y[tid * 4 + u * 1024];
        v[u * 4 + 0] = x.x; v[u * 4 + 1] = x.y; v[u * 4 + 2] = x.z; v[u * 4 + 3] = x.w;
        s += x.x + x.y + x.z + x.w;
        ss += x.x * x.x + x.y * x.y + x.z * x.z + x.w * x.w;
    }
#pragma unroll
    for (int off = 16; off; off >>= 1) {
        s  += __shfl_xor_sync(0xFFFFFFFFu, s, off);
        ss += __shfl_xor_sync(0xFFFFFFFFu, ss, off);
    }
    __shared__ float rs[8], rss[8];
    int warp = tid >> 5, lane = tid & 31;
    if (lane == 0) { rs[warp] = s; rss[warp] = ss; }
    __syncthreads();
    s = 0.f; ss = 0.f;
#pragma unroll
    for (int w = 0; w < 8; w++) { s += rs[w]; ss += rss[w]; }
    float mu = s * (1.f / DI);
    float var = ss * (1.f / DI) - mu * mu;
    float rstd = rsqrtf(var + 1e-5f);
#pragma unroll
    for (int u = 0; u < 4; u++) {
        int idx = tid * 4 + u * 1024;
        float4 w4 = *(const float4*)&ln_w[idx];
        float4 b4 = *(const float4*)&ln_b[idx];
        float o0 = (v[u * 4 + 0] - mu) * rstd * w4.x + b4.x;
        float o1 = (v[u * 4 + 1] - mu) * rstd * w4.y + b4.y;
        float o2 = (v[u * 4 + 2] - mu) * rstd * w4.z + b4.z;
        float o3 = (v[u * 4 + 3] - mu) * rstd * w4.w + b4.w;
        uint2 hh, ll;
        split2(o0, o1, hh.x, ll.x);
        split2(o2, o3, hh.y, ll.y);
        *(uint2*)&ohi[idx] = hh;
        *(uint2*)&olo[idx] = ll;
    }
}

// ---------------- launch ----------------
extern "C" void kernel_launch(void* const* d_in, const int* in_sizes, int n_in,
                              void* d_out, int out_size)
{
    const float* u          = (const float*)d_in[0];
    const float* in_proj_w  = (const float*)d_in[1];
    const float* in_proj_b  = (const float*)d_in[2];
    const float* conv_w     = (const float*)d_in[3];
    const float* conv_b     = (const float*)d_in[4];
    const float* dt_bias    = (const float*)d_in[5];
    const float* A_log      = (const float*)d_in[6];
    const float* ln_w       = (const float*)d_in[7];
    const float* ln_b       = (const float*)d_in[8];
    const float* out_proj_w = (const float*)d_in[9];
    const float* out_proj_b = (const float*)d_in[10];
    float* out = (float*)d_out;

    float* zx; cudaGetSymbolAddress((void**)&zx, g_zxbcdt);
    __nv_bfloat16 *uh, *ul, *w1h, *w1l, *w2h, *w2l, *ynh, *ynl;
    cudaGetSymbolAddress((void**)&uh,  g_u_hi);
    cudaGetSymbolAddress((void**)&ul,  g_u_lo);
    cudaGetSymbolAddress((void**)&w1h, g_w1_hi);
    cudaGetSymbolAddress((void**)&w1l, g_w1_lo);
    cudaGetSymbolAddress((void**)&w2h, g_w2_hi);
    cudaGetSymbolAddress((void**)&w2l, g_w2_lo);
    cudaGetSymbolAddress((void**)&ynh, g_yn_hi);
    cudaGetSymbolAddress((void**)&ynl, g_yn_lo);

    cudaFuncSetAttribute(gemm_mma, cudaFuncAttributeMaxDynamicSharedMemorySize, GEMM_SMEM);
    cudaFuncSetAttribute(ydiag_kernel, cudaFuncAttributeMaxDynamicSharedMemorySize, YSMEM);

    // K0: pre-split u / weights into bf16 hi/lo
    split_kernel<<<(TOK * DM / 4 + 255) / 256, 256>>>(u, uh, ul, TOK * DM / 4);
    split_kernel<<<(DIP * DM / 4 + 255) / 256, 256>>>(in_proj_w, w1h, w1l, DIP * DM / 4);
    split_kernel<<<(DM * DI / 4 + 255) / 256, 256>>>(out_proj_w, w2h, w2l, DM * DI / 4);

    // K1: in_proj GEMM (8192 x 8352 x 2048)
    gemm_mma<<<dim3((DIP + BN - 1) / BN, TOK / BM), 256, GEMM_SMEM>>>(
        uh, ul, w1h, w1l, in_proj_b, zx, TOK, DIP, DM);
    // K2: dt softplus + per-chunk cumsum (warp scan)
    dt_scan_kernel<<<BATCH * NH * NC, CHUNK>>>(dt_bias, A_log);
    // K3: conv + silu + scatter (8 tokens/thread)
    conv_kernel<<<dim3(TOK / 8, (CONVD + 255) / 256), 256>>>(conv_w, conv_b);
    // K4: G = C B^T per (b,c)
    bc_gemm_kernel<<<dim3(16, BATCH * NC), 256>>>();
    // K5: Y_diag (split-bf16 mma)
    ydiag_kernel<<<BATCH * NC * NH, 512, YSMEM>>>();
    // K5b: local chunk states (split-bf16 mma)
    states_kernel<<<BATCH * NC * NH, 256>>>();
    // K6: inter-chunk scan (8-way split)
    scan_kernel<<<BATCH * NH * 8, 256>>>();
    // K7: Y_off + gate
    yoff_kernel<<<BATCH * NC * NH, 256>>>();
    // K8: layernorm (emits bf16 hi/lo)
    ln_kernel<<<TOK, 256>>>(ln_w, ln_b);
    // K9: out_proj GEMM (8192 x 2048 x 4096)
    gemm_mma<<<dim3(DM / BN, TOK / BM), 256, GEMM_SMEM>>>(
        ynh, ynl, w2h, w2l, out_proj_b, out, TOK, DM, DI);
}

// round 17
// speedup vs baseline: 1.3309x; 1.0128x over previous
#include <cuda_runtime.h>
#include <cuda_bf16.h>
#include <math.h>
#include <stdint.h>

#define BATCH 2
#define SEQ   4096
#define DM    2048
#define DI    4096
#define NH    32
#define HD    128
#define DS    64
#define CONVD (DI + 2*DS)          /* 4224 */
#define DIP   (2*DI + 2*DS + NH)   /* 8352 */
#define OFF_DT (DI + CONVD)        /* 8320 */
#define CHUNK 256
#define NC    (SEQ/CHUNK)          /* 16 */
#define TOK   (BATCH*SEQ)          /* 8192 */

// ---------------- scratch (device globals; no allocation allowed) ----------------
__device__ float g_zxbcdt[(size_t)TOK*DIP];
__device__ float g_dtsp[TOK*NH];
__device__ float g_dacs[BATCH*NH*NC*CHUNK];
__device__ float g_csum[BATCH*NH*NC];
__device__ float g_X[(size_t)BATCH*NC*NH*CHUNK*HD];
__device__ float g_Bm[BATCH*NC*CHUNK*DS];
__device__ float g_Cm[BATCH*NC*CHUNK*DS];
__device__ float g_G[BATCH*NC*CHUNK*CHUNK];
__device__ float g_states[(size_t)BATCH*NC*NH*HD*DS];
__device__ float g_inter[(size_t)BATCH*NC*NH*HD*DS];
__device__ float g_y[(size_t)TOK*DI];
// pre-split bf16 operands for the two big GEMMs
__device__ __nv_bfloat16 g_u_hi[(size_t)TOK*DM];
__device__ __nv_bfloat16 g_u_lo[(size_t)TOK*DM];
__device__ __nv_bfloat16 g_w1_hi[(size_t)DIP*DM];
__device__ __nv_bfloat16 g_w1_lo[(size_t)DIP*DM];
__device__ __nv_bfloat16 g_w2_hi[(size_t)DM*DI];
__device__ __nv_bfloat16 g_w2_lo[(size_t)DM*DI];
__device__ __nv_bfloat16 g_yn_hi[(size_t)TOK*DI];
__device__ __nv_bfloat16 g_yn_lo[(size_t)TOK*DI];

// ================= helpers =================
__device__ __forceinline__ uint32_t smem_u32(const void* p) {
    uint32_t a;
    asm("{ .reg .u64 t; cvta.to.shared.u64 t, %1; cvt.u32.u64 %0, t; }" : "=r"(a) : "l"(p));
    return a;
}
// split x0,x1 -> hi bf16x2 (rn) and lo bf16x2 (residual)
__device__ __forceinline__ void split2(float x0, float x1, uint32_t& hi, uint32_t& lo) {
    uint32_t h;
    asm("cvt.rn.bf16x2.f32 %0, %1, %2;" : "=r"(h) : "f"(x1), "f"(x0));
    float h0 = __uint_as_float(h << 16);
    float h1 = __uint_as_float(h & 0xFFFF0000u);
    float l0 = x0 - h0, l1 = x1 - h1;
    asm("cvt.rn.bf16x2.f32 %0, %1, %2;" : "=r"(lo) : "f"(l1), "f"(l0));
    hi = h;
}
#define LDMX4(r0, r1, r2, r3, addr) \
    asm volatile("ldmatrix.sync.aligned.m8n8.x4.shared.b16 {%0,%1,%2,%3}, [%4];" \
                 : "=r"(r0), "=r"(r1), "=r"(r2), "=r"(r3) : "r"(addr))
#define LDMX4T(r0, r1, r2, r3, addr) \
    asm volatile("ldmatrix.sync.aligned.m8n8.x4.trans.shared.b16 {%0,%1,%2,%3}, [%4];" \
                 : "=r"(r0), "=r"(r1), "=r"(r2), "=r"(r3) : "r"(addr))
#define MMA16816(d, a, b0, b1) \
    asm volatile("mma.sync.aligned.m16n8k16.row.col.f32.bf16.bf16.f32 " \
                 "{%0,%1,%2,%3}, {%4,%5,%6,%7}, {%8,%9}, {%0,%1,%2,%3};" \
                 : "+f"(d[0]), "+f"(d[1]), "+f"(d[2]), "+f"(d[3]) \
                 : "r"(a[0]), "r"(a[1]), "r"(a[2]), "r"(a[3]), "r"(b0), "r"(b1))
#define CP16(dst, src, nbytes) \
    asm volatile("cp.async.ca.shared.global [%0], [%1], 16, %2;" \
                 :: "r"(dst), "l"(src), "r"(nbytes) : "memory")
#define CPCOMMIT() asm volatile("cp.async.commit_group;" ::: "memory")
#define CPWAIT1()  asm volatile("cp.async.wait_group 1;" ::: "memory")

// ---------------- K0: split pass f32 -> hi/lo bf16 ----------------
__global__ __launch_bounds__(256) void split_kernel(
    const float* __restrict__ src, __nv_bfloat16* __restrict__ hi,
    __nv_bfloat16* __restrict__ lo, int n4)
{
    int idx = blockIdx.x * 256 + threadIdx.x;
    if (idx >= n4) return;
    float4 v = ((const float4*)src)[idx];
    uint2 h, l;
    split2(v.x, v.y, h.x, l.x);
    split2(v.z, v.w, h.y, l.y);
    *(uint2*)&hi[(size_t)idx * 4] = h;
    *(uint2*)&lo[(size_t)idx * 4] = l;
}

// ---------------- K1/K9: cp.async double-buffered split-bf16 mma GEMM ----------------
#define BM 128
#define BN 128
#define BK 32
#define LDT 40                        /* padded bf16 row stride (80B) */
#define TARR (BM * LDT * 2)           /* one operand array: 10240 B */
#define STAGE (4 * TARR)              /* Ah,Al,Bh,Bl: 40960 B */
#define GEMM_SMEM (2 * STAGE)         /* 81920 B */

__global__ __launch_bounds__(256, 2) void gemm_mma(
    const __nv_bfloat16* __restrict__ Agh, const __nv_bfloat16* __restrict__ Agl,
    const __nv_bfloat16* __restrict__ Bgh, const __nv_bfloat16* __restrict__ Bgl,
    const float* __restrict__ bias, float* __restrict__ C,
    int M, int N, int K)
{
    extern __shared__ __align__(16) char gsm[];
    uint32_t sb = smem_u32(gsm);

    int tid = threadIdx.x;
    int warp = tid >> 5, lane = tid & 31;
    int wm = warp & 3, wn = warp >> 2;
    int m0 = blockIdx.y * BM, n0 = blockIdx.x * BN;

    float acc[2][8][4];
#pragma unroll
    for (int mi = 0; mi < 2; mi++)
#pragma unroll
        for (int ni = 0; ni < 8; ni++)
#pragma unroll
            for (int e = 0; e < 4; e++) acc[mi][ni][e] = 0.f;

    int r0 = tid >> 2;            // 0..63
    int c8 = (tid & 3) * 8;       // bf16 col: 0,8,16,24

    const size_t arow0 = (size_t)(m0 + r0) * K + c8;
    const size_t arow1 = (size_t)(m0 + r0 + 64) * K + c8;
    const bool ok0 = (n0 + r0) < N;
    const bool ok1 = (n0 + r0 + 64) < N;
    const size_t brow0 = (size_t)(ok0 ? n0 + r0 : 0) * K + c8;
    const size_t brow1 = (size_t)(ok1 ? n0 + r0 + 64 : 0) * K + c8;
    const int nb0 = ok0 ? 16 : 0;
    const int nb1 = ok1 ? 16 : 0;
    const uint32_t so0 = (uint32_t)(r0 * LDT + c8) * 2;
    const uint32_t so1 = (uint32_t)((r0 + 64) * LDT + c8) * 2;

    int lrow16 = lane & 15;
    int lkoff  = (lane >> 4) * 8;

    auto issue = [&](uint32_t st, int k0) {
        CP16(st + so0,            Agh + arow0 + k0, 16);
        CP16(st + so0 + TARR,     Agl + arow0 + k0, 16);
        CP16(st + so0 + 2 * TARR, Bgh + brow0 + k0, nb0);
        CP16(st + so0 + 3 * TARR, Bgl + brow0 + k0, nb0);
        CP16(st + so1,            Agh + arow1 + k0, 16);
        CP16(st + so1 + TARR,     Agl + arow1 + k0, 16);
        CP16(st + so1 + 2 * TARR, Bgh + brow1 + k0, nb1);
        CP16(st + so1 + 3 * TARR, Bgl + brow1 + k0, nb1);
    };

    const int ntiles = K >> 5;
    issue(sb, 0);          CPCOMMIT();
    issue(sb + STAGE, BK); CPCOMMIT();

    for (int t = 0; t < ntiles; t++) {
        CPWAIT1();
        __syncthreads();
        uint32_t buf = sb + (t & 1) * STAGE;
        uint32_t ah_b = buf, al_b = buf + TARR;
        uint32_t bh_b = buf + 2 * TARR, bl_b = buf + 3 * TARR;

#pragma unroll
        for (int ks = 0; ks < BK; ks += 16) {
            uint32_t ahf[2][4], alf[2][4];
#pragma unroll
            for (int mi = 0; mi < 2; mi++) {
                uint32_t off = (uint32_t)((wm * 32 + mi * 16 + lrow16) * LDT + ks + lkoff) * 2;
                LDMX4(ahf[mi][0], ahf[mi][1], ahf[mi][2], ahf[mi][3], ah_b + off);
                LDMX4(alf[mi][0], alf[mi][1], alf[mi][2], alf[mi][3], al_b + off);
            }
#pragma unroll
            for (int nt = 0; nt < 4; nt++) {
                uint32_t off = (uint32_t)((wn * 64 + nt * 16 + lrow16) * LDT + ks + lkoff) * 2;
                uint32_t h0, h1, h2, h3, l0, l1, l2, l3;
                LDMX4(h0, h1, h2, h3, bh_b + off);
                LDMX4(l0, l1, l2, l3, bl_b + off);
#pragma unroll
                for (int mi = 0; mi < 2; mi++) {
                    MMA16816(acc[mi][nt * 2 + 0], ahf[mi], h0, h2);
                    MMA16816(acc[mi][nt * 2 + 0], alf[mi], h0, h2);
                    MMA16816(acc[mi][nt * 2 + 0], ahf[mi], l0, l2);
                    MMA16816(acc[mi][nt * 2 + 1], ahf[mi], h1, h3);
                    MMA16816(acc[mi][nt * 2 + 1], alf[mi], h1, h3);
                    MMA16816(acc[mi][nt * 2 + 1], ahf[mi], l1, l3);
                }
            }
        }
        __syncthreads();
        if (t + 2 < ntiles) issue(buf, (t + 2) * BK);
        CPCOMMIT();
    }

    int rbase = m0 + wm * 32 + (lane >> 2);
    int cbase = n0 + wn * 64 + (lane & 3) * 2;
#pragma unroll
    for (int mi = 0; mi < 2; mi++) {
#pragma unroll
        for (int ni = 0; ni < 8; ni++) {
            int col = cbase + ni * 8;
            if (col < N) {
                float2 bb = *(const float2*)&bias[col];
                int r = rbase + mi * 16;
                float2 v0 = make_float2(acc[mi][ni][0] + bb.x, acc[mi][ni][1] + bb.y);
                *(float2*)&C[(size_t)r * N + col] = v0;
                float2 v1 = make_float2(acc[mi][ni][2] + bb.x, acc[mi][ni][3] + bb.y);
                *(float2*)&C[(size_t)(r + 8) * N + col] = v1;
            }
        }
    }
}

// ---------------- K2: dt softplus + per-chunk inclusive cumsum (warp scan) ----------------
__global__ __launch_bounds__(256) void dt_scan_kernel(
    const float* __restrict__ dt_bias, const float* __restrict__ A_log)
{
    int blk = blockIdx.x;
    int c = blk % NC; int bh = blk / NC;
    int h = bh % NH;  int b = bh / NH;
    int t = threadIdx.x;
    int l = c * CHUNK + t;
    int warp = t >> 5, lane = t & 31;

    float x = g_zxbcdt[(size_t)(b * SEQ + l) * DIP + OFF_DT + h] + dt_bias[h];
    float sp = (x > 20.f) ? x : log1pf(expf(x));
    g_dtsp[(b * SEQ + l) * NH + h] = sp;
    float v = -expf(A_log[h]) * sp;

#pragma unroll
    for (int off = 1; off < 32; off <<= 1) {
        float n = __shfl_up_sync(0xFFFFFFFFu, v, off);
        if (lane >= off) v += n;
    }
    __shared__ float wsum[8];
    if (lane == 31) wsum[warp] = v;
    __syncthreads();
    float offs = 0.f;
#pragma unroll
    for (int w = 0; w < 8; w++)
        if (w < warp) offs += wsum[w];
    v += offs;

    int base = ((b * NH + h) * NC + c) * CHUNK;
    g_dacs[base + t] = v;
    if (t == CHUNK - 1) g_csum[(b * NH + h) * NC + c] = v;
}

// ---------------- K3: causal depthwise conv4 + SiLU + scatter (8 tokens/thread) ----------------
__global__ __launch_bounds__(256) void conv_kernel(
    const float* __restrict__ conv_w, const float* __restrict__ conv_b)
{
    int ch = blockIdx.y * 256 + threadIdx.x;
    if (ch >= CONVD) return;
    int tok0 = blockIdx.x * 8;
    int b = tok0 / SEQ, l0 = tok0 % SEQ;

    const float* w = conv_w + ch * 4;
    float w0 = w[0], w1 = w[1], w2 = w[2], w3 = w[3];
    float bb = conv_b[ch];

    float xv[11];
#pragma unroll
    for (int r = 0; r < 11; r++) {
        int ls = l0 - 3 + r;
        xv[r] = (ls >= 0) ? g_zxbcdt[(size_t)(b * SEQ + ls) * DIP + DI + ch] : 0.f;
    }

#pragma unroll
    for (int j = 0; j < 8; j++) {
        float acc = bb + w0 * xv[j] + w1 * xv[j + 1] + w2 * xv[j + 2] + w3 * xv[j + 3];
        float v = acc / (1.f + __expf(-acc));
        int l = l0 + j;
        int c = l / CHUNK, t = l % CHUNK;
        if (ch < DI) {
            int h = ch >> 7, p = ch & 127;
            float dt = g_dtsp[(b * SEQ + l) * NH + h];
            g_X[(size_t)(((b * NC + c) * NH + h) * CHUNK + t) * HD + p] = v * dt;
        } else if (ch < DI + DS) {
            g_Bm[((b * NC + c) * CHUNK + t) * DS + (ch - DI)] = v;
        } else {
            g_Cm[((b * NC + c) * CHUNK + t) * DS + (ch - DI - DS)] = v;
        }
    }
}

// ---------------- K4: G[l,s] = sum_n C[l,n] B[s,n] per (b,c) ----------------
__global__ __launch_bounds__(256) void bc_gemm_kernel()
{
    int bc = blockIdx.y;
    int tile = blockIdx.x;
    int l0 = (tile >> 2) * 64, s0 = (tile & 3) * 64;
    __shared__ float Cs[64][65];
    __shared__ float Bs[64][65];
    int tid = threadIdx.x;
    const float* Cb = g_Cm + (size_t)bc * CHUNK * DS;
    const float* Bb = g_Bm + (size_t)bc * CHUNK * DS;

#pragma unroll
    for (int u = 0; u < 4; u++) {
        int e = tid + u * 256;
        int r = e >> 4, cv = (e & 15) << 2;
        float4 vc = *(const float4*)&Cb[(l0 + r) * DS + cv];
        Cs[r][cv + 0] = vc.x; Cs[r][cv + 1] = vc.y; Cs[r][cv + 2] = vc.z; Cs[r][cv + 3] = vc.w;
        float4 vb = *(const float4*)&Bb[(s0 + r) * DS + cv];
        Bs[r][cv + 0] = vb.x; Bs[r][cv + 1] = vb.y; Bs[r][cv + 2] = vb.z; Bs[r][cv + 3] = vb.w;
    }
    __syncthreads();

    int sq = tid & 15, lq = tid >> 4;
    float acc[4][4];
#pragma unroll
    for (int i = 0; i < 4; i++)
#pragma unroll
        for (int j = 0; j < 4; j++) acc[i][j] = 0.f;

#pragma unroll 8
    for (int n = 0; n < 64; n++) {
        float a[4], bb[4];
#pragma unroll
        for (int i = 0; i < 4; i++) a[i] = Cs[lq * 4 + i][n];
#pragma unroll
        for (int j = 0; j < 4; j++) bb[j] = Bs[sq * 4 + j][n];
#pragma unroll
        for (int i = 0; i < 4; i++)
#pragma unroll
            for (int j = 0; j < 4; j++) acc[i][j] = fmaf(a[i], bb[j], acc[i][j]);
    }
    float* Gout = g_G + (size_t)bc * CHUNK * CHUNK;
#pragma unroll
    for (int i = 0; i < 4; i++) {
        float4 v = make_float4(acc[i][0], acc[i][1], acc[i][2], acc[i][3]);
        *(float4*)&Gout[(l0 + lq * 4 + i) * CHUNK + s0 + sq * 4] = v;
    }
}

// ---------------- K5: Y_diag = (G .* L) @ X per (b,c,h), split-bf16 mma ----------------
#define YLDT 40
#define XLDT 136
#define YSMEM (2*256*YLDT*2 + 2*32*XLDT*2 + 256*4 + 256*4)   /* 60416 */

__global__ __launch_bounds__(512, 1) void ydiag_kernel()
{
    extern __shared__ __align__(16) char ysm[];
    __nv_bfloat16* Msh = (__nv_bfloat16*)ysm;
    __nv_bfloat16* Msl = Msh + 256 * YLDT;
    __nv_bfloat16* Xsh = Msl + 256 * YLDT;
    __nv_bfloat16* Xsl = Xsh + 32 * XLDT;
    float* acs   = (float*)(Xsl + 32 * XLDT);
    float* cfall = acs + 256;

    uint32_t msh_b = smem_u32(Msh), msl_b = smem_u32(Msl);
    uint32_t xsh_b = smem_u32(Xsh), xsl_b = smem_u32(Xsl);

    int blk = blockIdx.x;
    int h = blk % NH; int bc = blk / NH;
    int c = bc % NC;  int b = bc / NC;
    int tid = threadIdx.x;
    int warp = tid >> 5, lane = tid & 31;
    int wm = warp & 7, wn = warp >> 3;

    if (tid < 256) acs[tid] = g_dacs[((b * NH + h) * NC + c) * CHUNK + tid];
    __syncthreads();
    if (tid < 256) cfall[tid] = __expf(acs[tid & ~31] - acs[tid]);
    __syncthreads();

    const float* Gb = g_G + (size_t)bc * CHUNK * CHUNK;
    const float* Xb = g_X + (size_t)blk * CHUNK * HD;

    float acc[2][8][4];
#pragma unroll
    for (int mi = 0; mi < 2; mi++)
#pragma unroll
        for (int ni = 0; ni < 8; ni++)
#pragma unroll
            for (int e = 0; e < 4; e++) acc[mi][ni][e] = 0.f;

    int lrow16 = lane & 15, lkoff = (lane >> 4) * 8;
    int bl = tid >> 1, bs = (tid & 1) * 16;
    int i8 = lane & 7, sel = lane >> 3;

    for (int s0 = 0; s0 < CHUNK; s0 += 32) {
        if (s0) __syncthreads();

#pragma unroll
        for (int u = 0; u < 2; u++) {
            int e = tid + u * 512;
            int s = e >> 5, p4 = e & 31;
            float4 v = *(const float4*)&Xb[(s0 + s) * HD + p4 * 4];
            uint32_t h0, l0, h1, l1;
            split2(v.x, v.y, h0, l0);
            split2(v.z, v.w, h1, l1);
            uint32_t off = (uint32_t)(s * XLDT + p4 * 4) * 2;
            asm volatile("st.shared.v2.b32 [%0], {%1,%2};" :: "r"(xsh_b + off), "r"(h0), "r"(h1) : "memory");
            asm volatile("st.shared.v2.b32 [%0], {%1,%2};" :: "r"(xsl_b + off), "r"(l0), "r"(l1) : "memory");
        }

        if (bl >= s0 - 32) {
            float rowfac = __expf(acs[bl] - acs[s0]);
#pragma unroll
            for (int j4 = 0; j4 < 4; j4++) {
                int sg = s0 + bs + j4 * 4;
                float4 g4 = *(const float4*)&Gb[bl * CHUNK + sg];
                float m0 = (sg + 0 <= bl) ? g4.x * rowfac * cfall[sg + 0] : 0.f;
                float m1 = (sg + 1 <= bl) ? g4.y * rowfac * cfall[sg + 1] : 0.f;
                float m2 = (sg + 2 <= bl) ? g4.z * rowfac * cfall[sg + 2] : 0.f;
                float m3 = (sg + 3 <= bl) ? g4.w * rowfac * cfall[sg + 3] : 0.f;
                uint32_t h01, l01, h23, l23;
                split2(m0, m1, h01, l01);
                split2(m2, m3, h23, l23);
                uint32_t off = (uint32_t)(bl * YLDT + bs + j4 * 4) * 2;
                asm volatile("st.shared.v2.b32 [%0], {%1,%2};" :: "r"(msh_b + off), "r"(h01), "r"(h23) : "memory");
                asm volatile("st.shared.v2.b32 [%0], {%1,%2};" :: "r"(msl_b + off), "r"(l01), "r"(l23) : "memory");
            }
        }
        __syncthreads();

        if (wm * 32 + 31 >= s0) {
#pragma unroll
            for (int ks = 0; ks < 32; ks += 16) {
                uint32_t ahf[2][4], alf[2][4];
#pragma unroll
                for (int mi = 0; mi < 2; mi++) {
                    uint32_t off = (uint32_t)((wm * 32 + mi * 16 + lrow16) * YLDT + ks + lkoff) * 2;
                    LDMX4(ahf[mi][0], ahf[mi][1], ahf[mi][2], ahf[mi][3], msh_b + off);
                    LDMX4(alf[mi][0], alf[mi][1], alf[mi][2], alf[mi][3], msl_b + off);
                }
#pragma unroll
                for (int nt = 0; nt < 4; nt++) {
                    uint32_t xoff = (uint32_t)((ks + (sel >> 1) * 8 + i8) * XLDT
                                               + wn * 64 + nt * 16 + (sel & 1) * 8) * 2;
                    uint32_t h0, h1, h2, h3, l0, l1, l2, l3;
                    LDMX4T(h0, h1, h2, h3, xsh_b + xoff);
                    LDMX4T(l0, l1, l2, l3, xsl_b + xoff);
#pragma unroll
                    for (int mi = 0; mi < 2; mi++) {
                        MMA16816(acc[mi][nt * 2 + 0], ahf[mi], h0, h2);
                        MMA16816(acc[mi][nt * 2 + 0], alf[mi], h0, h2);
                        MMA16816(acc[mi][nt * 2 + 0], ahf[mi], l0, l2);
                        MMA16816(acc[mi][nt * 2 + 1], ahf[mi], h1, h3);
                        MMA16816(acc[mi][nt * 2 + 1], alf[mi], h1, h3);
                        MMA16816(acc[mi][nt * 2 + 1], ahf[mi], l1, l3);
                    }
                }
            }
        }
    }

    int rbase = wm * 32 + (lane >> 2);
    int cbase = wn * 64 + (lane & 3) * 2;
#pragma unroll
    for (int mi = 0; mi < 2; mi++) {
#pragma unroll
        for (int ni = 0; ni < 8; ni++) {
            int l0r = rbase + mi * 16;
            int col = cbase + ni * 8;
            float* out0 = g_y + (size_t)(b * SEQ + c * CHUNK + l0r) * DI + h * HD + col;
            *(float2*)out0 = make_float2(acc[mi][ni][0], acc[mi][ni][1]);
            float* out1 = g_y + (size_t)(b * SEQ + c * CHUNK + l0r + 8) * DI + h * HD + col;
            *(float2*)out1 = make_float2(acc[mi][ni][2], acc[mi][ni][3]);
        }
    }
}

// ---------------- K5b: states via mma: S[p,n] = sum_l X[l,p]*w[l]*B[l,n] ----------------
#define SXP 136
#define SBP 72

__global__ __launch_bounds__(256, 1) void states_kernel()
{
    __shared__ __align__(16) __nv_bfloat16 Xh[32 * SXP];
    __shared__ __align__(16) __nv_bfloat16 Xl[32 * SXP];
    __shared__ __align__(16) __nv_bfloat16 Bh2[32 * SBP];
    __shared__ __align__(16) __nv_bfloat16 Bl2[32 * SBP];
    __shared__ float acs[CHUNK];

    uint32_t xh_b = smem_u32(Xh), xl_b = smem_u32(Xl);
    uint32_t bh_b = smem_u32(Bh2), bl_b = smem_u32(Bl2);

    int blk = blockIdx.x;
    int h = blk % NH; int bc = blk / NH;
    int c = bc % NC;  int b = bc / NC;
    int tid = threadIdx.x;
    int warp = tid >> 5, lane = tid & 31;
    int i8 = lane & 7, sel = lane >> 3;

    if (tid < 256) acs[tid] = g_dacs[((b * NH + h) * NC + c) * CHUNK + tid];
    __syncthreads();
    float alast = acs[CHUNK - 1];

    const float* Xb = g_X + (size_t)blk * CHUNK * HD;
    const float* Bb = g_Bm + (size_t)bc * CHUNK * DS;

    float acc[8][4];
#pragma unroll
    for (int ni = 0; ni < 8; ni++)
#pragma unroll
        for (int e = 0; e < 4; e++) acc[ni][e] = 0.f;

    for (int l0 = 0; l0 < CHUNK; l0 += 32) {
        if (l0) __syncthreads();
#pragma unroll
        for (int u = 0; u < 4; u++) {
            int e = tid + u * 256;
            int s = e >> 5, p4 = e & 31;
            float4 v = *(const float4*)&Xb[(l0 + s) * HD + p4 * 4];
            uint32_t h0, l0r, h1, l1r;
            split2(v.x, v.y, h0, l0r);
            split2(v.z, v.w, h1, l1r);
            uint32_t off = (uint32_t)(s * SXP + p4 * 4) * 2;
            asm volatile("st.shared.v2.b32 [%0], {%1,%2};" :: "r"(xh_b + off), "r"(h0), "r"(h1) : "memory");
            asm volatile("st.shared.v2.b32 [%0], {%1,%2};" :: "r"(xl_b + off), "r"(l0r), "r"(l1r) : "memory");
        }
#pragma unroll
        for (int u = 0; u < 2; u++) {
            int e = tid + u * 256;
            int s = e >> 4, n4 = e & 15;
            float w = __expf(alast - acs[l0 + s]);
            float4 v = *(const float4*)&Bb[(l0 + s) * DS + n4 * 4];
            uint32_t h0, l0r, h1, l1r;
            split2(v.x * w, v.y * w, h0, l0r);
            split2(v.z * w, v.w * w, h1, l1r);
            uint32_t off = (uint32_t)(s * SBP + n4 * 4) * 2;
            asm volatile("st.shared.v2.b32 [%0], {%1,%2};" :: "r"(bh_b + off), "r"(h0), "r"(h1) : "memory");
            asm volatile("st.shared.v2.b32 [%0], {%1,%2};" :: "r"(bl_b + off), "r"(l0r), "r"(l1r) : "memory");
        }
        __syncthreads();

#pragma unroll
        for (int ks = 0; ks < 32; ks += 16) {
            uint32_t aoff = (uint32_t)((ks + (sel >> 1) * 8 + i8) * SXP
                                       + warp * 16 + (sel & 1) * 8) * 2;
            uint32_t ah[4], al[4];
            LDMX4T(ah[0], ah[1], ah[2], ah[3], xh_b + aoff);
            LDMX4T(al[0], al[1], al[2], al[3], xl_b + aoff);
#pragma unroll
            for (int nt = 0; nt < 2; nt++) {
                uint32_t boff = (uint32_t)((ks + (sel >> 1) * 8 + i8) * SBP
                                           + nt * 32 + (sel & 1) * 8) * 2;
                uint32_t h0, h1, h2, h3, l0r, l1r, l2r, l3r;
                LDMX4T(h0, h1, h2, h3, bh_b + boff);
                LDMX4T(l0r, l1r, l2r, l3r, bl_b + boff);
                MMA16816(acc[nt * 4 + 0], ah, h0, h2);
                MMA16816(acc[nt * 4 + 0], al, h0, h2);
                MMA16816(acc[nt * 4 + 0], ah, l0r, l2r);
                MMA16816(acc[nt * 4 + 1], ah, h1, h3);
                MMA16816(acc[nt * 4 + 1], al, h1, h3);
                MMA16816(acc[nt * 4 + 1], ah, l1r, l3r);
                uint32_t boff2 = (uint32_t)((ks + (sel >> 1) * 8 + i8) * SBP
                                            + nt * 32 + 16 + (sel & 1) * 8) * 2;
                LDMX4T(h0, h1, h2, h3, bh_b + boff2);
                LDMX4T(l0r, l1r, l2r, l3r, bl_b + boff2);
                MMA16816(acc[nt * 4 + 2], ah, h0, h2);
                MMA16816(acc[nt * 4 + 2], al, h0, h2);
                MMA16816(acc[nt * 4 + 2], ah, l0r, l2r);
                MMA16816(acc[nt * 4 + 3], ah, h1, h3);
                MMA16816(acc[nt * 4 + 3], al, h1, h3);
                MMA16816(acc[nt * 4 + 3], ah, l1r, l3r);
            }
        }
    }

    float* So = g_states + (size_t)blk * HD * DS;
    int p0 = warp * 16 + (lane >> 2);
    int nc0 = (lane & 3) * 2;
#pragma unroll
    for (int ni = 0; ni < 8; ni++) {
        int col = nc0 + ni * 8;
        *(float2*)&So[p0 * DS + col] = make_float2(acc[ni][0], acc[ni][1]);
        *(float2*)&So[(p0 + 8) * DS + col] = make_float2(acc[ni][2], acc[ni][3]);
    }
}

// ---------------- K6: inter-chunk scan (8-way split, float4) ----------------
__global__ __launch_bounds__(256) void scan_kernel()
{
    int blk = blockIdx.x;
    int part = blk & 7;
    int bh = blk >> 3;
    int b = bh / NH, h = bh % NH;
    int e0 = part * 1024 + threadIdx.x * 4;

    float4 S = make_float4(0.f, 0.f, 0.f, 0.f);
    for (int c = 0; c < NC; c++) {
        float dec = __expf(g_csum[bh * NC + c]);
        size_t base = (size_t)((b * NC + c) * NH + h) * HD * DS + e0;
        *(float4*)&g_inter[base] = S;
        float4 v = *(const float4*)&g_states[base];
        S.x = S.x * dec + v.x;
        S.y = S.y * dec + v.y;
        S.z = S.z * dec + v.z;
        S.w = S.w * dec + v.w;
    }
}

// ---------------- K7: Y_off via mma (128t x 128p per block, 2 blocks/(b,c,h)) ----------------
// Y_off[t,p] = ea[t] * sum_n C[t,n] inter[p,n]; epilogue: g_y accumulate + silu(z) gate.
// 256 thr = 8 warps (4m x 2n), both operands K-major non-trans ldmatrix (gemm pattern).
#define OLP 72
#define OSMEM2 (4*128*OLP*2 + 128*4)   /* 73728 + 512 = 74240 */

__global__ __launch_bounds__(256, 2) void yoff_kernel()
{
    extern __shared__ __align__(16) char osm[];
    __nv_bfloat16* Ch = (__nv_bfloat16*)osm;
    __nv_bfloat16* Cl = Ch + 128 * OLP;
    __nv_bfloat16* Ih = Cl + 128 * OLP;
    __nv_bfloat16* Il = Ih + 128 * OLP;
    float* acs = (float*)(Il + 128 * OLP);

    uint32_t ch_b = smem_u32(Ch), cl_b = smem_u32(Cl);
    uint32_t ih_b = smem_u32(Ih), il_b = smem_u32(Il);

    int blk = blockIdx.x;
    int tg = blk & 1; int bch = blk >> 1;      // t-half, (b*NC+c)*NH+h
    int h = bch % NH; int bc = bch / NH;
    int c = bc % NC;  int b = bc / NC;
    int tid = threadIdx.x;
    int warp = tid >> 5, lane = tid & 31;
    int wm = warp & 3, wn = warp >> 2;
    int lrow16 = lane & 15, lkoff = (lane >> 4) * 8;

    if (tid < 128) acs[tid] = g_dacs[((b * NH + h) * NC + c) * CHUNK + tg * 128 + tid];

    const float* Cb = g_Cm + (size_t)bc * CHUNK * DS + (size_t)tg * 128 * DS;
    const float* Ib = g_inter + (size_t)bch * HD * DS;

    // build C' and I' tiles (128 x 64 f32 each -> bf16 hi/lo)
#pragma unroll
    for (int u = 0; u < 8; u++) {
        int e = tid + u * 256;                 // 0..2047
        int r = e >> 4, n4 = e & 15;
        uint32_t off = (uint32_t)(r * OLP + n4 * 4) * 2;
        float4 v = *(const float4*)&Cb[r * DS + n4 * 4];
        uint32_t h0, l0, h1, l1;
        split2(v.x, v.y, h0, l0);
        split2(v.z, v.w, h1, l1);
        asm volatile("st.shared.v2.b32 [%0], {%1,%2};" :: "r"(ch_b + off), "r"(h0), "r"(h1) : "memory");
        asm volatile("st.shared.v2.b32 [%0], {%1,%2};" :: "r"(cl_b + off), "r"(l0), "r"(l1) : "memory");
        float4 w = *(const float4*)&Ib[r * DS + n4 * 4];
        split2(w.x, w.y, h0, l0);
        split2(w.z, w.w, h1, l1);
        asm volatile("st.shared.v2.b32 [%0], {%1,%2};" :: "r"(ih_b + off), "r"(h0), "r"(h1) : "memory");
        asm volatile("st.shared.v2.b32 [%0], {%1,%2};" :: "r"(il_b + off), "r"(l0), "r"(l1) : "memory");
    }
    __syncthreads();

    float acc[2][8][4];
#pragma unroll
    for (int mi = 0; mi < 2; mi++)
#pragma unroll
        for (int ni = 0; ni < 8; ni++)
#pragma unroll
            for (int e = 0; e < 4; e++) acc[mi][ni][e] = 0.f;

#pragma unroll
    for (int ks = 0; ks < 64; ks += 16) {
        uint32_t ahf[2][4], alf[2][4];
#pragma unroll
        for (int mi = 0; mi < 2; mi++) {
            uint32_t off = (uint32_t)((wm * 32 + mi * 16 + lrow16) * OLP + ks + lkoff) * 2;
            LDMX4(ahf[mi][0], ahf[mi][1], ahf[mi][2], ahf[mi][3], ch_b + off);
            LDMX4(alf[mi][0], alf[mi][1], alf[mi][2], alf[mi][3], cl_b + off);
        }
#pragma unroll
        for (int nt = 0; nt < 4; nt++) {
            uint32_t off = (uint32_t)((wn * 64 + nt * 16 + lrow16) * OLP + ks + lkoff) * 2;
            uint32_t h0, h1, h2, h3, l0, l1, l2, l3;
            LDMX4(h0, h1, h2, h3, ih_b + off);
            LDMX4(l0, l1, l2, l3, il_b + off);
#pragma unroll
            for (int mi = 0; mi < 2; mi++) {
                MMA16816(acc[mi][nt * 2 + 0], ahf[mi], h0, h2);
                MMA16816(acc[mi][nt * 2 + 0], alf[mi], h0, h2);
                MMA16816(acc[mi][nt * 2 + 0], ahf[mi], l0, l2);
                MMA16816(acc[mi][nt * 2 + 1], ahf[mi], h1, h3);
                MMA16816(acc[mi][nt * 2 + 1], alf[mi], h1, h3);
                MMA16816(acc[mi][nt * 2 + 1], ahf[mi], l1, l3);
            }
        }
    }

    // epilogue: combine with g_y, gate with silu(z)
    int rbase = wm * 32 + (lane >> 2);
    int cbase = wn * 64 + (lane & 3) * 2;
#pragma unroll
    for (int mi = 0; mi < 2; mi++) {
#pragma unroll
        for (int rr = 0; rr < 2; rr++) {
            int tl = rbase + mi * 16 + rr * 8;
            float ea = __expf(acs[tl]);
            int gl = c * CHUNK + tg * 128 + tl;
            size_t rowy = (size_t)(b * SEQ + gl) * DI + h * HD;
            size_t rowz = (size_t)(b * SEQ + gl) * DIP + h * HD;
#pragma unroll
            for (int ni = 0; ni < 8; ni++) {
                int col = cbase + ni * 8;
                float2 yd = *(float2*)&g_y[rowy + col];
                float2 z  = *(const float2*)&g_zxbcdt[rowz + col];
                float a0 = acc[mi][ni][rr * 2 + 0], a1 = acc[mi][ni][rr * 2 + 1];
                float2 o;
                o.x = (yd.x + ea * a0) * z.x / (1.f + __expf(-z.x));
                o.y = (yd.y + ea * a1) * z.y / (1.f + __expf(-z.y));
                *(float2*)&g_y[rowy + col] = o;
            }
        }
    }
}

// ---------------- K8: layernorm over 4096, emits split bf16 hi/lo ----------------
__global__ __launch_bounds__(256) void ln_kernel(
    const float* __restrict__ ln_w, const float* __restrict__ ln_b)
{
    int tok = blockIdx.x;
    const float* y = g_y + (size_t)tok * DI;
    __nv_bfloat16* ohi = g_yn_hi + (size_t)tok * DI;
    __nv_bfloat16* olo = g_yn_lo + (size_t)tok * DI;
    int tid = threadIdx.x;

    float v[16];
    float s = 0.f, ss = 0.f;
#pragma unroll
    for (int u = 0; u < 4; u++) {
        float4 x = *(const float4*)&y[tid * 4 + u * 1024];
        v[u * 4 + 0] = x.x; v[u * 4 + 1] = x.y; v[u * 4 + 2] = x.z; v[u * 4 + 3] = x.w;
        s += x.x + x.y + x.z + x.w;
        ss += x.x * x.x + x.y * x.y + x.z * x.z + x.w * x.w;
    }
#pragma unroll
    for (int off = 16; off; off >>= 1) {
        s  += __shfl_xor_sync(0xFFFFFFFFu, s, off);
        ss += __shfl_xor_sync(0xFFFFFFFFu, ss, off);
    }
    __shared__ float rs[8], rss[8];
    int warp = tid >> 5, lane = tid & 31;
    if (lane == 0) { rs[warp] = s; rss[warp] = ss; }
    __syncthreads();
    s = 0.f; ss = 0.f;
#pragma unroll
    for (int w = 0; w < 8; w++) { s += rs[w]; ss += rss[w]; }
    float mu = s * (1.f / DI);
    float var = ss * (1.f / DI) - mu * mu;
    float rstd = rsqrtf(var + 1e-5f);
#pragma unroll
    for (int u = 0; u < 4; u++) {
        int idx = tid * 4 + u * 1024;
        float4 w4 = *(const float4*)&ln_w[idx];
        float4 b4 = *(const float4*)&ln_b[idx];
        float o0 = (v[u * 4 + 0] - mu) * rstd * w4.x + b4.x;
        float o1 = (v[u * 4 + 1] - mu) * rstd * w4.y + b4.y;
        float o2 = (v[u * 4 + 2] - mu) * rstd * w4.z + b4.z;
        float o3 = (v[u * 4 + 3] - mu) * rstd * w4.w + b4.w;
        uint2 hh, ll;
        split2(o0, o1, hh.x, ll.x);
        split2(o2, o3, hh.y, ll.y);
        *(uint2*)&ohi[idx] = hh;
        *(uint2*)&olo[idx] = ll;
    }
}

// ---------------- launch ----------------
extern "C" void kernel_launch(void* const* d_in, const int* in_sizes, int n_in,
                              void* d_out, int out_size)
{
    const float* u          = (const float*)d_in[0];
    const float* in_proj_w  = (const float*)d_in[1];
    const float* in_proj_b  = (const float*)d_in[2];
    const float* conv_w     = (const float*)d_in[3];
    const float* conv_b     = (const float*)d_in[4];
    const float* dt_bias    = (const float*)d_in[5];
    const float* A_log      = (const float*)d_in[6];
    const float* ln_w       = (const float*)d_in[7];
    const float* ln_b       = (const float*)d_in[8];
    const float* out_proj_w = (const float*)d_in[9];
    const float* out_proj_b = (const float*)d_in[10];
    float* out = (float*)d_out;

    float* zx; cudaGetSymbolAddress((void**)&zx, g_zxbcdt);
    __nv_bfloat16 *uh, *ul, *w1h, *w1l, *w2h, *w2l, *ynh, *ynl;
    cudaGetSymbolAddress((void**)&uh,  g_u_hi);
    cudaGetSymbolAddress((void**)&ul,  g_u_lo);
    cudaGetSymbolAddress((void**)&w1h, g_w1_hi);
    cudaGetSymbolAddress((void**)&w1l, g_w1_lo);
    cudaGetSymbolAddress((void**)&w2h, g_w2_hi);
    cudaGetSymbolAddress((void**)&w2l, g_w2_lo);
    cudaGetSymbolAddress((void**)&ynh, g_yn_hi);
    cudaGetSymbolAddress((void**)&ynl, g_yn_lo);

    cudaFuncSetAttribute(gemm_mma, cudaFuncAttributeMaxDynamicSharedMemorySize, GEMM_SMEM);
    cudaFuncSetAttribute(ydiag_kernel, cudaFuncAttributeMaxDynamicSharedMemorySize, YSMEM);
    cudaFuncSetAttribute(yoff_kernel, cudaFuncAttributeMaxDynamicSharedMemorySize, OSMEM2);

    // K0: pre-split u / weights into bf16 hi/lo
    split_kernel<<<(TOK * DM / 4 + 255) / 256, 256>>>(u, uh, ul, TOK * DM / 4);
    split_kernel<<<(DIP * DM / 4 + 255) / 256, 256>>>(in_proj_w, w1h, w1l, DIP * DM / 4);
    split_kernel<<<(DM * DI / 4 + 255) / 256, 256>>>(out_proj_w, w2h, w2l, DM * DI / 4);

    // K1: in_proj GEMM (8192 x 8352 x 2048)
    gemm_mma<<<dim3((DIP + BN - 1) / BN, TOK / BM), 256, GEMM_SMEM>>>(
        uh, ul, w1h, w1l, in_proj_b, zx, TOK, DIP, DM);
    // K2: dt softplus + per-chunk cumsum (warp scan)
    dt_scan_kernel<<<BATCH * NH * NC, CHUNK>>>(dt_bias, A_log);
    // K3: conv + silu + scatter (8 tokens/thread)
    conv_kernel<<<dim3(TOK / 8, (CONVD + 255) / 256), 256>>>(conv_w, conv_b);
    // K4: G = C B^T per (b,c)
    bc_gemm_kernel<<<dim3(16, BATCH * NC), 256>>>();
    // K5: Y_diag (split-bf16 mma)
    ydiag_kernel<<<BATCH * NC * NH, 512, YSMEM>>>();
    // K5b: local chunk states (split-bf16 mma)
    states_kernel<<<BATCH * NC * NH, 256>>>();
    // K6: inter-chunk scan (8-way split)
    scan_kernel<<<BATCH * NH * 8, 256>>>();
    // K7: Y_off (split-bf16 mma, 2 blocks per (b,c,h)) + gate
    yoff_kernel<<<BATCH * NC * NH * 2, 256, OSMEM2>>>();
    // K8: layernorm (emits bf16 hi/lo)
    ln_kernel<<<TOK, 256>>>(ln_w, ln_b);
    // K9: out_proj GEMM (8192 x 2048 x 4096)
    gemm_mma<<<dim3(DM / BN, TOK / BM), 256, GEMM_SMEM>>>(
        ynh, ynl, w2h, w2l, out_proj_b, out, TOK, DM, DI);
}